// round 1
// baseline (speedup 1.0000x reference)
#include <cuda_runtime.h>
#include <math.h>
#include <stdint.h>

// ---------------------------------------------------------------------------
// Problem constants (fixed by dataset)
// ---------------------------------------------------------------------------
#define NMAX 50000
#define EMAX 800000

// ---------------------------------------------------------------------------
// Scratch (device globals; no allocation allowed)
// ---------------------------------------------------------------------------
__device__ float g_h  [(size_t)NMAX * 128];   // Wh of current layer
__device__ float g_rh [(size_t)NMAX * 128];   // rW residual of current layer
__device__ float g_hs [(size_t)NMAX * 128];   // h_s after layer 0
__device__ float g_hs2[(size_t)NMAX * 128];   // h_s after layer 1
__device__ float g_hp [(size_t)NMAX * 64];    // h_p after layer 0
__device__ float g_el [(size_t)NMAX * 2];
__device__ float g_er [(size_t)NMAX * 2];
__device__ int   g_off[NMAX + 1];
__device__ int   g_cnt[NMAX];
__device__ int   g_esrc[EMAX];                // src node per dst-sorted edge slot

// ---------------------------------------------------------------------------
// CSR build
// ---------------------------------------------------------------------------
__global__ void count_kernel(const int* __restrict__ dst, int e) {
    int i = blockIdx.x * blockDim.x + threadIdx.x;
    if (i < e) atomicAdd(&g_cnt[dst[i]], 1);
}

// Single-block exclusive scan of g_cnt -> g_off, zeroes g_cnt for reuse as cursor.
__global__ void scan_kernel(int n) {
    __shared__ int partial[1024];
    const int t = threadIdx.x;
    const int C = (n + 1023) / 1024;
    int s = 0;
    for (int j = 0; j < C; j++) {
        int idx = t * C + j;
        if (idx < n) s += g_cnt[idx];
    }
    partial[t] = s;
    __syncthreads();
    // Hillis-Steele inclusive scan
    for (int ofs = 1; ofs < 1024; ofs <<= 1) {
        int v = (t >= ofs) ? partial[t - ofs] : 0;
        __syncthreads();
        partial[t] += v;
        __syncthreads();
    }
    int run = (t == 0) ? 0 : partial[t - 1];
    for (int j = 0; j < C; j++) {
        int idx = t * C + j;
        if (idx < n) {
            g_off[idx] = run;
            run += g_cnt[idx];
            g_cnt[idx] = 0;
        }
    }
    if (t == 1023) g_off[n] = run;
}

__global__ void fill_kernel(const int* __restrict__ src, const int* __restrict__ dst, int e) {
    int i = blockIdx.x * blockDim.x + threadIdx.x;
    if (i < e) {
        int d = dst[i];
        int p = atomicAdd(&g_cnt[d], 1);
        g_esrc[g_off[d] + p] = src[i];
    }
}

// ---------------------------------------------------------------------------
// GEMM:  C[M, BN] = A1[M,K1] @ W[0:K1, :]  +  A2[M,K2] @ W[K1:K1+K2, :]
// (implicit concat of A1|A2; A2 may be null with K2 == 0)
// ---------------------------------------------------------------------------
template <int BN>
__global__ __launch_bounds__(256) void gemm_kernel(
    const float* __restrict__ A1, int K1,
    const float* __restrict__ A2, int K2,
    const float* __restrict__ W,
    float* __restrict__ C, int M)
{
    constexpr int BM = 64, KB = 16;
    constexpr int TM = BM / 16;   // 4
    constexpr int TN = BN / 16;   // 8 (BN=128) or 4 (BN=64)
    __shared__ float As[KB][BM];
    __shared__ float Bs[KB][BN];

    const int t  = threadIdx.x;
    const int bm = blockIdx.x * BM;
    const int tx = t & 15;
    const int ty = t >> 4;
    const int K  = K1 + K2;

    float acc[TM][TN];
#pragma unroll
    for (int i = 0; i < TM; i++)
#pragma unroll
        for (int j = 0; j < TN; j++) acc[i][j] = 0.f;

    for (int k0 = 0; k0 < K; k0 += KB) {
        // load A tile (transposed into As[kk][m])
#pragma unroll
        for (int i = 0; i < (BM * KB) / 256; i++) {
            int idx = t + 256 * i;
            int m  = idx & (BM - 1);
            int kk = idx / BM;
            int row = bm + m;
            int k = k0 + kk;
            float v = 0.f;
            if (row < M) {
                if (k < K1) v = A1[(size_t)row * K1 + k];
                else        v = A2[(size_t)row * K2 + (k - K1)];
            }
            As[kk][m] = v;
        }
        // load B tile
#pragma unroll
        for (int i = 0; i < (KB * BN) / 256; i++) {
            int idx = t + 256 * i;
            int col = idx & (BN - 1);
            int kk  = idx / BN;
            Bs[kk][col] = W[(size_t)(k0 + kk) * BN + col];
        }
        __syncthreads();
#pragma unroll
        for (int kk = 0; kk < KB; kk++) {
            float ra[TM], rb[TN];
#pragma unroll
            for (int i = 0; i < TM; i++) ra[i] = As[kk][ty * TM + i];
#pragma unroll
            for (int j = 0; j < TN; j++) rb[j] = Bs[kk][tx + 16 * j];
#pragma unroll
            for (int i = 0; i < TM; i++)
#pragma unroll
                for (int j = 0; j < TN; j++)
                    acc[i][j] = fmaf(ra[i], rb[j], acc[i][j]);
        }
        __syncthreads();
    }
#pragma unroll
    for (int i = 0; i < TM; i++) {
        int row = bm + ty * TM + i;
        if (row < M) {
#pragma unroll
            for (int j = 0; j < TN; j++)
                C[(size_t)row * BN + tx + 16 * j] = acc[i][j];
        }
    }
}

// ---------------------------------------------------------------------------
// el / er:  el[n,h] = dot(h[n, h*D : (h+1)*D], al[h, :])   (warp per node)
// al/ar are flat [H*D] matching the flattened h row.
// ---------------------------------------------------------------------------
template <int HD>
__global__ void eler_kernel(const float* __restrict__ h,
                            const float* __restrict__ al,
                            const float* __restrict__ ar, int n)
{
    int warp = (blockIdx.x * blockDim.x + threadIdx.x) >> 5;
    int lane = threadIdx.x & 31;
    if (warp >= n) return;
    const float* row = h + (size_t)warp * HD;
    constexpr int KN = HD / 32;
    float pl0 = 0.f, pl1 = 0.f, pr0 = 0.f, pr1 = 0.f;
#pragma unroll
    for (int k = 0; k < KN; k++) {
        int idx = lane + 32 * k;
        float v = row[idx];
        if (32 * k < HD / 2) { pl0 += v * al[idx]; pr0 += v * ar[idx]; }
        else                 { pl1 += v * al[idx]; pr1 += v * ar[idx]; }
    }
#pragma unroll
    for (int o = 16; o; o >>= 1) {
        pl0 += __shfl_xor_sync(0xffffffffu, pl0, o);
        pl1 += __shfl_xor_sync(0xffffffffu, pl1, o);
        pr0 += __shfl_xor_sync(0xffffffffu, pr0, o);
        pr1 += __shfl_xor_sync(0xffffffffu, pr1, o);
    }
    if (lane == 0) {
        g_el[2 * warp]     = pl0;
        g_el[2 * warp + 1] = pl1;
        g_er[2 * warp]     = pr0;
        g_er[2 * warp + 1] = pr1;
    }
}

// ---------------------------------------------------------------------------
// Aggregation: warp per dst node. Two passes over its edges:
//   pass 1: per-head max of leaky_relu(el[src]+er[dst])
//   pass 2: denom = sum exp(e-m); acc = sum exp(e-m) * h[src]
// then out = act(acc/denom + res), optional head-mean.
// ACT: 0 = elu, 1 = tanh.
// ---------------------------------------------------------------------------
__device__ __forceinline__ float leaky02(float x) { return x > 0.f ? x : 0.2f * x; }

template <int HD, int ACT, bool HEADMEAN>
__global__ void agg_kernel(const float* __restrict__ h,
                           const float* __restrict__ res,
                           float* __restrict__ out, int n)
{
    int node = (blockIdx.x * blockDim.x + threadIdx.x) >> 5;
    int lane = threadIdx.x & 31;
    if (node >= n) return;

    const int beg = g_off[node];
    const int end = g_off[node + 1];
    const float2 erv = ((const float2*)g_er)[node];

    float m0 = -1e30f, m1 = -1e30f;
    for (int i = beg; i < end; i++) {
        int s = g_esrc[i];
        float2 elv = ((const float2*)g_el)[s];
        float e0 = leaky02(elv.x + erv.x);
        float e1 = leaky02(elv.y + erv.y);
        m0 = fmaxf(m0, e0);
        m1 = fmaxf(m1, e1);
    }

    constexpr int KN = HD / 32;
    float acc[KN];
#pragma unroll
    for (int k = 0; k < KN; k++) acc[k] = 0.f;
    float d0 = 0.f, d1 = 0.f;

    for (int i = beg; i < end; i++) {
        int s = g_esrc[i];
        float2 elv = ((const float2*)g_el)[s];
        float e0 = leaky02(elv.x + erv.x);
        float e1 = leaky02(elv.y + erv.y);
        float w0 = __expf(e0 - m0);
        float w1 = __expf(e1 - m1);
        d0 += w0;
        d1 += w1;
        const float* hr = h + (size_t)s * HD;
#pragma unroll
        for (int k = 0; k < KN; k++) {
            float wv = (32 * k < HD / 2) ? w0 : w1;
            acc[k] = fmaf(wv, hr[lane + 32 * k], acc[k]);
        }
    }

    const bool has = (end > beg);
    const float inv0 = has ? 1.f / d0 : 0.f;
    const float inv1 = has ? 1.f / d1 : 0.f;
    const float* rr = res + (size_t)node * HD;

    if (HEADMEAN) {
        // HD = 128, elu then mean over 2 heads -> 64 outputs
#pragma unroll
        for (int k = 0; k < 2; k++) {
            int idx = lane + 32 * k;
            float v0 = acc[k]     * inv0 + rr[idx];
            float v1 = acc[k + 2] * inv1 + rr[idx + 64];
            v0 = v0 > 0.f ? v0 : expm1f(v0);
            v1 = v1 > 0.f ? v1 : expm1f(v1);
            out[(size_t)node * 64 + idx] = 0.5f * (v0 + v1);
        }
    } else {
#pragma unroll
        for (int k = 0; k < KN; k++) {
            int idx = lane + 32 * k;
            float inv = (32 * k < HD / 2) ? inv0 : inv1;
            float v = acc[k] * inv + rr[idx];
            if (ACT == 0) v = v > 0.f ? v : expm1f(v);
            else          v = tanhf(v);
            out[(size_t)node * HD + idx] = v;
        }
    }
}

// ---------------------------------------------------------------------------
// Launch
// ---------------------------------------------------------------------------
extern "C" void kernel_launch(void* const* d_in, const int* in_sizes, int n_in,
                              void* d_out, int out_size)
{
    const float* fvs = (const float*)d_in[0];   // [N,128]
    const float* pos = (const float*)d_in[1];   // [N,64]
    const int*   src = (const int*)d_in[2];     // [E]
    const int*   dst = (const int*)d_in[3];     // [E]
    const float* g0W  = (const float*)d_in[4];
    const float* g0al = (const float*)d_in[5];
    const float* g0ar = (const float*)d_in[6];
    const float* g0rW = (const float*)d_in[7];
    const float* g1W  = (const float*)d_in[8];
    const float* g1al = (const float*)d_in[9];
    const float* g1ar = (const float*)d_in[10];
    const float* g1rW = (const float*)d_in[11];
    const float* g2W  = (const float*)d_in[12];
    const float* g2al = (const float*)d_in[13];
    const float* g2ar = (const float*)d_in[14];
    const float* g2rW = (const float*)d_in[15];
    const float* p0W  = (const float*)d_in[16];
    const float* p0al = (const float*)d_in[17];
    const float* p0ar = (const float*)d_in[18];
    const float* p1W  = (const float*)d_in[19];
    const float* p1al = (const float*)d_in[20];
    const float* p1ar = (const float*)d_in[21];

    const int n = in_sizes[0] / 128;
    const int e = in_sizes[2];

    float *h, *rh, *hs, *hs2, *hp;
    int* cnt;
    cudaGetSymbolAddress((void**)&h,   g_h);
    cudaGetSymbolAddress((void**)&rh,  g_rh);
    cudaGetSymbolAddress((void**)&hs,  g_hs);
    cudaGetSymbolAddress((void**)&hs2, g_hs2);
    cudaGetSymbolAddress((void**)&hp,  g_hp);
    cudaGetSymbolAddress((void**)&cnt, g_cnt);

    float* out_hs = (float*)d_out;                       // [N,64]
    float* out_hp = (float*)d_out + (size_t)n * 64;      // [N,64]

    const int EB = (e + 255) / 256;
    const int GB = (n + 63) / 64;            // gemm blocks (BM=64)
    const int WB = (n + 7) / 8;              // warp-per-node kernels, 256 thr

    // ---- CSR build ----
    cudaMemsetAsync(cnt, 0, (size_t)n * sizeof(int));
    count_kernel<<<EB, 256>>>(dst, e);
    scan_kernel<<<1, 1024>>>(n);
    fill_kernel<<<EB, 256>>>(src, dst, e);

    // ---- layer 0 ----
    // gat0: feat = [fvs | pos]
    gemm_kernel<128><<<GB, 256>>>(fvs, 128, pos, 64, g0W,  h,  n);
    gemm_kernel<128><<<GB, 256>>>(fvs, 128, pos, 64, g0rW, rh, n);
    eler_kernel<128><<<WB, 256>>>(h, g0al, g0ar, n);
    agg_kernel<128, 0, false><<<WB, 256>>>(h, rh, hs, n);
    // pg0: feat = pos, identity residual
    gemm_kernel<64><<<GB, 256>>>(pos, 64, (const float*)nullptr, 0, p0W, h, n);
    eler_kernel<64><<<WB, 256>>>(h, p0al, p0ar, n);
    agg_kernel<64, 1, false><<<WB, 256>>>(h, pos, hp, n);

    // ---- layer 1 ----
    gemm_kernel<128><<<GB, 256>>>(hs, 128, hp, 64, g1W,  h,  n);
    gemm_kernel<128><<<GB, 256>>>(hs, 128, hp, 64, g1rW, rh, n);
    eler_kernel<128><<<WB, 256>>>(h, g1al, g1ar, n);
    agg_kernel<128, 0, false><<<WB, 256>>>(h, rh, hs2, n);
    // pg1 -> final h_p, written straight into d_out second half
    gemm_kernel<64><<<GB, 256>>>(hp, 64, (const float*)nullptr, 0, p1W, h, n);
    eler_kernel<64><<<WB, 256>>>(h, p1al, p1ar, n);
    agg_kernel<64, 1, false><<<WB, 256>>>(h, hp, out_hp, n);

    // ---- layer 2 (output, head-mean) ----
    gemm_kernel<128><<<GB, 256>>>(hs2, 128, out_hp, 64, g2W,  h,  n);
    gemm_kernel<128><<<GB, 256>>>(hs2, 128, out_hp, 64, g2rW, rh, n);
    eler_kernel<128><<<WB, 256>>>(h, g2al, g2ar, n);
    agg_kernel<128, 0, true><<<WB, 256>>>(h, rh, out_hs, n);
}

// round 2
// speedup vs baseline: 1.2511x; 1.2511x over previous
#include <cuda_runtime.h>
#include <math.h>
#include <stdint.h>

// ---------------------------------------------------------------------------
// Problem constants (fixed by dataset)
// ---------------------------------------------------------------------------
#define NMAX 50000
#define EMAX 800000

// ---------------------------------------------------------------------------
// Scratch (device globals; no allocation allowed)
// ---------------------------------------------------------------------------
__device__ float g_h  [(size_t)NMAX * 128];   // Wh of current layer
__device__ float g_rh [(size_t)NMAX * 128];   // rW residual of current layer
__device__ float g_hs [(size_t)NMAX * 128];   // h_s after layer 0
__device__ float g_hs2[(size_t)NMAX * 128];   // h_s after layer 1
__device__ float g_hp [(size_t)NMAX * 64];    // h_p after layer 0
__device__ float g_el [(size_t)NMAX * 2];
__device__ float g_er [(size_t)NMAX * 2];
__device__ int   g_off[NMAX + 1];
__device__ int   g_cnt[NMAX];
__device__ int   g_esrc[EMAX];                // src node per dst-sorted edge slot

// ---------------------------------------------------------------------------
// CSR build
// ---------------------------------------------------------------------------
__global__ void count_kernel(const int* __restrict__ dst, int e) {
    int i = blockIdx.x * blockDim.x + threadIdx.x;
    if (i < e) atomicAdd(&g_cnt[dst[i]], 1);
}

// Single-block exclusive scan of g_cnt -> g_off, zeroes g_cnt for reuse as cursor.
__global__ void scan_kernel(int n) {
    __shared__ int partial[1024];
    const int t = threadIdx.x;
    const int C = (n + 1023) / 1024;
    int s = 0;
    for (int j = 0; j < C; j++) {
        int idx = t * C + j;
        if (idx < n) s += g_cnt[idx];
    }
    partial[t] = s;
    __syncthreads();
    for (int ofs = 1; ofs < 1024; ofs <<= 1) {
        int v = (t >= ofs) ? partial[t - ofs] : 0;
        __syncthreads();
        partial[t] += v;
        __syncthreads();
    }
    int run = (t == 0) ? 0 : partial[t - 1];
    for (int j = 0; j < C; j++) {
        int idx = t * C + j;
        if (idx < n) {
            g_off[idx] = run;
            run += g_cnt[idx];
            g_cnt[idx] = 0;
        }
    }
    if (t == 1023) g_off[n] = run;
}

__global__ void fill_kernel(const int* __restrict__ src, const int* __restrict__ dst, int e) {
    int i = blockIdx.x * blockDim.x + threadIdx.x;
    if (i < e) {
        int d = dst[i];
        int p = atomicAdd(&g_cnt[d], 1);
        g_esrc[g_off[d] + p] = src[i];
    }
}

// ---------------------------------------------------------------------------
// GEMM:  C[M, BN] = [A1 | A2] @ W   (implicit concat; A2 may be null, K2=0)
// BM=128, KB=16, 256 threads, per-thread micro-tile 8 x (BN/16).
// K1 and K2 must be multiples of 16 (128/64/0 here) so each K-chunk lives
// entirely in one of A1/A2.
// ---------------------------------------------------------------------------
template <int BN>
__global__ __launch_bounds__(256) void gemm_kernel(
    const float* __restrict__ A1, int K1,
    const float* __restrict__ A2, int K2,
    const float* __restrict__ W,
    float* __restrict__ C, int M)
{
    constexpr int BM = 128, KB = 16;
    constexpr int TM = 8;
    constexpr int TN = BN / 16;            // 8 or 4
    __shared__ float As[KB][BM + 4];       // padded, stored transposed
    __shared__ float Bs[KB][BN];

    const int t     = threadIdx.x;
    const int tx    = t & 15;
    const int ty    = t >> 4;
    const int bm    = blockIdx.x * BM;
    const int row_l = t & 127;             // local row this thread loads for A
    const int half  = t >> 7;              // 0 or 1
    const int K     = K1 + K2;
    const int grow  = bm + row_l;
    const bool rok  = (grow < M);

    float acc[TM][TN];
#pragma unroll
    for (int i = 0; i < TM; i++)
#pragma unroll
        for (int j = 0; j < TN; j++) acc[i][j] = 0.f;

    for (int k0 = 0; k0 < K; k0 += KB) {
        // ---- load A chunk (transposed into As[k][m]) ----
        const float* base;
        int ldk, koff;
        if (k0 < K1) { base = A1; ldk = K1; koff = k0; }
        else         { base = A2; ldk = K2; koff = k0 - K1; }
        const float* arow = base + (size_t)grow * ldk + koff;
#pragma unroll
        for (int c = 0; c < 2; c++) {
            int kp = half * 2 + c;          // which float4 of the 16-wide chunk
            float4 v = make_float4(0.f, 0.f, 0.f, 0.f);
            if (rok) v = *(const float4*)(arow + kp * 4);
            As[kp * 4 + 0][row_l] = v.x;
            As[kp * 4 + 1][row_l] = v.y;
            As[kp * 4 + 2][row_l] = v.z;
            As[kp * 4 + 3][row_l] = v.w;
        }
        // ---- load B chunk ----
#pragma unroll
        for (int i = 0; i < (KB * BN) / 1024; i++) {     // float4s per thread
            int idx = t + 256 * i;
            int kk  = idx / (BN / 4);
            int cp  = idx % (BN / 4);
            *(float4*)&Bs[kk][cp * 4] =
                *(const float4*)(W + (size_t)(k0 + kk) * BN + cp * 4);
        }
        __syncthreads();

#pragma unroll
        for (int kk = 0; kk < KB; kk++) {
            float a[TM], b[TN];
            *(float4*)&a[0] = *(const float4*)&As[kk][ty * TM];
            *(float4*)&a[4] = *(const float4*)&As[kk][ty * TM + 4];
#pragma unroll
            for (int j4 = 0; j4 < TN / 4; j4++)
                *(float4*)&b[j4 * 4] = *(const float4*)&Bs[kk][tx * TN + j4 * 4];
#pragma unroll
            for (int i = 0; i < TM; i++)
#pragma unroll
                for (int j = 0; j < TN; j++)
                    acc[i][j] = fmaf(a[i], b[j], acc[i][j]);
        }
        __syncthreads();
    }

#pragma unroll
    for (int i = 0; i < TM; i++) {
        int row = bm + ty * TM + i;
        if (row < M) {
#pragma unroll
            for (int j4 = 0; j4 < TN / 4; j4++)
                *(float4*)&C[(size_t)row * BN + tx * TN + j4 * 4] =
                    *(const float4*)&acc[i][j4 * 4];
        }
    }
}

// ---------------------------------------------------------------------------
// el / er:  el[n,h] = dot(h[n, h*D:(h+1)*D], al[h,:])   (warp per node)
// ---------------------------------------------------------------------------
template <int HD>
__global__ void eler_kernel(const float* __restrict__ h,
                            const float* __restrict__ al,
                            const float* __restrict__ ar, int n)
{
    int warp = (blockIdx.x * blockDim.x + threadIdx.x) >> 5;
    int lane = threadIdx.x & 31;
    if (warp >= n) return;
    const float* row = h + (size_t)warp * HD;
    constexpr int KN = HD / 32;
    float pl0 = 0.f, pl1 = 0.f, pr0 = 0.f, pr1 = 0.f;
#pragma unroll
    for (int k = 0; k < KN; k++) {
        int idx = lane + 32 * k;
        float v = row[idx];
        if (32 * k < HD / 2) { pl0 += v * al[idx]; pr0 += v * ar[idx]; }
        else                 { pl1 += v * al[idx]; pr1 += v * ar[idx]; }
    }
#pragma unroll
    for (int o = 16; o; o >>= 1) {
        pl0 += __shfl_xor_sync(0xffffffffu, pl0, o);
        pl1 += __shfl_xor_sync(0xffffffffu, pl1, o);
        pr0 += __shfl_xor_sync(0xffffffffu, pr0, o);
        pr1 += __shfl_xor_sync(0xffffffffu, pr1, o);
    }
    if (lane == 0) {
        g_el[2 * warp]     = pl0;
        g_el[2 * warp + 1] = pl1;
        g_er[2 * warp]     = pr0;
        g_er[2 * warp + 1] = pr1;
    }
}

// ---------------------------------------------------------------------------
// Aggregation: warp per dst node, two passes (exact segment max, then sum).
// ACT: 0 = elu, 1 = tanh.
// ---------------------------------------------------------------------------
__device__ __forceinline__ float leaky02(float x) { return x > 0.f ? x : 0.2f * x; }

template <int HD, int ACT, bool HEADMEAN>
__global__ void agg_kernel(const float* __restrict__ h,
                           const float* __restrict__ res,
                           float* __restrict__ out, int n)
{
    int node = (blockIdx.x * blockDim.x + threadIdx.x) >> 5;
    int lane = threadIdx.x & 31;
    if (node >= n) return;

    const int beg = g_off[node];
    const int end = g_off[node + 1];
    const float2 erv = ((const float2*)g_er)[node];

    float m0 = -1e30f, m1 = -1e30f;
    for (int i = beg; i < end; i++) {
        int s = g_esrc[i];
        float2 elv = ((const float2*)g_el)[s];
        m0 = fmaxf(m0, leaky02(elv.x + erv.x));
        m1 = fmaxf(m1, leaky02(elv.y + erv.y));
    }

    constexpr int KN = HD / 32;
    float acc[KN];
#pragma unroll
    for (int k = 0; k < KN; k++) acc[k] = 0.f;
    float d0 = 0.f, d1 = 0.f;

    for (int i = beg; i < end; i++) {
        int s = g_esrc[i];
        float2 elv = ((const float2*)g_el)[s];
        float w0 = __expf(leaky02(elv.x + erv.x) - m0);
        float w1 = __expf(leaky02(elv.y + erv.y) - m1);
        d0 += w0;
        d1 += w1;
        const float* hr = h + (size_t)s * HD;
#pragma unroll
        for (int k = 0; k < KN; k++) {
            float wv = (32 * k < HD / 2) ? w0 : w1;
            acc[k] = fmaf(wv, hr[lane + 32 * k], acc[k]);
        }
    }

    const bool has = (end > beg);
    const float inv0 = has ? 1.f / d0 : 0.f;
    const float inv1 = has ? 1.f / d1 : 0.f;
    const float* rr = res + (size_t)node * HD;

    if (HEADMEAN) {
#pragma unroll
        for (int k = 0; k < 2; k++) {
            int idx = lane + 32 * k;
            float v0 = acc[k]     * inv0 + rr[idx];
            float v1 = acc[k + 2] * inv1 + rr[idx + 64];
            v0 = v0 > 0.f ? v0 : expm1f(v0);
            v1 = v1 > 0.f ? v1 : expm1f(v1);
            out[(size_t)node * 64 + idx] = 0.5f * (v0 + v1);
        }
    } else {
#pragma unroll
        for (int k = 0; k < KN; k++) {
            int idx = lane + 32 * k;
            float inv = (32 * k < HD / 2) ? inv0 : inv1;
            float v = acc[k] * inv + rr[idx];
            if (ACT == 0) v = v > 0.f ? v : expm1f(v);
            else          v = tanhf(v);
            out[(size_t)node * HD + idx] = v;
        }
    }
}

// ---------------------------------------------------------------------------
// Launch
// ---------------------------------------------------------------------------
extern "C" void kernel_launch(void* const* d_in, const int* in_sizes, int n_in,
                              void* d_out, int out_size)
{
    const float* fvs = (const float*)d_in[0];   // [N,128]
    const float* pos = (const float*)d_in[1];   // [N,64]
    const int*   src = (const int*)d_in[2];     // [E]
    const int*   dst = (const int*)d_in[3];     // [E]
    const float* g0W  = (const float*)d_in[4];
    const float* g0al = (const float*)d_in[5];
    const float* g0ar = (const float*)d_in[6];
    const float* g0rW = (const float*)d_in[7];
    const float* g1W  = (const float*)d_in[8];
    const float* g1al = (const float*)d_in[9];
    const float* g1ar = (const float*)d_in[10];
    const float* g1rW = (const float*)d_in[11];
    const float* g2W  = (const float*)d_in[12];
    const float* g2al = (const float*)d_in[13];
    const float* g2ar = (const float*)d_in[14];
    const float* g2rW = (const float*)d_in[15];
    const float* p0W  = (const float*)d_in[16];
    const float* p0al = (const float*)d_in[17];
    const float* p0ar = (const float*)d_in[18];
    const float* p1W  = (const float*)d_in[19];
    const float* p1al = (const float*)d_in[20];
    const float* p1ar = (const float*)d_in[21];

    const int n = in_sizes[0] / 128;
    const int e = in_sizes[2];

    float *h, *rh, *hs, *hs2, *hp;
    int* cnt;
    cudaGetSymbolAddress((void**)&h,   g_h);
    cudaGetSymbolAddress((void**)&rh,  g_rh);
    cudaGetSymbolAddress((void**)&hs,  g_hs);
    cudaGetSymbolAddress((void**)&hs2, g_hs2);
    cudaGetSymbolAddress((void**)&hp,  g_hp);
    cudaGetSymbolAddress((void**)&cnt, g_cnt);

    float* out_hs = (float*)d_out;                       // [N,64]
    float* out_hp = (float*)d_out + (size_t)n * 64;      // [N,64]

    const int EB = (e + 255) / 256;
    const int GB = (n + 127) / 128;          // gemm blocks (BM=128)
    const int WB = (n + 7) / 8;              // warp-per-node kernels, 256 thr

    // ---- CSR build ----
    cudaMemsetAsync(cnt, 0, (size_t)n * sizeof(int));
    count_kernel<<<EB, 256>>>(dst, e);
    scan_kernel<<<1, 1024>>>(n);
    fill_kernel<<<EB, 256>>>(src, dst, e);

    // ---- layer 0 ----
    gemm_kernel<128><<<GB, 256>>>(fvs, 128, pos, 64, g0W,  h,  n);
    gemm_kernel<128><<<GB, 256>>>(fvs, 128, pos, 64, g0rW, rh, n);
    eler_kernel<128><<<WB, 256>>>(h, g0al, g0ar, n);
    agg_kernel<128, 0, false><<<WB, 256>>>(h, rh, hs, n);
    gemm_kernel<64><<<GB, 256>>>(pos, 64, (const float*)nullptr, 0, p0W, h, n);
    eler_kernel<64><<<WB, 256>>>(h, p0al, p0ar, n);
    agg_kernel<64, 1, false><<<WB, 256>>>(h, pos, hp, n);

    // ---- layer 1 ----
    gemm_kernel<128><<<GB, 256>>>(hs, 128, hp, 64, g1W,  h,  n);
    gemm_kernel<128><<<GB, 256>>>(hs, 128, hp, 64, g1rW, rh, n);
    eler_kernel<128><<<WB, 256>>>(h, g1al, g1ar, n);
    agg_kernel<128, 0, false><<<WB, 256>>>(h, rh, hs2, n);
    gemm_kernel<64><<<GB, 256>>>(hp, 64, (const float*)nullptr, 0, p1W, h, n);
    eler_kernel<64><<<WB, 256>>>(h, p1al, p1ar, n);
    agg_kernel<64, 1, false><<<WB, 256>>>(h, hp, out_hp, n);

    // ---- layer 2 (output, head-mean) ----
    gemm_kernel<128><<<GB, 256>>>(hs2, 128, out_hp, 64, g2W,  h,  n);
    gemm_kernel<128><<<GB, 256>>>(hs2, 128, out_hp, 64, g2rW, rh, n);
    eler_kernel<128><<<WB, 256>>>(h, g2al, g2ar, n);
    agg_kernel<128, 0, true><<<WB, 256>>>(h, rh, out_hs, n);
}

// round 4
// speedup vs baseline: 1.4477x; 1.1572x over previous
#include <cuda_runtime.h>
#include <cuda_bf16.h>
#include <math.h>
#include <stdint.h>

// ---------------------------------------------------------------------------
// Problem constants
// ---------------------------------------------------------------------------
#define NMAX 50000
#define EMAX 800000

// ---------------------------------------------------------------------------
// Scratch (device globals)
// ---------------------------------------------------------------------------
__device__ float g_h  [(size_t)NMAX * 128];
__device__ float g_rh [(size_t)NMAX * 128];
__device__ float g_hs [(size_t)NMAX * 128];
__device__ float g_hs2[(size_t)NMAX * 128];
__device__ float g_hp [(size_t)NMAX * 64];
__device__ float g_el [(size_t)NMAX * 2];
__device__ float g_er [(size_t)NMAX * 2];
__device__ int   g_off[NMAX + 1];
__device__ int   g_cnt[NMAX];
__device__ int   g_esrc[EMAX];

// Transposed hi/lo bf16 weights: 6 big mats (128x192) then 2 small (64x64)
#define WT_BIG   (128 * 192)
#define WT_SMALL (64 * 64)
__device__ uint16_t g_wthi[6 * WT_BIG + 2 * WT_SMALL];
__device__ uint16_t g_wtlo[6 * WT_BIG + 2 * WT_SMALL];

// ---------------------------------------------------------------------------
// Helpers
// ---------------------------------------------------------------------------
__device__ __forceinline__ uint32_t smem_u32(const void* p) {
    uint32_t a;
    asm("{ .reg .u64 t; cvta.to.shared.u64 t, %1; cvt.u32.u64 %0, t; }"
        : "=r"(a) : "l"(p));
    return a;
}

__device__ __forceinline__ void ldsm_x4(uint32_t* r, uint32_t addr) {
    asm volatile("ldmatrix.sync.aligned.m8n8.x4.shared.b16 {%0,%1,%2,%3}, [%4];"
                 : "=r"(r[0]), "=r"(r[1]), "=r"(r[2]), "=r"(r[3]) : "r"(addr));
}

__device__ __forceinline__ void mma16816(float* c, const uint32_t* a, const uint32_t* b) {
    asm volatile(
        "mma.sync.aligned.m16n8k16.row.col.f32.bf16.bf16.f32 "
        "{%0,%1,%2,%3}, {%4,%5,%6,%7}, {%8,%9}, {%0,%1,%2,%3};"
        : "+f"(c[0]), "+f"(c[1]), "+f"(c[2]), "+f"(c[3])
        : "r"(a[0]), "r"(a[1]), "r"(a[2]), "r"(a[3]), "r"(b[0]), "r"(b[1]));
}

__device__ __forceinline__ void split8(const float* v, uint4& h4, uint4& l4) {
    uint16_t* hp = (uint16_t*)&h4;
    uint16_t* lp = (uint16_t*)&l4;
#pragma unroll
    for (int i = 0; i < 8; i++) {
        __nv_bfloat16 hb = __float2bfloat16(v[i]);
        float r = v[i] - __bfloat162float(hb);
        __nv_bfloat16 lb = __float2bfloat16(r);
        hp[i] = *(uint16_t*)&hb;
        lp[i] = *(uint16_t*)&lb;
    }
}

// 16B-chunk XOR swizzle within 128B groups: conflict-free ldmatrix + STS.
__device__ __forceinline__ uint32_t swz(int row, int g, int ROWB) {
    int c = (g & ~7) | ((g ^ row) & 7);
    return (uint32_t)(row * ROWB + c * 16);
}

// ---------------------------------------------------------------------------
// Weight prep: Wt[n][k] = W[k][n], split into bf16 hi/lo planes.
// ---------------------------------------------------------------------------
struct Prep8 {
    const float* W[8];
    int K[8], N[8], off[8];
};

__global__ void prep_kernel(Prep8 p) {
    for (int m = 0; m < 8; m++) {
        const int K = p.K[m], N = p.N[m], tot = K * N, off = p.off[m];
        const float* W = p.W[m];
        for (int idx = blockIdx.x * blockDim.x + threadIdx.x; idx < tot;
             idx += gridDim.x * blockDim.x) {
            int n = idx / K, k = idx - n * K;
            float w = W[(size_t)k * N + n];
            __nv_bfloat16 h = __float2bfloat16(w);
            float r = w - __bfloat162float(h);
            __nv_bfloat16 l = __float2bfloat16(r);
            g_wthi[off + idx] = *(uint16_t*)&h;
            g_wtlo[off + idx] = *(uint16_t*)&l;
        }
    }
}

// ---------------------------------------------------------------------------
// bf16x3 mma.sync GEMM:  C[M,BN] = [A1|A2] @ Wt^T
// One 128-row tile per CTA, full K resident in SMEM as hi/lo bf16 planes.
// D = Ah*Bh + Ah*Bl + Al*Bh  (fp32 accumulators in registers)
// 8 warps: 4 (M) x 2 (N); warp tile 32 x BN/2.
// ---------------------------------------------------------------------------
template <int BN, int K>
__global__ __launch_bounds__(256, 1) void tc_gemm(
    const float* __restrict__ A1, int K1,
    const float* __restrict__ A2,
    const uint16_t* __restrict__ Bh, const uint16_t* __restrict__ Bl,
    float* __restrict__ C, int M)
{
    constexpr int ROWB = K * 2;          // bytes per smem row
    constexpr int NG   = K / 8;          // 16B chunks per row
    constexpr int WN   = BN / 2;         // warp N extent
    constexpr int NT   = WN / 8;         // n8 frags per warp (8 or 4)
    constexpr int KS   = K / 16;         // k16 steps

    extern __shared__ char smem[];
    const uint32_t sAH = smem_u32(smem);
    const uint32_t sAL = sAH + 128 * ROWB;
    const uint32_t sBH = sAL + 128 * ROWB;
    const uint32_t sBL = sBH + BN * ROWB;

    const int t    = threadIdx.x;
    const int wid  = t >> 5;
    const int lane = t & 31;
    const int bm   = blockIdx.x * 128;

    // ---- load + split A (implicit concat A1|A2) ----
    for (int idx = t; idx < 128 * NG; idx += 256) {
        int row = idx / NG, g = idx - row * NG, k0 = g * 8;
        int grow = bm + row;
        float v[8] = {0, 0, 0, 0, 0, 0, 0, 0};
        if (grow < M) {
            const float* p = (k0 < K1) ? (A1 + (size_t)grow * K1 + k0)
                                       : (A2 + (size_t)grow * (K - K1) + (k0 - K1));
            *(float4*)&v[0] = ((const float4*)p)[0];
            *(float4*)&v[4] = ((const float4*)p)[1];
        }
        uint4 h4, l4;
        split8(v, h4, l4);
        uint32_t o = swz(row, g, ROWB);
        *(uint4*)(uintptr_t)(smem + (o))                 = h4;   // placeholder avoid
        // NOTE: write via smem pointer arithmetic (same offsets as sAH/sAL)
        *(uint4*)(smem + o) = h4;
        *(uint4*)(smem + 128 * ROWB + o) = l4;
    }
    // ---- load pre-split B planes ----
    for (int idx = t; idx < BN * NG; idx += 256) {
        int rn = idx / NG, g = idx - rn * NG, k0 = g * 8;
        uint4 h4 = *(const uint4*)(Bh + (size_t)rn * K + k0);
        uint4 l4 = *(const uint4*)(Bl + (size_t)rn * K + k0);
        uint32_t o = swz(rn, g, ROWB);
        *(uint4*)(smem + 2 * 128 * ROWB + o) = h4;
        *(uint4*)(smem + 2 * 128 * ROWB + BN * ROWB + o) = l4;
    }
    __syncthreads();

    const int wm = wid & 3;        // 0..3  (M groups of 32)
    const int wn = wid >> 2;       // 0..1  (N groups of WN)
    const int lr   = lane & 7;
    const int sel  = lane >> 3;    // 0..3
    const int selb1 = sel & 1;
    const int selb2 = sel >> 1;

    // ldmatrix lane-row bases
    const int rowA_base = wm * 32 + lr + selb1 * 8;   // + mt*16
    const int rowB_base = wn * WN + lr + selb2 * 8;   // + nt2*16

    float acc[2][NT][4];
#pragma unroll
    for (int mt = 0; mt < 2; mt++)
#pragma unroll
        for (int nt = 0; nt < NT; nt++)
#pragma unroll
            for (int q = 0; q < 4; q++) acc[mt][nt][q] = 0.f;

#pragma unroll
    for (int pr = 0; pr < 3; pr++) {
        const uint32_t baseA = (pr == 2) ? sAL : sAH;
        const uint32_t baseB = (pr == 1) ? sBL : sBH;
#pragma unroll
        for (int ks = 0; ks < KS; ks++) {
            uint32_t afr[2][4];
#pragma unroll
            for (int mt = 0; mt < 2; mt++) {
                uint32_t ad = baseA + swz(rowA_base + mt * 16, ks * 2 + selb2, ROWB);
                ldsm_x4(afr[mt], ad);
            }
            uint32_t bfr[NT][2];
#pragma unroll
            for (int nt2 = 0; nt2 < NT / 2; nt2++) {
                uint32_t r[4];
                uint32_t bd = baseB + swz(rowB_base + nt2 * 16, ks * 2 + selb1, ROWB);
                ldsm_x4(r, bd);
                bfr[2 * nt2][0]     = r[0];
                bfr[2 * nt2][1]     = r[1];
                bfr[2 * nt2 + 1][0] = r[2];
                bfr[2 * nt2 + 1][1] = r[3];
            }
#pragma unroll
            for (int mt = 0; mt < 2; mt++)
#pragma unroll
                for (int nt = 0; nt < NT; nt++)
                    mma16816(acc[mt][nt], afr[mt], bfr[nt]);
        }
    }

    // ---- epilogue: direct global stores ----
    const int colb = wn * WN + (lane & 3) * 2;
#pragma unroll
    for (int mt = 0; mt < 2; mt++) {
        int r0 = bm + wm * 32 + mt * 16 + (lane >> 2);
        int r1 = r0 + 8;
#pragma unroll
        for (int nt = 0; nt < NT; nt++) {
            int col = colb + nt * 8;
            if (r0 < M) *(float2*)&C[(size_t)r0 * BN + col] =
                make_float2(acc[mt][nt][0], acc[mt][nt][1]);
            if (r1 < M) *(float2*)&C[(size_t)r1 * BN + col] =
                make_float2(acc[mt][nt][2], acc[mt][nt][3]);
        }
    }
}

// ---------------------------------------------------------------------------
// CSR build
// ---------------------------------------------------------------------------
__global__ void count_kernel(const int* __restrict__ dst, int e) {
    int i = blockIdx.x * blockDim.x + threadIdx.x;
    if (i < e) atomicAdd(&g_cnt[dst[i]], 1);
}

__global__ void scan_kernel(int n) {
    __shared__ int partial[1024];
    const int t = threadIdx.x;
    const int C = (n + 1023) / 1024;
    int s = 0;
    for (int j = 0; j < C; j++) {
        int idx = t * C + j;
        if (idx < n) s += g_cnt[idx];
    }
    partial[t] = s;
    __syncthreads();
    for (int ofs = 1; ofs < 1024; ofs <<= 1) {
        int v = (t >= ofs) ? partial[t - ofs] : 0;
        __syncthreads();
        partial[t] += v;
        __syncthreads();
    }
    int run = (t == 0) ? 0 : partial[t - 1];
    for (int j = 0; j < C; j++) {
        int idx = t * C + j;
        if (idx < n) {
            g_off[idx] = run;
            run += g_cnt[idx];
            g_cnt[idx] = 0;
        }
    }
    if (t == 1023) g_off[n] = run;
}

__global__ void fill_kernel(const int* __restrict__ src, const int* __restrict__ dst, int e) {
    int i = blockIdx.x * blockDim.x + threadIdx.x;
    if (i < e) {
        int d = dst[i];
        int p = atomicAdd(&g_cnt[d], 1);
        g_esrc[g_off[d] + p] = src[i];
    }
}

// ---------------------------------------------------------------------------
// el / er  (warp per node)
// ---------------------------------------------------------------------------
template <int HD>
__global__ void eler_kernel(const float* __restrict__ h,
                            const float* __restrict__ al,
                            const float* __restrict__ ar, int n)
{
    int warp = (blockIdx.x * blockDim.x + threadIdx.x) >> 5;
    int lane = threadIdx.x & 31;
    if (warp >= n) return;
    const float* row = h + (size_t)warp * HD;
    constexpr int KN = HD / 32;
    float pl0 = 0.f, pl1 = 0.f, pr0 = 0.f, pr1 = 0.f;
#pragma unroll
    for (int k = 0; k < KN; k++) {
        int idx = lane + 32 * k;
        float v = row[idx];
        if (32 * k < HD / 2) { pl0 += v * al[idx]; pr0 += v * ar[idx]; }
        else                 { pl1 += v * al[idx]; pr1 += v * ar[idx]; }
    }
#pragma unroll
    for (int o = 16; o; o >>= 1) {
        pl0 += __shfl_xor_sync(0xffffffffu, pl0, o);
        pl1 += __shfl_xor_sync(0xffffffffu, pl1, o);
        pr0 += __shfl_xor_sync(0xffffffffu, pr0, o);
        pr1 += __shfl_xor_sync(0xffffffffu, pr1, o);
    }
    if (lane == 0) {
        g_el[2 * warp]     = pl0;
        g_el[2 * warp + 1] = pl1;
        g_er[2 * warp]     = pr0;
        g_er[2 * warp + 1] = pr1;
    }
}

// ---------------------------------------------------------------------------
// Aggregation (warp per dst node, exact two-pass softmax)
// ---------------------------------------------------------------------------
__device__ __forceinline__ float leaky02(float x) { return x > 0.f ? x : 0.2f * x; }

template <int HD, int ACT, bool HEADMEAN>
__global__ void agg_kernel(const float* __restrict__ h,
                           const float* __restrict__ res,
                           float* __restrict__ out, int n)
{
    int node = (blockIdx.x * blockDim.x + threadIdx.x) >> 5;
    int lane = threadIdx.x & 31;
    if (node >= n) return;

    const int beg = g_off[node];
    const int end = g_off[node + 1];
    const float2 erv = ((const float2*)g_er)[node];

    float m0 = -1e30f, m1 = -1e30f;
    for (int i = beg; i < end; i++) {
        int s = g_esrc[i];
        float2 elv = ((const float2*)g_el)[s];
        m0 = fmaxf(m0, leaky02(elv.x + erv.x));
        m1 = fmaxf(m1, leaky02(elv.y + erv.y));
    }

    constexpr int KN = HD / 32;
    float acc[KN];
#pragma unroll
    for (int k = 0; k < KN; k++) acc[k] = 0.f;
    float d0 = 0.f, d1 = 0.f;

    for (int i = beg; i < end; i++) {
        int s = g_esrc[i];
        float2 elv = ((const float2*)g_el)[s];
        float w0 = __expf(leaky02(elv.x + erv.x) - m0);
        float w1 = __expf(leaky02(elv.y + erv.y) - m1);
        d0 += w0;
        d1 += w1;
        const float* hr = h + (size_t)s * HD;
#pragma unroll
        for (int k = 0; k < KN; k++) {
            float wv = (32 * k < HD / 2) ? w0 : w1;
            acc[k] = fmaf(wv, hr[lane + 32 * k], acc[k]);
        }
    }

    const bool has = (end > beg);
    const float inv0 = has ? 1.f / d0 : 0.f;
    const float inv1 = has ? 1.f / d1 : 0.f;
    const float* rr = res + (size_t)node * HD;

    if (HEADMEAN) {
#pragma unroll
        for (int k = 0; k < 2; k++) {
            int idx = lane + 32 * k;
            float v0 = acc[k]     * inv0 + rr[idx];
            float v1 = acc[k + 2] * inv1 + rr[idx + 64];
            v0 = v0 > 0.f ? v0 : expm1f(v0);
            v1 = v1 > 0.f ? v1 : expm1f(v1);
            out[(size_t)node * 64 + idx] = 0.5f * (v0 + v1);
        }
    } else {
#pragma unroll
        for (int k = 0; k < KN; k++) {
            int idx = lane + 32 * k;
            float inv = (32 * k < HD / 2) ? inv0 : inv1;
            float v = acc[k] * inv + rr[idx];
            if (ACT == 0) v = v > 0.f ? v : expm1f(v);
            else          v = tanhf(v);
            out[(size_t)node * HD + idx] = v;
        }
    }
}

// ---------------------------------------------------------------------------
// Launch
// ---------------------------------------------------------------------------
extern "C" void kernel_launch(void* const* d_in, const int* in_sizes, int n_in,
                              void* d_out, int out_size)
{
    const float* fvs = (const float*)d_in[0];
    const float* pos = (const float*)d_in[1];
    const int*   src = (const int*)d_in[2];
    const int*   dst = (const int*)d_in[3];
    const float* g0W  = (const float*)d_in[4];
    const float* g0al = (const float*)d_in[5];
    const float* g0ar = (const float*)d_in[6];
    const float* g0rW = (const float*)d_in[7];
    const float* g1W  = (const float*)d_in[8];
    const float* g1al = (const float*)d_in[9];
    const float* g1ar = (const float*)d_in[10];
    const float* g1rW = (const float*)d_in[11];
    const float* g2W  = (const float*)d_in[12];
    const float* g2al = (const float*)d_in[13];
    const float* g2ar = (const float*)d_in[14];
    const float* g2rW = (const float*)d_in[15];
    const float* p0W  = (const float*)d_in[16];
    const float* p0al = (const float*)d_in[17];
    const float* p0ar = (const float*)d_in[18];
    const float* p1W  = (const float*)d_in[19];
    const float* p1al = (const float*)d_in[20];
    const float* p1ar = (const float*)d_in[21];

    const int n = in_sizes[0] / 128;
    const int e = in_sizes[2];

    float *h, *rh, *hs, *hs2, *hp;
    int* cnt;
    uint16_t *wthi, *wtlo;
    cudaGetSymbolAddress((void**)&h,    g_h);
    cudaGetSymbolAddress((void**)&rh,   g_rh);
    cudaGetSymbolAddress((void**)&hs,   g_hs);
    cudaGetSymbolAddress((void**)&hs2,  g_hs2);
    cudaGetSymbolAddress((void**)&hp,   g_hp);
    cudaGetSymbolAddress((void**)&cnt,  g_cnt);
    cudaGetSymbolAddress((void**)&wthi, g_wthi);
    cudaGetSymbolAddress((void**)&wtlo, g_wtlo);

    float* out_hs = (float*)d_out;
    float* out_hp = (float*)d_out + (size_t)n * 64;

    const int EB = (e + 255) / 256;
    const int GB = (n + 127) / 128;
    const int WB = (n + 7) / 8;

    constexpr int SMEM_BIG   = (128 + 128 + 128 + 128) * 192 * 2;  // 196608
    constexpr int SMEM_SMALL = (128 + 128 + 64 + 64) * 64 * 2;     // 49152
    cudaFuncSetAttribute(tc_gemm<128, 192>, cudaFuncAttributeMaxDynamicSharedMemorySize, SMEM_BIG);
    cudaFuncSetAttribute(tc_gemm<64, 64>,   cudaFuncAttributeMaxDynamicSharedMemorySize, SMEM_SMALL);

    // ---- weight prep ----
    Prep8 pa;
    const float* Ws[8] = {g0W, g0rW, g1W, g1rW, g2W, g2rW, p0W, p1W};
    for (int m = 0; m < 8; m++) {
        pa.W[m] = Ws[m];
        pa.K[m] = (m < 6) ? 192 : 64;
        pa.N[m] = (m < 6) ? 128 : 64;
        pa.off[m] = (m < 6) ? m * WT_BIG : 6 * WT_BIG + (m - 6) * WT_SMALL;
    }
    prep_kernel<<<64, 256>>>(pa);

    // ---- CSR build ----
    cudaMemsetAsync(cnt, 0, (size_t)n * sizeof(int));
    count_kernel<<<EB, 256>>>(dst, e);
    scan_kernel<<<1, 1024>>>(n);
    fill_kernel<<<EB, 256>>>(src, dst, e);

    const int O0 = 0 * WT_BIG, O1 = 1 * WT_BIG, O2 = 2 * WT_BIG;
    const int O3 = 3 * WT_BIG, O4 = 4 * WT_BIG, O5 = 5 * WT_BIG;
    const int P0 = 6 * WT_BIG, P1 = 6 * WT_BIG + WT_SMALL;

    // ---- layer 0 ----
    tc_gemm<128, 192><<<GB, 256, SMEM_BIG>>>(fvs, 128, pos, wthi + O0, wtlo + O0, h,  n);
    tc_gemm<128, 192><<<GB, 256, SMEM_BIG>>>(fvs, 128, pos, wthi + O1, wtlo + O1, rh, n);
    eler_kernel<128><<<WB, 256>>>(h, g0al, g0ar, n);
    agg_kernel<128, 0, false><<<WB, 256>>>(h, rh, hs, n);
    tc_gemm<64, 64><<<GB, 256, SMEM_SMALL>>>(pos, 64, (const float*)nullptr, wthi + P0, wtlo + P0, h, n);
    eler_kernel<64><<<WB, 256>>>(h, p0al, p0ar, n);
    agg_kernel<64, 1, false><<<WB, 256>>>(h, pos, hp, n);

    // ---- layer 1 ----
    tc_gemm<128, 192><<<GB, 256, SMEM_BIG>>>(hs, 128, hp, wthi + O2, wtlo + O2, h,  n);
    tc_gemm<128, 192><<<GB, 256, SMEM_BIG>>>(hs, 128, hp, wthi + O3, wtlo + O3, rh, n);
    eler_kernel<128><<<WB, 256>>>(h, g1al, g1ar, n);
    agg_kernel<128, 0, false><<<WB, 256>>>(h, rh, hs2, n);
    tc_gemm<64, 64><<<GB, 256, SMEM_SMALL>>>(hp, 64, (const float*)nullptr, wthi + P1, wtlo + P1, h, n);
    eler_kernel<64><<<WB, 256>>>(h, p1al, p1ar, n);
    agg_kernel<64, 1, false><<<WB, 256>>>(h, hp, out_hp, n);

    // ---- layer 2 (output, head-mean) ----
    tc_gemm<128, 192><<<GB, 256, SMEM_BIG>>>(hs2, 128, out_hp, wthi + O4, wtlo + O4, h,  n);
    tc_gemm<128, 192><<<GB, 256, SMEM_BIG>>>(hs2, 128, out_hp, wthi + O5, wtlo + O5, rh, n);
    eler_kernel<128><<<WB, 256>>>(h, g2al, g2ar, n);
    agg_kernel<128, 0, true><<<WB, 256>>>(h, rh, out_hs, n);
}

// round 5
// speedup vs baseline: 1.7352x; 1.1986x over previous
#include <cuda_runtime.h>
#include <cuda_bf16.h>
#include <math.h>
#include <stdint.h>

// ---------------------------------------------------------------------------
// Problem constants
// ---------------------------------------------------------------------------
#define NMAX 50000
#define EMAX 800000

// ---------------------------------------------------------------------------
// Scratch (device globals)
// ---------------------------------------------------------------------------
__device__ float g_h  [(size_t)NMAX * 128];
__device__ float g_rh [(size_t)NMAX * 128];
__device__ float g_hs [(size_t)NMAX * 128];
__device__ float g_hs2[(size_t)NMAX * 128];
__device__ float g_hp [(size_t)NMAX * 64];
__device__ float g_el [(size_t)NMAX * 2];
__device__ float g_er [(size_t)NMAX * 2];
__device__ int   g_off[NMAX + 1];
__device__ int   g_cnt[NMAX];
__device__ int   g_esrc[EMAX];

// Fused transposed hi/lo bf16 weights:
// 3 fused big mats [256 x 192]  (rows 0-127 = W^T, rows 128-255 = rW^T)
// 2 small mats [64 x 64]
#define WT_FUSED (256 * 192)
#define WT_SMALL (64 * 64)
__device__ uint16_t g_wthi[3 * WT_FUSED + 2 * WT_SMALL];
__device__ uint16_t g_wtlo[3 * WT_FUSED + 2 * WT_SMALL];

// ---------------------------------------------------------------------------
// Helpers
// ---------------------------------------------------------------------------
__device__ __forceinline__ uint32_t smem_u32(const void* p) {
    uint32_t a;
    asm("{ .reg .u64 t; cvta.to.shared.u64 t, %1; cvt.u32.u64 %0, t; }"
        : "=r"(a) : "l"(p));
    return a;
}

__device__ __forceinline__ void ldsm_x4(uint32_t* r, uint32_t addr) {
    asm volatile("ldmatrix.sync.aligned.m8n8.x4.shared.b16 {%0,%1,%2,%3}, [%4];"
                 : "=r"(r[0]), "=r"(r[1]), "=r"(r[2]), "=r"(r[3]) : "r"(addr));
}

__device__ __forceinline__ void mma16816(float* c, const uint32_t* a, const uint32_t* b) {
    asm volatile(
        "mma.sync.aligned.m16n8k16.row.col.f32.bf16.bf16.f32 "
        "{%0,%1,%2,%3}, {%4,%5,%6,%7}, {%8,%9}, {%0,%1,%2,%3};"
        : "+f"(c[0]), "+f"(c[1]), "+f"(c[2]), "+f"(c[3])
        : "r"(a[0]), "r"(a[1]), "r"(a[2]), "r"(a[3]), "r"(b[0]), "r"(b[1]));
}

__device__ __forceinline__ void cpasync16(uint32_t s, const void* g) {
    asm volatile("cp.async.cg.shared.global [%0], [%1], 16;" :: "r"(s), "l"(g));
}
__device__ __forceinline__ void cpasync_wait() {
    asm volatile("cp.async.commit_group;");
    asm volatile("cp.async.wait_group 0;" ::: "memory");
}

__device__ __forceinline__ void split8(const float* v, uint4& h4, uint4& l4) {
    uint16_t* hp = (uint16_t*)&h4;
    uint16_t* lp = (uint16_t*)&l4;
#pragma unroll
    for (int i = 0; i < 8; i++) {
        __nv_bfloat16 hb = __float2bfloat16(v[i]);
        float r = v[i] - __bfloat162float(hb);
        __nv_bfloat16 lb = __float2bfloat16(r);
        hp[i] = *(uint16_t*)&hb;
        lp[i] = *(uint16_t*)&lb;
    }
}

// 16B-chunk XOR swizzle within 128B groups: conflict-free ldmatrix + STS.
__device__ __forceinline__ uint32_t swz(int row, int g, int ROWB) {
    int c = (g & ~7) | ((g ^ row) & 7);
    return (uint32_t)(row * ROWB + c * 16);
}

// ---------------------------------------------------------------------------
// Weight prep: build fused [W|rW]^T hi/lo planes.
// ---------------------------------------------------------------------------
struct Prep8 {
    const float* W[8];
    int K[8], N[8], off[8];
};

__global__ void prep_kernel(Prep8 p) {
    for (int m = 0; m < 8; m++) {
        const int K = p.K[m], N = p.N[m], tot = K * N, off = p.off[m];
        const float* W = p.W[m];
        for (int idx = blockIdx.x * blockDim.x + threadIdx.x; idx < tot;
             idx += gridDim.x * blockDim.x) {
            int n = idx / K, k = idx - n * K;
            float w = W[(size_t)k * N + n];
            __nv_bfloat16 h = __float2bfloat16(w);
            float r = w - __bfloat162float(h);
            __nv_bfloat16 l = __float2bfloat16(r);
            g_wthi[off + idx] = *(uint16_t*)&h;
            g_wtlo[off + idx] = *(uint16_t*)&l;
        }
    }
}

// ---------------------------------------------------------------------------
// Fused bf16x3 GEMM:  [C1 | C2][M,128+128] = [A1|A2][M,192] @ [W|rW]^T
// Full K resident in SMEM for A (hi+lo); B staged (Bh then Bl) via cp.async.
// D = Ah*Bh + Al*Bh + Ah*Bl.
// 8 warps: 4(M) x 2(N); warp tile 32 x 128. wn=0 -> C1, wn=1 -> C2.
// ---------------------------------------------------------------------------
template <int K>
__global__ __launch_bounds__(256, 1) void tc_gemm_fused(
    const float* __restrict__ A1, int K1,
    const float* __restrict__ A2,
    const uint16_t* __restrict__ Bh, const uint16_t* __restrict__ Bl,
    float* __restrict__ C1, float* __restrict__ C2, int M)
{
    constexpr int BN   = 256;
    constexpr int ROWB = K * 2;          // 384 bytes per smem row
    constexpr int NG   = K / 8;          // 24 16B chunks per row
    constexpr int WN   = 128;            // warp N extent
    constexpr int NT   = WN / 8;         // 16 n8 frags
    constexpr int KS   = K / 16;         // 12 k-steps
    constexpr int AOFF = 0;              // sAH
    constexpr int ALOFF = 128 * ROWB;    // sAL
    constexpr int BOFF  = 2 * 128 * ROWB;// staged B

    extern __shared__ char smem[];
    const uint32_t sb  = smem_u32(smem);
    const uint32_t sAH = sb + AOFF;
    const uint32_t sAL = sb + ALOFF;
    const uint32_t sB  = sb + BOFF;

    const int t    = threadIdx.x;
    const int wid  = t >> 5;
    const int lane = t & 31;
    const int bm   = blockIdx.x * 128;

    // ---- stage 1 B load (cp.async, overlapped with A load/split) ----
    for (int idx = t; idx < BN * NG; idx += 256) {
        int rn = idx / NG, g = idx - rn * NG;
        cpasync16(sB + swz(rn, g, ROWB), Bh + (size_t)rn * K + g * 8);
    }

    // ---- load + split A (implicit concat A1|A2) ----
    for (int idx = t; idx < 128 * NG; idx += 256) {
        int row = idx / NG, g = idx - row * NG, k0 = g * 8;
        int grow = bm + row;
        float v[8] = {0, 0, 0, 0, 0, 0, 0, 0};
        if (grow < M) {
            const float* p = (k0 < K1) ? (A1 + (size_t)grow * K1 + k0)
                                       : (A2 + (size_t)grow * (K - K1) + (k0 - K1));
            *(float4*)&v[0] = ((const float4*)p)[0];
            *(float4*)&v[4] = ((const float4*)p)[1];
        }
        uint4 h4, l4;
        split8(v, h4, l4);
        uint32_t o = swz(row, g, ROWB);
        *(uint4*)(smem + AOFF + o)  = h4;
        *(uint4*)(smem + ALOFF + o) = l4;
    }
    cpasync_wait();
    __syncthreads();

    const int wm   = wid & 3;
    const int wn   = wid >> 2;
    const int lr   = lane & 7;
    const int sel  = lane >> 3;
    const int selb1 = sel & 1;
    const int selb2 = sel >> 1;
    const int rowA_base = wm * 32 + lr + selb1 * 8;
    const int rowB_base = wn * WN + lr + selb2 * 8;

    float acc[2][NT][4];
#pragma unroll
    for (int mt = 0; mt < 2; mt++)
#pragma unroll
        for (int nt = 0; nt < NT; nt++)
#pragma unroll
            for (int q = 0; q < 4; q++) acc[mt][nt][q] = 0.f;

    // ---- stage 1: Ah*Bh + Al*Bh ----
#pragma unroll
    for (int ks = 0; ks < KS; ks++) {
        uint32_t bfr[NT][2];
#pragma unroll
        for (int nt2 = 0; nt2 < NT / 2; nt2++) {
            uint32_t r[4];
            ldsm_x4(r, sB + swz(rowB_base + nt2 * 16, ks * 2 + selb1, ROWB));
            bfr[2 * nt2][0]     = r[0];
            bfr[2 * nt2][1]     = r[1];
            bfr[2 * nt2 + 1][0] = r[2];
            bfr[2 * nt2 + 1][1] = r[3];
        }
        uint32_t afr[2][4];
#pragma unroll
        for (int mt = 0; mt < 2; mt++)
            ldsm_x4(afr[mt], sAH + swz(rowA_base + mt * 16, ks * 2 + selb2, ROWB));
#pragma unroll
        for (int mt = 0; mt < 2; mt++)
#pragma unroll
            for (int nt = 0; nt < NT; nt++)
                mma16816(acc[mt][nt], afr[mt], bfr[nt]);
#pragma unroll
        for (int mt = 0; mt < 2; mt++)
            ldsm_x4(afr[mt], sAL + swz(rowA_base + mt * 16, ks * 2 + selb2, ROWB));
#pragma unroll
        for (int mt = 0; mt < 2; mt++)
#pragma unroll
            for (int nt = 0; nt < NT; nt++)
                mma16816(acc[mt][nt], afr[mt], bfr[nt]);
    }

    // ---- swap B buffer to Bl ----
    __syncthreads();
    for (int idx = t; idx < BN * NG; idx += 256) {
        int rn = idx / NG, g = idx - rn * NG;
        cpasync16(sB + swz(rn, g, ROWB), Bl + (size_t)rn * K + g * 8);
    }
    cpasync_wait();
    __syncthreads();

    // ---- stage 2: Ah*Bl ----
#pragma unroll
    for (int ks = 0; ks < KS; ks++) {
        uint32_t bfr[NT][2];
#pragma unroll
        for (int nt2 = 0; nt2 < NT / 2; nt2++) {
            uint32_t r[4];
            ldsm_x4(r, sB + swz(rowB_base + nt2 * 16, ks * 2 + selb1, ROWB));
            bfr[2 * nt2][0]     = r[0];
            bfr[2 * nt2][1]     = r[1];
            bfr[2 * nt2 + 1][0] = r[2];
            bfr[2 * nt2 + 1][1] = r[3];
        }
        uint32_t afr[2][4];
#pragma unroll
        for (int mt = 0; mt < 2; mt++)
            ldsm_x4(afr[mt], sAH + swz(rowA_base + mt * 16, ks * 2 + selb2, ROWB));
#pragma unroll
        for (int mt = 0; mt < 2; mt++)
#pragma unroll
            for (int nt = 0; nt < NT; nt++)
                mma16816(acc[mt][nt], afr[mt], bfr[nt]);
    }

    // ---- epilogue: wn=0 -> C1, wn=1 -> C2 ----
    float* __restrict__ C = (wn == 0) ? C1 : C2;
    const int colb = (lane & 3) * 2;
#pragma unroll
    for (int mt = 0; mt < 2; mt++) {
        int r0 = bm + wm * 32 + mt * 16 + (lane >> 2);
        int r1 = r0 + 8;
#pragma unroll
        for (int nt = 0; nt < NT; nt++) {
            int col = colb + nt * 8;
            if (r0 < M) *(float2*)&C[(size_t)r0 * 128 + col] =
                make_float2(acc[mt][nt][0], acc[mt][nt][1]);
            if (r1 < M) *(float2*)&C[(size_t)r1 * 128 + col] =
                make_float2(acc[mt][nt][2], acc[mt][nt][3]);
        }
    }
}

// ---------------------------------------------------------------------------
// Small bf16x3 GEMM (pg layers): C[M,64] = A[M,64] @ Wt^T, full K resident.
// ---------------------------------------------------------------------------
template <int BN, int K>
__global__ __launch_bounds__(256, 1) void tc_gemm(
    const float* __restrict__ A1,
    const uint16_t* __restrict__ Bh, const uint16_t* __restrict__ Bl,
    float* __restrict__ C, int M)
{
    constexpr int ROWB = K * 2;
    constexpr int NG   = K / 8;
    constexpr int WN   = BN / 2;
    constexpr int NT   = WN / 8;
    constexpr int KS   = K / 16;

    extern __shared__ char smem[];
    const uint32_t sAH = smem_u32(smem);
    const uint32_t sAL = sAH + 128 * ROWB;
    const uint32_t sBH = sAL + 128 * ROWB;
    const uint32_t sBL = sBH + BN * ROWB;

    const int t    = threadIdx.x;
    const int wid  = t >> 5;
    const int lane = t & 31;
    const int bm   = blockIdx.x * 128;

    for (int idx = t; idx < BN * NG; idx += 256) {
        int rn = idx / NG, g = idx - rn * NG, k0 = g * 8;
        cpasync16(sBH + swz(rn, g, ROWB), Bh + (size_t)rn * K + k0);
        cpasync16(sBL + swz(rn, g, ROWB), Bl + (size_t)rn * K + k0);
    }
    for (int idx = t; idx < 128 * NG; idx += 256) {
        int row = idx / NG, g = idx - row * NG, k0 = g * 8;
        int grow = bm + row;
        float v[8] = {0, 0, 0, 0, 0, 0, 0, 0};
        if (grow < M) {
            const float* p = A1 + (size_t)grow * K + k0;
            *(float4*)&v[0] = ((const float4*)p)[0];
            *(float4*)&v[4] = ((const float4*)p)[1];
        }
        uint4 h4, l4;
        split8(v, h4, l4);
        uint32_t o = swz(row, g, ROWB);
        *(uint4*)(smem + o) = h4;
        *(uint4*)(smem + 128 * ROWB + o) = l4;
    }
    cpasync_wait();
    __syncthreads();

    const int wm = wid & 3;
    const int wn = wid >> 2;
    const int lr   = lane & 7;
    const int sel  = lane >> 3;
    const int selb1 = sel & 1;
    const int selb2 = sel >> 1;
    const int rowA_base = wm * 32 + lr + selb1 * 8;
    const int rowB_base = wn * WN + lr + selb2 * 8;

    float acc[2][NT][4];
#pragma unroll
    for (int mt = 0; mt < 2; mt++)
#pragma unroll
        for (int nt = 0; nt < NT; nt++)
#pragma unroll
            for (int q = 0; q < 4; q++) acc[mt][nt][q] = 0.f;

#pragma unroll
    for (int pr = 0; pr < 3; pr++) {
        const uint32_t baseA = (pr == 2) ? sAL : sAH;
        const uint32_t baseB = (pr == 1) ? sBL : sBH;
#pragma unroll
        for (int ks = 0; ks < KS; ks++) {
            uint32_t afr[2][4];
#pragma unroll
            for (int mt = 0; mt < 2; mt++)
                ldsm_x4(afr[mt], baseA + swz(rowA_base + mt * 16, ks * 2 + selb2, ROWB));
            uint32_t bfr[NT][2];
#pragma unroll
            for (int nt2 = 0; nt2 < NT / 2; nt2++) {
                uint32_t r[4];
                ldsm_x4(r, baseB + swz(rowB_base + nt2 * 16, ks * 2 + selb1, ROWB));
                bfr[2 * nt2][0]     = r[0];
                bfr[2 * nt2][1]     = r[1];
                bfr[2 * nt2 + 1][0] = r[2];
                bfr[2 * nt2 + 1][1] = r[3];
            }
#pragma unroll
            for (int mt = 0; mt < 2; mt++)
#pragma unroll
                for (int nt = 0; nt < NT; nt++)
                    mma16816(acc[mt][nt], afr[mt], bfr[nt]);
        }
    }

    const int colb = wn * WN + (lane & 3) * 2;
#pragma unroll
    for (int mt = 0; mt < 2; mt++) {
        int r0 = bm + wm * 32 + mt * 16 + (lane >> 2);
        int r1 = r0 + 8;
#pragma unroll
        for (int nt = 0; nt < NT; nt++) {
            int col = colb + nt * 8;
            if (r0 < M) *(float2*)&C[(size_t)r0 * BN + col] =
                make_float2(acc[mt][nt][0], acc[mt][nt][1]);
            if (r1 < M) *(float2*)&C[(size_t)r1 * BN + col] =
                make_float2(acc[mt][nt][2], acc[mt][nt][3]);
        }
    }
}

// ---------------------------------------------------------------------------
// CSR build
// ---------------------------------------------------------------------------
__global__ void count_kernel(const int* __restrict__ dst, int e) {
    int i = blockIdx.x * blockDim.x + threadIdx.x;
    if (i < e) atomicAdd(&g_cnt[dst[i]], 1);
}

__global__ void scan_kernel(int n) {
    __shared__ int partial[1024];
    const int t = threadIdx.x;
    const int C = (n + 1023) / 1024;
    int s = 0;
    for (int j = 0; j < C; j++) {
        int idx = t * C + j;
        if (idx < n) s += g_cnt[idx];
    }
    partial[t] = s;
    __syncthreads();
    for (int ofs = 1; ofs < 1024; ofs <<= 1) {
        int v = (t >= ofs) ? partial[t - ofs] : 0;
        __syncthreads();
        partial[t] += v;
        __syncthreads();
    }
    int run = (t == 0) ? 0 : partial[t - 1];
    for (int j = 0; j < C; j++) {
        int idx = t * C + j;
        if (idx < n) {
            g_off[idx] = run;
            run += g_cnt[idx];
            g_cnt[idx] = 0;
        }
    }
    if (t == 1023) g_off[n] = run;
}

__global__ void fill_kernel(const int* __restrict__ src, const int* __restrict__ dst, int e) {
    int i = blockIdx.x * blockDim.x + threadIdx.x;
    if (i < e) {
        int d = dst[i];
        int p = atomicAdd(&g_cnt[d], 1);
        g_esrc[g_off[d] + p] = src[i];
    }
}

// ---------------------------------------------------------------------------
// el / er  (warp per node)
// ---------------------------------------------------------------------------
template <int HD>
__global__ void eler_kernel(const float* __restrict__ h,
                            const float* __restrict__ al,
                            const float* __restrict__ ar, int n)
{
    int warp = (blockIdx.x * blockDim.x + threadIdx.x) >> 5;
    int lane = threadIdx.x & 31;
    if (warp >= n) return;
    const float* row = h + (size_t)warp * HD;
    constexpr int KN = HD / 32;
    float pl0 = 0.f, pl1 = 0.f, pr0 = 0.f, pr1 = 0.f;
#pragma unroll
    for (int k = 0; k < KN; k++) {
        int idx = lane + 32 * k;
        float v = row[idx];
        if (32 * k < HD / 2) { pl0 += v * al[idx]; pr0 += v * ar[idx]; }
        else                 { pl1 += v * al[idx]; pr1 += v * ar[idx]; }
    }
#pragma unroll
    for (int o = 16; o; o >>= 1) {
        pl0 += __shfl_xor_sync(0xffffffffu, pl0, o);
        pl1 += __shfl_xor_sync(0xffffffffu, pl1, o);
        pr0 += __shfl_xor_sync(0xffffffffu, pr0, o);
        pr1 += __shfl_xor_sync(0xffffffffu, pr1, o);
    }
    if (lane == 0) {
        g_el[2 * warp]     = pl0;
        g_el[2 * warp + 1] = pl1;
        g_er[2 * warp]     = pr0;
        g_er[2 * warp + 1] = pr1;
    }
}

// ---------------------------------------------------------------------------
// Aggregation (warp per dst node, exact two-pass softmax)
// ---------------------------------------------------------------------------
__device__ __forceinline__ float leaky02(float x) { return x > 0.f ? x : 0.2f * x; }

template <int HD, int ACT, bool HEADMEAN>
__global__ void agg_kernel(const float* __restrict__ h,
                           const float* __restrict__ res,
                           float* __restrict__ out, int n)
{
    int node = (blockIdx.x * blockDim.x + threadIdx.x) >> 5;
    int lane = threadIdx.x & 31;
    if (node >= n) return;

    const int beg = g_off[node];
    const int end = g_off[node + 1];
    const float2 erv = ((const float2*)g_er)[node];

    float m0 = -1e30f, m1 = -1e30f;
    for (int i = beg; i < end; i++) {
        int s = g_esrc[i];
        float2 elv = ((const float2*)g_el)[s];
        m0 = fmaxf(m0, leaky02(elv.x + erv.x));
        m1 = fmaxf(m1, leaky02(elv.y + erv.y));
    }

    constexpr int KN = HD / 32;
    float acc[KN];
#pragma unroll
    for (int k = 0; k < KN; k++) acc[k] = 0.f;
    float d0 = 0.f, d1 = 0.f;

    for (int i = beg; i < end; i++) {
        int s = g_esrc[i];
        float2 elv = ((const float2*)g_el)[s];
        float w0 = __expf(leaky02(elv.x + erv.x) - m0);
        float w1 = __expf(leaky02(elv.y + erv.y) - m1);
        d0 += w0;
        d1 += w1;
        const float* hr = h + (size_t)s * HD;
#pragma unroll
        for (int k = 0; k < KN; k++) {
            float wv = (32 * k < HD / 2) ? w0 : w1;
            acc[k] = fmaf(wv, hr[lane + 32 * k], acc[k]);
        }
    }

    const bool has = (end > beg);
    const float inv0 = has ? 1.f / d0 : 0.f;
    const float inv1 = has ? 1.f / d1 : 0.f;
    const float* rr = res + (size_t)node * HD;

    if (HEADMEAN) {
#pragma unroll
        for (int k = 0; k < 2; k++) {
            int idx = lane + 32 * k;
            float v0 = acc[k]     * inv0 + rr[idx];
            float v1 = acc[k + 2] * inv1 + rr[idx + 64];
            v0 = v0 > 0.f ? v0 : expm1f(v0);
            v1 = v1 > 0.f ? v1 : expm1f(v1);
            out[(size_t)node * 64 + idx] = 0.5f * (v0 + v1);
        }
    } else {
#pragma unroll
        for (int k = 0; k < KN; k++) {
            int idx = lane + 32 * k;
            float inv = (32 * k < HD / 2) ? inv0 : inv1;
            float v = acc[k] * inv + rr[idx];
            if (ACT == 0) v = v > 0.f ? v : expm1f(v);
            else          v = tanhf(v);
            out[(size_t)node * HD + idx] = v;
        }
    }
}

// ---------------------------------------------------------------------------
// Launch
// ---------------------------------------------------------------------------
extern "C" void kernel_launch(void* const* d_in, const int* in_sizes, int n_in,
                              void* d_out, int out_size)
{
    const float* fvs = (const float*)d_in[0];
    const float* pos = (const float*)d_in[1];
    const int*   src = (const int*)d_in[2];
    const int*   dst = (const int*)d_in[3];
    const float* g0W  = (const float*)d_in[4];
    const float* g0al = (const float*)d_in[5];
    const float* g0ar = (const float*)d_in[6];
    const float* g0rW = (const float*)d_in[7];
    const float* g1W  = (const float*)d_in[8];
    const float* g1al = (const float*)d_in[9];
    const float* g1ar = (const float*)d_in[10];
    const float* g1rW = (const float*)d_in[11];
    const float* g2W  = (const float*)d_in[12];
    const float* g2al = (const float*)d_in[13];
    const float* g2ar = (const float*)d_in[14];
    const float* g2rW = (const float*)d_in[15];
    const float* p0W  = (const float*)d_in[16];
    const float* p0al = (const float*)d_in[17];
    const float* p0ar = (const float*)d_in[18];
    const float* p1W  = (const float*)d_in[19];
    const float* p1al = (const float*)d_in[20];
    const float* p1ar = (const float*)d_in[21];

    const int n = in_sizes[0] / 128;
    const int e = in_sizes[2];

    float *h, *rh, *hs, *hs2, *hp;
    int* cnt;
    uint16_t *wthi, *wtlo;
    cudaGetSymbolAddress((void**)&h,    g_h);
    cudaGetSymbolAddress((void**)&rh,   g_rh);
    cudaGetSymbolAddress((void**)&hs,   g_hs);
    cudaGetSymbolAddress((void**)&hs2,  g_hs2);
    cudaGetSymbolAddress((void**)&hp,   g_hp);
    cudaGetSymbolAddress((void**)&cnt,  g_cnt);
    cudaGetSymbolAddress((void**)&wthi, g_wthi);
    cudaGetSymbolAddress((void**)&wtlo, g_wtlo);

    float* out_hs = (float*)d_out;
    float* out_hp = (float*)d_out + (size_t)n * 64;

    const int EB = (e + 255) / 256;
    const int GB = (n + 127) / 128;
    const int WB = (n + 7) / 8;

    // Fused: A(hi+lo) 2*128*384 + staged B 256*384 = 196608
    constexpr int SMEM_F     = 2 * 128 * 384 + 256 * 384;
    constexpr int SMEM_SMALL = (128 + 128 + 64 + 64) * 64 * 2;     // 49152
    cudaFuncSetAttribute(tc_gemm_fused<192>, cudaFuncAttributeMaxDynamicSharedMemorySize, SMEM_F);
    cudaFuncSetAttribute(tc_gemm<64, 64>,    cudaFuncAttributeMaxDynamicSharedMemorySize, SMEM_SMALL);

    // ---- weight prep: fused [W|rW]^T layout ----
    Prep8 pa;
    const float* Ws[8] = {g0W, g0rW, g1W, g1rW, g2W, g2rW, p0W, p1W};
    for (int m = 0; m < 8; m++) {
        pa.W[m] = Ws[m];
        pa.K[m] = (m < 6) ? 192 : 64;
        pa.N[m] = (m < 6) ? 128 : 64;
        pa.off[m] = (m < 6) ? (m >> 1) * WT_FUSED + (m & 1) * (128 * 192)
                            : 3 * WT_FUSED + (m - 6) * WT_SMALL;
    }
    prep_kernel<<<64, 256>>>(pa);

    // ---- CSR build ----
    cudaMemsetAsync(cnt, 0, (size_t)n * sizeof(int));
    count_kernel<<<EB, 256>>>(dst, e);
    scan_kernel<<<1, 1024>>>(n);
    fill_kernel<<<EB, 256>>>(src, dst, e);

    const int F0 = 0 * WT_FUSED, F1 = 1 * WT_FUSED, F2 = 2 * WT_FUSED;
    const int P0 = 3 * WT_FUSED, P1 = 3 * WT_FUSED + WT_SMALL;

    // ---- layer 0 ----
    tc_gemm_fused<192><<<GB, 256, SMEM_F>>>(fvs, 128, pos, wthi + F0, wtlo + F0, h, rh, n);
    eler_kernel<128><<<WB, 256>>>(h, g0al, g0ar, n);
    agg_kernel<128, 0, false><<<WB, 256>>>(h, rh, hs, n);
    tc_gemm<64, 64><<<GB, 256, SMEM_SMALL>>>(pos, wthi + P0, wtlo + P0, h, n);
    eler_kernel<64><<<WB, 256>>>(h, p0al, p0ar, n);
    agg_kernel<64, 1, false><<<WB, 256>>>(h, pos, hp, n);

    // ---- layer 1 ----
    tc_gemm_fused<192><<<GB, 256, SMEM_F>>>(hs, 128, hp, wthi + F1, wtlo + F1, h, rh, n);
    eler_kernel<128><<<WB, 256>>>(h, g1al, g1ar, n);
    agg_kernel<128, 0, false><<<WB, 256>>>(h, rh, hs2, n);
    tc_gemm<64, 64><<<GB, 256, SMEM_SMALL>>>(hp, wthi + P1, wtlo + P1, h, n);
    eler_kernel<64><<<WB, 256>>>(h, p1al, p1ar, n);
    agg_kernel<64, 1, false><<<WB, 256>>>(h, hp, out_hp, n);

    // ---- layer 2 (output, head-mean) ----
    tc_gemm_fused<192><<<GB, 256, SMEM_F>>>(hs2, 128, out_hp, wthi + F2, wtlo + F2, h, rh, n);
    eler_kernel<128><<<WB, 256>>>(h, g2al, g2ar, n);
    agg_kernel<128, 0, true><<<WB, 256>>>(h, rh, out_hs, n);
}

// round 6
// speedup vs baseline: 1.7669x; 1.0183x over previous
#include <cuda_runtime.h>
#include <cuda_bf16.h>
#include <math.h>
#include <stdint.h>

// ---------------------------------------------------------------------------
// Problem constants
// ---------------------------------------------------------------------------
#define NMAX 50000
#define EMAX 800000

// ---------------------------------------------------------------------------
// Scratch (device globals)
// ---------------------------------------------------------------------------
__device__ float g_h  [(size_t)NMAX * 128];
__device__ float g_rh [(size_t)NMAX * 128];
__device__ float g_hs [(size_t)NMAX * 128];
__device__ float g_hs2[(size_t)NMAX * 128];
__device__ float g_hp [(size_t)NMAX * 64];
__device__ float g_el [(size_t)NMAX * 2];
__device__ float g_er [(size_t)NMAX * 2];
__device__ int   g_off[NMAX + 1];
__device__ int   g_cnt[NMAX];
__device__ int   g_esrc[EMAX];

// Fused transposed hi/lo bf16 weights:
// 3 fused big mats [256 x 192]  (rows 0-127 = W^T, rows 128-255 = rW^T)
// 2 small mats [64 x 64]
#define WT_FUSED (256 * 192)
#define WT_SMALL (64 * 64)
__device__ uint16_t g_wthi[3 * WT_FUSED + 2 * WT_SMALL];
__device__ uint16_t g_wtlo[3 * WT_FUSED + 2 * WT_SMALL];

// ---------------------------------------------------------------------------
// Helpers
// ---------------------------------------------------------------------------
__device__ __forceinline__ uint32_t smem_u32(const void* p) {
    uint32_t a;
    asm("{ .reg .u64 t; cvta.to.shared.u64 t, %1; cvt.u32.u64 %0, t; }"
        : "=r"(a) : "l"(p));
    return a;
}

__device__ __forceinline__ void ldsm_x4(uint32_t* r, uint32_t addr) {
    asm volatile("ldmatrix.sync.aligned.m8n8.x4.shared.b16 {%0,%1,%2,%3}, [%4];"
                 : "=r"(r[0]), "=r"(r[1]), "=r"(r[2]), "=r"(r[3]) : "r"(addr));
}

__device__ __forceinline__ void mma16816(float* c, const uint32_t* a, const uint32_t* b) {
    asm volatile(
        "mma.sync.aligned.m16n8k16.row.col.f32.bf16.bf16.f32 "
        "{%0,%1,%2,%3}, {%4,%5,%6,%7}, {%8,%9}, {%0,%1,%2,%3};"
        : "+f"(c[0]), "+f"(c[1]), "+f"(c[2]), "+f"(c[3])
        : "r"(a[0]), "r"(a[1]), "r"(a[2]), "r"(a[3]), "r"(b[0]), "r"(b[1]));
}

__device__ __forceinline__ void cpasync16(uint32_t s, const void* g) {
    asm volatile("cp.async.cg.shared.global [%0], [%1], 16;" :: "r"(s), "l"(g));
}
__device__ __forceinline__ void cpasync_wait() {
    asm volatile("cp.async.commit_group;");
    asm volatile("cp.async.wait_group 0;" ::: "memory");
}

__device__ __forceinline__ void split8(const float* v, uint4& h4, uint4& l4) {
    uint16_t* hp = (uint16_t*)&h4;
    uint16_t* lp = (uint16_t*)&l4;
#pragma unroll
    for (int i = 0; i < 8; i++) {
        __nv_bfloat16 hb = __float2bfloat16(v[i]);
        float r = v[i] - __bfloat162float(hb);
        __nv_bfloat16 lb = __float2bfloat16(r);
        hp[i] = *(uint16_t*)&hb;
        lp[i] = *(uint16_t*)&lb;
    }
}

// 16B-chunk XOR swizzle within 128B groups: conflict-free ldmatrix + STS.
__device__ __forceinline__ uint32_t swz(int row, int g, int ROWB) {
    int c = (g & ~7) | ((g ^ row) & 7);
    return (uint32_t)(row * ROWB + c * 16);
}

// ---------------------------------------------------------------------------
// Weight prep: build fused [W|rW]^T hi/lo planes.
// ---------------------------------------------------------------------------
struct Prep8 {
    const float* W[8];
    int K[8], N[8], off[8];
};

__global__ void prep_kernel(Prep8 p) {
    for (int m = 0; m < 8; m++) {
        const int K = p.K[m], N = p.N[m], tot = K * N, off = p.off[m];
        const float* W = p.W[m];
        for (int idx = blockIdx.x * blockDim.x + threadIdx.x; idx < tot;
             idx += gridDim.x * blockDim.x) {
            int n = idx / K, k = idx - n * K;
            float w = W[(size_t)k * N + n];
            __nv_bfloat16 h = __float2bfloat16(w);
            float r = w - __bfloat162float(h);
            __nv_bfloat16 l = __float2bfloat16(r);
            g_wthi[off + idx] = *(uint16_t*)&h;
            g_wtlo[off + idx] = *(uint16_t*)&l;
        }
    }
}

// ---------------------------------------------------------------------------
// Fused bf16x3 GEMM:  [C1 | C2][M,128+128] = [A1|A2][M,192] @ [W|rW]^T
// Also computes el/er from the C1 register fragments (eler fusion).
// D = Ah*Bh + Al*Bh + Ah*Bl.
// 8 warps: 4(M) x 2(N); warp tile 32 x 128. wn=0 -> C1(h), wn=1 -> C2(rh).
// ---------------------------------------------------------------------------
template <int K>
__global__ __launch_bounds__(256, 1) void tc_gemm_fused(
    const float* __restrict__ A1, int K1,
    const float* __restrict__ A2,
    const uint16_t* __restrict__ Bh, const uint16_t* __restrict__ Bl,
    const float* __restrict__ al, const float* __restrict__ ar,
    float* __restrict__ C1, float* __restrict__ C2, int M)
{
    constexpr int BN   = 256;
    constexpr int ROWB = K * 2;
    constexpr int NG   = K / 8;
    constexpr int WN   = 128;
    constexpr int NT   = WN / 8;          // 16
    constexpr int KS   = K / 16;          // 12
    constexpr int AOFF  = 0;
    constexpr int ALOFF = 128 * ROWB;
    constexpr int BOFF  = 2 * 128 * ROWB;

    extern __shared__ char smem[];
    const uint32_t sb  = smem_u32(smem);
    const uint32_t sAH = sb + AOFF;
    const uint32_t sAL = sb + ALOFF;
    const uint32_t sB  = sb + BOFF;

    const int t    = threadIdx.x;
    const int wid  = t >> 5;
    const int lane = t & 31;
    const int bm   = blockIdx.x * 128;

    // ---- stage 1 B load (cp.async, overlapped with A load/split) ----
    for (int idx = t; idx < BN * NG; idx += 256) {
        int rn = idx / NG, g = idx - rn * NG;
        cpasync16(sB + swz(rn, g, ROWB), Bh + (size_t)rn * K + g * 8);
    }

    // ---- load + split A (implicit concat A1|A2) ----
    for (int idx = t; idx < 128 * NG; idx += 256) {
        int row = idx / NG, g = idx - row * NG, k0 = g * 8;
        int grow = bm + row;
        float v[8] = {0, 0, 0, 0, 0, 0, 0, 0};
        if (grow < M) {
            const float* p = (k0 < K1) ? (A1 + (size_t)grow * K1 + k0)
                                       : (A2 + (size_t)grow * (K - K1) + (k0 - K1));
            *(float4*)&v[0] = ((const float4*)p)[0];
            *(float4*)&v[4] = ((const float4*)p)[1];
        }
        uint4 h4, l4;
        split8(v, h4, l4);
        uint32_t o = swz(row, g, ROWB);
        *(uint4*)(smem + AOFF + o)  = h4;
        *(uint4*)(smem + ALOFF + o) = l4;
    }
    cpasync_wait();
    __syncthreads();

    const int wm   = wid & 3;
    const int wn   = wid >> 2;
    const int lr   = lane & 7;
    const int sel  = lane >> 3;
    const int selb1 = sel & 1;
    const int selb2 = sel >> 1;
    const int rowA_base = wm * 32 + lr + selb1 * 8;
    const int rowB_base = wn * WN + lr + selb2 * 8;

    float acc[2][NT][4];
#pragma unroll
    for (int mt = 0; mt < 2; mt++)
#pragma unroll
        for (int nt = 0; nt < NT; nt++)
#pragma unroll
            for (int q = 0; q < 4; q++) acc[mt][nt][q] = 0.f;

    // ---- stage 1: Ah*Bh + Al*Bh ----
#pragma unroll
    for (int ks = 0; ks < KS; ks++) {
        uint32_t bfr[NT][2];
#pragma unroll
        for (int nt2 = 0; nt2 < NT / 2; nt2++) {
            uint32_t r[4];
            ldsm_x4(r, sB + swz(rowB_base + nt2 * 16, ks * 2 + selb1, ROWB));
            bfr[2 * nt2][0]     = r[0];
            bfr[2 * nt2][1]     = r[1];
            bfr[2 * nt2 + 1][0] = r[2];
            bfr[2 * nt2 + 1][1] = r[3];
        }
        uint32_t afr[2][4];
#pragma unroll
        for (int mt = 0; mt < 2; mt++)
            ldsm_x4(afr[mt], sAH + swz(rowA_base + mt * 16, ks * 2 + selb2, ROWB));
#pragma unroll
        for (int mt = 0; mt < 2; mt++)
#pragma unroll
            for (int nt = 0; nt < NT; nt++)
                mma16816(acc[mt][nt], afr[mt], bfr[nt]);
#pragma unroll
        for (int mt = 0; mt < 2; mt++)
            ldsm_x4(afr[mt], sAL + swz(rowA_base + mt * 16, ks * 2 + selb2, ROWB));
#pragma unroll
        for (int mt = 0; mt < 2; mt++)
#pragma unroll
            for (int nt = 0; nt < NT; nt++)
                mma16816(acc[mt][nt], afr[mt], bfr[nt]);
    }

    // ---- swap B buffer to Bl ----
    __syncthreads();
    for (int idx = t; idx < BN * NG; idx += 256) {
        int rn = idx / NG, g = idx - rn * NG;
        cpasync16(sB + swz(rn, g, ROWB), Bl + (size_t)rn * K + g * 8);
    }
    cpasync_wait();
    __syncthreads();

    // ---- stage 2: Ah*Bl ----
#pragma unroll
    for (int ks = 0; ks < KS; ks++) {
        uint32_t bfr[NT][2];
#pragma unroll
        for (int nt2 = 0; nt2 < NT / 2; nt2++) {
            uint32_t r[4];
            ldsm_x4(r, sB + swz(rowB_base + nt2 * 16, ks * 2 + selb1, ROWB));
            bfr[2 * nt2][0]     = r[0];
            bfr[2 * nt2][1]     = r[1];
            bfr[2 * nt2 + 1][0] = r[2];
            bfr[2 * nt2 + 1][1] = r[3];
        }
        uint32_t afr[2][4];
#pragma unroll
        for (int mt = 0; mt < 2; mt++)
            ldsm_x4(afr[mt], sAH + swz(rowA_base + mt * 16, ks * 2 + selb2, ROWB));
#pragma unroll
        for (int mt = 0; mt < 2; mt++)
#pragma unroll
            for (int nt = 0; nt < NT; nt++)
                mma16816(acc[mt][nt], afr[mt], bfr[nt]);
    }

    // ---- epilogue: store C (wn=0 -> C1=h, wn=1 -> C2=rh) ----
    float* __restrict__ C = (wn == 0) ? C1 : C2;
    const int colb = (lane & 3) * 2;
#pragma unroll
    for (int mt = 0; mt < 2; mt++) {
        int r0 = bm + wm * 32 + mt * 16 + (lane >> 2);
        int r1 = r0 + 8;
#pragma unroll
        for (int nt = 0; nt < NT; nt++) {
            int col = colb + nt * 8;
            if (r0 < M) *(float2*)&C[(size_t)r0 * 128 + col] =
                make_float2(acc[mt][nt][0], acc[mt][nt][1]);
            if (r1 < M) *(float2*)&C[(size_t)r1 * 128 + col] =
                make_float2(acc[mt][nt][2], acc[mt][nt][3]);
        }
    }

    // ---- fused el/er from C1 fragments (wn == 0 warps only) ----
    if (wn == 0) {
#pragma unroll
        for (int mt = 0; mt < 2; mt++) {
            float e[8];  // {el0_h0, el0_h1, er0_h0, er0_h1, el1_h0, el1_h1, er1_h0, er1_h1}
#pragma unroll
            for (int q = 0; q < 8; q++) e[q] = 0.f;
#pragma unroll
            for (int nt = 0; nt < NT; nt++) {
                int c = colb + nt * 8;
                float a0 = al[c], a1 = al[c + 1];
                float b0 = ar[c], b1 = ar[c + 1];
                float sl0 = acc[mt][nt][0] * a0 + acc[mt][nt][1] * a1;
                float sl1 = acc[mt][nt][2] * a0 + acc[mt][nt][3] * a1;
                float sr0 = acc[mt][nt][0] * b0 + acc[mt][nt][1] * b1;
                float sr1 = acc[mt][nt][2] * b0 + acc[mt][nt][3] * b1;
                int hsel = (nt < 8) ? 0 : 1;
                e[hsel]     += sl0;
                e[2 + hsel] += sr0;
                e[4 + hsel] += sl1;
                e[6 + hsel] += sr1;
            }
#pragma unroll
            for (int o = 1; o <= 2; o <<= 1)
#pragma unroll
                for (int q = 0; q < 8; q++)
                    e[q] += __shfl_xor_sync(0xffffffffu, e[q], o);
            if ((lane & 3) == 0) {
                int r0 = bm + wm * 32 + mt * 16 + (lane >> 2);
                int r1 = r0 + 8;
                if (r0 < M) {
                    g_el[2 * r0] = e[0]; g_el[2 * r0 + 1] = e[1];
                    g_er[2 * r0] = e[2]; g_er[2 * r0 + 1] = e[3];
                }
                if (r1 < M) {
                    g_el[2 * r1] = e[4]; g_el[2 * r1 + 1] = e[5];
                    g_er[2 * r1] = e[6]; g_er[2 * r1 + 1] = e[7];
                }
            }
        }
    }
}

// ---------------------------------------------------------------------------
// Small bf16x3 GEMM (pg layers): C[M,64] = A[M,64] @ Wt^T, full K resident.
// ---------------------------------------------------------------------------
template <int BN, int K>
__global__ __launch_bounds__(256, 1) void tc_gemm(
    const float* __restrict__ A1,
    const uint16_t* __restrict__ Bh, const uint16_t* __restrict__ Bl,
    float* __restrict__ C, int M)
{
    constexpr int ROWB = K * 2;
    constexpr int NG   = K / 8;
    constexpr int WN   = BN / 2;
    constexpr int NT   = WN / 8;
    constexpr int KS   = K / 16;

    extern __shared__ char smem[];
    const uint32_t sAH = smem_u32(smem);
    const uint32_t sAL = sAH + 128 * ROWB;
    const uint32_t sBH = sAL + 128 * ROWB;
    const uint32_t sBL = sBH + BN * ROWB;

    const int t    = threadIdx.x;
    const int wid  = t >> 5;
    const int lane = t & 31;
    const int bm   = blockIdx.x * 128;

    for (int idx = t; idx < BN * NG; idx += 256) {
        int rn = idx / NG, g = idx - rn * NG, k0 = g * 8;
        cpasync16(sBH + swz(rn, g, ROWB), Bh + (size_t)rn * K + k0);
        cpasync16(sBL + swz(rn, g, ROWB), Bl + (size_t)rn * K + k0);
    }
    for (int idx = t; idx < 128 * NG; idx += 256) {
        int row = idx / NG, g = idx - row * NG, k0 = g * 8;
        int grow = bm + row;
        float v[8] = {0, 0, 0, 0, 0, 0, 0, 0};
        if (grow < M) {
            const float* p = A1 + (size_t)grow * K + k0;
            *(float4*)&v[0] = ((const float4*)p)[0];
            *(float4*)&v[4] = ((const float4*)p)[1];
        }
        uint4 h4, l4;
        split8(v, h4, l4);
        uint32_t o = swz(row, g, ROWB);
        *(uint4*)(smem + o) = h4;
        *(uint4*)(smem + 128 * ROWB + o) = l4;
    }
    cpasync_wait();
    __syncthreads();

    const int wm = wid & 3;
    const int wn = wid >> 2;
    const int lr   = lane & 7;
    const int sel  = lane >> 3;
    const int selb1 = sel & 1;
    const int selb2 = sel >> 1;
    const int rowA_base = wm * 32 + lr + selb1 * 8;
    const int rowB_base = wn * WN + lr + selb2 * 8;

    float acc[2][NT][4];
#pragma unroll
    for (int mt = 0; mt < 2; mt++)
#pragma unroll
        for (int nt = 0; nt < NT; nt++)
#pragma unroll
            for (int q = 0; q < 4; q++) acc[mt][nt][q] = 0.f;

#pragma unroll
    for (int pr = 0; pr < 3; pr++) {
        const uint32_t baseA = (pr == 2) ? sAL : sAH;
        const uint32_t baseB = (pr == 1) ? sBL : sBH;
#pragma unroll
        for (int ks = 0; ks < KS; ks++) {
            uint32_t afr[2][4];
#pragma unroll
            for (int mt = 0; mt < 2; mt++)
                ldsm_x4(afr[mt], baseA + swz(rowA_base + mt * 16, ks * 2 + selb2, ROWB));
            uint32_t bfr[NT][2];
#pragma unroll
            for (int nt2 = 0; nt2 < NT / 2; nt2++) {
                uint32_t r[4];
                ldsm_x4(r, baseB + swz(rowB_base + nt2 * 16, ks * 2 + selb1, ROWB));
                bfr[2 * nt2][0]     = r[0];
                bfr[2 * nt2][1]     = r[1];
                bfr[2 * nt2 + 1][0] = r[2];
                bfr[2 * nt2 + 1][1] = r[3];
            }
#pragma unroll
            for (int mt = 0; mt < 2; mt++)
#pragma unroll
                for (int nt = 0; nt < NT; nt++)
                    mma16816(acc[mt][nt], afr[mt], bfr[nt]);
        }
    }

    const int colb = wn * WN + (lane & 3) * 2;
#pragma unroll
    for (int mt = 0; mt < 2; mt++) {
        int r0 = bm + wm * 32 + mt * 16 + (lane >> 2);
        int r1 = r0 + 8;
#pragma unroll
        for (int nt = 0; nt < NT; nt++) {
            int col = colb + nt * 8;
            if (r0 < M) *(float2*)&C[(size_t)r0 * BN + col] =
                make_float2(acc[mt][nt][0], acc[mt][nt][1]);
            if (r1 < M) *(float2*)&C[(size_t)r1 * BN + col] =
                make_float2(acc[mt][nt][2], acc[mt][nt][3]);
        }
    }
}

// ---------------------------------------------------------------------------
// CSR build
// ---------------------------------------------------------------------------
__global__ void count_kernel(const int* __restrict__ dst, int e) {
    int i = blockIdx.x * blockDim.x + threadIdx.x;
    if (i < e) atomicAdd(&g_cnt[dst[i]], 1);
}

__global__ void scan_kernel(int n) {
    __shared__ int partial[1024];
    const int t = threadIdx.x;
    const int C = (n + 1023) / 1024;
    int s = 0;
    for (int j = 0; j < C; j++) {
        int idx = t * C + j;
        if (idx < n) s += g_cnt[idx];
    }
    partial[t] = s;
    __syncthreads();
    for (int ofs = 1; ofs < 1024; ofs <<= 1) {
        int v = (t >= ofs) ? partial[t - ofs] : 0;
        __syncthreads();
        partial[t] += v;
        __syncthreads();
    }
    int run = (t == 0) ? 0 : partial[t - 1];
    for (int j = 0; j < C; j++) {
        int idx = t * C + j;
        if (idx < n) {
            g_off[idx] = run;
            run += g_cnt[idx];
            g_cnt[idx] = 0;
        }
    }
    if (t == 1023) g_off[n] = run;
}

__global__ void fill_kernel(const int* __restrict__ src, const int* __restrict__ dst, int e) {
    int i = blockIdx.x * blockDim.x + threadIdx.x;
    if (i < e) {
        int d = dst[i];
        int p = atomicAdd(&g_cnt[d], 1);
        g_esrc[g_off[d] + p] = src[i];
    }
}

// ---------------------------------------------------------------------------
// el / er  (warp per node) — used for pg layers only
// ---------------------------------------------------------------------------
template <int HD>
__global__ void eler_kernel(const float* __restrict__ h,
                            const float* __restrict__ al,
                            const float* __restrict__ ar, int n)
{
    int warp = (blockIdx.x * blockDim.x + threadIdx.x) >> 5;
    int lane = threadIdx.x & 31;
    if (warp >= n) return;
    const float* row = h + (size_t)warp * HD;
    constexpr int KN = HD / 32;
    float pl0 = 0.f, pl1 = 0.f, pr0 = 0.f, pr1 = 0.f;
#pragma unroll
    for (int k = 0; k < KN; k++) {
        int idx = lane + 32 * k;
        float v = row[idx];
        if (32 * k < HD / 2) { pl0 += v * al[idx]; pr0 += v * ar[idx]; }
        else                 { pl1 += v * al[idx]; pr1 += v * ar[idx]; }
    }
#pragma unroll
    for (int o = 16; o; o >>= 1) {
        pl0 += __shfl_xor_sync(0xffffffffu, pl0, o);
        pl1 += __shfl_xor_sync(0xffffffffu, pl1, o);
        pr0 += __shfl_xor_sync(0xffffffffu, pr0, o);
        pr1 += __shfl_xor_sync(0xffffffffu, pr1, o);
    }
    if (lane == 0) {
        g_el[2 * warp]     = pl0;
        g_el[2 * warp + 1] = pl1;
        g_er[2 * warp]     = pr0;
        g_er[2 * warp + 1] = pr1;
    }
}

// ---------------------------------------------------------------------------
// Aggregation: warp per dst node; lane owns V=HD/32 contiguous cols (float4/2
// gathers); pass-2 unrolled 2 edges for MLP. ACT: 0 = elu, 1 = tanh.
// ---------------------------------------------------------------------------
__device__ __forceinline__ float leaky02(float x) { return x > 0.f ? x : 0.2f * x; }

template <int HD, int ACT, bool HEADMEAN>
__global__ void agg_kernel(const float* __restrict__ h,
                           const float* __restrict__ res,
                           float* __restrict__ out, int n)
{
    constexpr int V = HD / 32;           // 4 or 2
    int node = (blockIdx.x * blockDim.x + threadIdx.x) >> 5;
    int lane = threadIdx.x & 31;
    if (node >= n) return;

    const int beg = g_off[node];
    const int end = g_off[node + 1];
    const float2 erv = ((const float2*)g_er)[node];
    const float2* __restrict__ el2 = (const float2*)g_el;

    float m0 = -1e30f, m1 = -1e30f;
    for (int i = beg; i < end; i++) {
        int s = g_esrc[i];
        float2 elv = el2[s];
        m0 = fmaxf(m0, leaky02(elv.x + erv.x));
        m1 = fmaxf(m1, leaky02(elv.y + erv.y));
    }

    const bool head0 = (lane * V) < (HD / 2);
    float acc[V];
#pragma unroll
    for (int q = 0; q < V; q++) acc[q] = 0.f;
    float d0 = 0.f, d1 = 0.f;

    int i = beg;
    if ((end - beg) & 1) {
        int s = g_esrc[i];
        float2 elv = el2[s];
        float hv[V];
        if (V == 4) *(float4*)hv = *(const float4*)(h + (size_t)s * HD + lane * V);
        else        *(float2*)hv = *(const float2*)(h + (size_t)s * HD + lane * V);
        float w0 = __expf(leaky02(elv.x + erv.x) - m0);
        float w1 = __expf(leaky02(elv.y + erv.y) - m1);
        d0 += w0; d1 += w1;
        float wv = head0 ? w0 : w1;
#pragma unroll
        for (int q = 0; q < V; q++) acc[q] = fmaf(wv, hv[q], acc[q]);
        i++;
    }
    for (; i < end; i += 2) {
        int s0 = g_esrc[i];
        int s1 = g_esrc[i + 1];
        float2 ev0 = el2[s0];
        float2 ev1 = el2[s1];
        float hv0[V], hv1[V];
        if (V == 4) {
            *(float4*)hv0 = *(const float4*)(h + (size_t)s0 * HD + lane * V);
            *(float4*)hv1 = *(const float4*)(h + (size_t)s1 * HD + lane * V);
        } else {
            *(float2*)hv0 = *(const float2*)(h + (size_t)s0 * HD + lane * V);
            *(float2*)hv1 = *(const float2*)(h + (size_t)s1 * HD + lane * V);
        }
        float w00 = __expf(leaky02(ev0.x + erv.x) - m0);
        float w01 = __expf(leaky02(ev0.y + erv.y) - m1);
        float w10 = __expf(leaky02(ev1.x + erv.x) - m0);
        float w11 = __expf(leaky02(ev1.y + erv.y) - m1);
        d0 += w00 + w10;
        d1 += w01 + w11;
        float wv0 = head0 ? w00 : w01;
        float wv1 = head0 ? w10 : w11;
#pragma unroll
        for (int q = 0; q < V; q++) {
            acc[q] = fmaf(wv0, hv0[q], acc[q]);
            acc[q] = fmaf(wv1, hv1[q], acc[q]);
        }
    }

    const bool has = (end > beg);
    const float inv0 = has ? 1.f / d0 : 0.f;
    const float inv1 = has ? 1.f / d1 : 0.f;
    const float invv = head0 ? inv0 : inv1;

    float rr[V];
    if (V == 4) *(float4*)rr = *(const float4*)(res + (size_t)node * HD + lane * V);
    else        *(float2*)rr = *(const float2*)(res + (size_t)node * HD + lane * V);

    float v[V];
#pragma unroll
    for (int q = 0; q < V; q++) {
        v[q] = acc[q] * invv + rr[q];
        if (ACT == 0) v[q] = v[q] > 0.f ? v[q] : expm1f(v[q]);
        else          v[q] = tanhf(v[q]);
    }

    if (HEADMEAN) {
        // combine col c (lanes 0-15) with col c+64 (lanes 16-31), write 64 cols
        float p[V];
#pragma unroll
        for (int q = 0; q < V; q++) p[q] = __shfl_xor_sync(0xffffffffu, v[q], 16);
        if (lane < 16) {
            float o[V];
#pragma unroll
            for (int q = 0; q < V; q++) o[q] = 0.5f * (v[q] + p[q]);
            if (V == 4) *(float4*)(out + (size_t)node * 64 + lane * V) = *(float4*)o;
            else        *(float2*)(out + (size_t)node * 64 + lane * V) = *(float2*)o;
        }
    } else {
        if (V == 4) *(float4*)(out + (size_t)node * HD + lane * V) = *(float4*)v;
        else        *(float2*)(out + (size_t)node * HD + lane * V) = *(float2*)v;
    }
}

// ---------------------------------------------------------------------------
// Launch
// ---------------------------------------------------------------------------
extern "C" void kernel_launch(void* const* d_in, const int* in_sizes, int n_in,
                              void* d_out, int out_size)
{
    const float* fvs = (const float*)d_in[0];
    const float* pos = (const float*)d_in[1];
    const int*   src = (const int*)d_in[2];
    const int*   dst = (const int*)d_in[3];
    const float* g0W  = (const float*)d_in[4];
    const float* g0al = (const float*)d_in[5];
    const float* g0ar = (const float*)d_in[6];
    const float* g0rW = (const float*)d_in[7];
    const float* g1W  = (const float*)d_in[8];
    const float* g1al = (const float*)d_in[9];
    const float* g1ar = (const float*)d_in[10];
    const float* g1rW = (const float*)d_in[11];
    const float* g2W  = (const float*)d_in[12];
    const float* g2al = (const float*)d_in[13];
    const float* g2ar = (const float*)d_in[14];
    const float* g2rW = (const float*)d_in[15];
    const float* p0W  = (const float*)d_in[16];
    const float* p0al = (const float*)d_in[17];
    const float* p0ar = (const float*)d_in[18];
    const float* p1W  = (const float*)d_in[19];
    const float* p1al = (const float*)d_in[20];
    const float* p1ar = (const float*)d_in[21];

    const int n = in_sizes[0] / 128;
    const int e = in_sizes[2];

    float *h, *rh, *hs, *hs2, *hp;
    int* cnt;
    uint16_t *wthi, *wtlo;
    cudaGetSymbolAddress((void**)&h,    g_h);
    cudaGetSymbolAddress((void**)&rh,   g_rh);
    cudaGetSymbolAddress((void**)&hs,   g_hs);
    cudaGetSymbolAddress((void**)&hs2,  g_hs2);
    cudaGetSymbolAddress((void**)&hp,   g_hp);
    cudaGetSymbolAddress((void**)&cnt,  g_cnt);
    cudaGetSymbolAddress((void**)&wthi, g_wthi);
    cudaGetSymbolAddress((void**)&wtlo, g_wtlo);

    float* out_hs = (float*)d_out;
    float* out_hp = (float*)d_out + (size_t)n * 64;

    const int EB = (e + 255) / 256;
    const int GB = (n + 127) / 128;
    const int WB = (n + 7) / 8;

    constexpr int SMEM_F     = 2 * 128 * 384 + 256 * 384;          // 196608
    constexpr int SMEM_SMALL = (128 + 128 + 64 + 64) * 64 * 2;     // 49152
    cudaFuncSetAttribute(tc_gemm_fused<192>, cudaFuncAttributeMaxDynamicSharedMemorySize, SMEM_F);
    cudaFuncSetAttribute(tc_gemm<64, 64>,    cudaFuncAttributeMaxDynamicSharedMemorySize, SMEM_SMALL);

    // ---- weight prep: fused [W|rW]^T layout ----
    Prep8 pa;
    const float* Ws[8] = {g0W, g0rW, g1W, g1rW, g2W, g2rW, p0W, p1W};
    for (int m = 0; m < 8; m++) {
        pa.W[m] = Ws[m];
        pa.K[m] = (m < 6) ? 192 : 64;
        pa.N[m] = (m < 6) ? 128 : 64;
        pa.off[m] = (m < 6) ? (m >> 1) * WT_FUSED + (m & 1) * (128 * 192)
                            : 3 * WT_FUSED + (m - 6) * WT_SMALL;
    }
    prep_kernel<<<64, 256>>>(pa);

    // ---- CSR build ----
    cudaMemsetAsync(cnt, 0, (size_t)n * sizeof(int));
    count_kernel<<<EB, 256>>>(dst, e);
    scan_kernel<<<1, 1024>>>(n);
    fill_kernel<<<EB, 256>>>(src, dst, e);

    const int F0 = 0 * WT_FUSED, F1 = 1 * WT_FUSED, F2 = 2 * WT_FUSED;
    const int P0 = 3 * WT_FUSED, P1 = 3 * WT_FUSED + WT_SMALL;

    // ---- layer 0 ----
    tc_gemm_fused<192><<<GB, 256, SMEM_F>>>(fvs, 128, pos, wthi + F0, wtlo + F0,
                                            g0al, g0ar, h, rh, n);
    agg_kernel<128, 0, false><<<WB, 256>>>(h, rh, hs, n);
    tc_gemm<64, 64><<<GB, 256, SMEM_SMALL>>>(pos, wthi + P0, wtlo + P0, h, n);
    eler_kernel<64><<<WB, 256>>>(h, p0al, p0ar, n);
    agg_kernel<64, 1, false><<<WB, 256>>>(h, pos, hp, n);

    // ---- layer 1 ----
    tc_gemm_fused<192><<<GB, 256, SMEM_F>>>(hs, 128, hp, wthi + F1, wtlo + F1,
                                            g1al, g1ar, h, rh, n);
    agg_kernel<128, 0, false><<<WB, 256>>>(h, rh, hs2, n);
    tc_gemm<64, 64><<<GB, 256, SMEM_SMALL>>>(hp, wthi + P1, wtlo + P1, h, n);
    eler_kernel<64><<<WB, 256>>>(h, p1al, p1ar, n);
    agg_kernel<64, 1, false><<<WB, 256>>>(h, hp, out_hp, n);

    // ---- layer 2 (output, head-mean) ----
    tc_gemm_fused<192><<<GB, 256, SMEM_F>>>(hs2, 128, out_hp, wthi + F2, wtlo + F2,
                                            g2al, g2ar, h, rh, n);
    agg_kernel<128, 0, true><<<WB, 256>>>(h, rh, out_hs, n);
}

// round 7
// speedup vs baseline: 1.8021x; 1.0199x over previous
#include <cuda_runtime.h>
#include <cuda_bf16.h>
#include <math.h>
#include <stdint.h>

// ---------------------------------------------------------------------------
// Problem constants
// ---------------------------------------------------------------------------
#define NMAX 50000
#define EMAX 800000

// ---------------------------------------------------------------------------
// Scratch (device globals)
// ---------------------------------------------------------------------------
__device__ float g_h  [(size_t)NMAX * 128];
__device__ float g_rh [(size_t)NMAX * 128];
__device__ float g_hs [(size_t)NMAX * 128];
__device__ float g_hs2[(size_t)NMAX * 128];
__device__ float g_hp [(size_t)NMAX * 64];
__device__ float g_el [(size_t)NMAX * 2];
__device__ float g_er [(size_t)NMAX * 2];
__device__ int   g_off[NMAX + 1];
__device__ int   g_cnt[NMAX];
__device__ int   g_esrc[EMAX];

// Fused transposed hi/lo bf16 weights:
// 3 fused big mats [256 x 192]  (rows 0-127 = W^T, rows 128-255 = rW^T)
// 2 small mats [64 x 64]
#define WT_FUSED (256 * 192)
#define WT_SMALL (64 * 64)
__device__ uint16_t g_wthi[3 * WT_FUSED + 2 * WT_SMALL];
__device__ uint16_t g_wtlo[3 * WT_FUSED + 2 * WT_SMALL];

// ---------------------------------------------------------------------------
// Helpers
// ---------------------------------------------------------------------------
__device__ __forceinline__ uint32_t smem_u32(const void* p) {
    uint32_t a;
    asm("{ .reg .u64 t; cvta.to.shared.u64 t, %1; cvt.u32.u64 %0, t; }"
        : "=r"(a) : "l"(p));
    return a;
}

__device__ __forceinline__ void ldsm_x4(uint32_t* r, uint32_t addr) {
    asm volatile("ldmatrix.sync.aligned.m8n8.x4.shared.b16 {%0,%1,%2,%3}, [%4];"
                 : "=r"(r[0]), "=r"(r[1]), "=r"(r[2]), "=r"(r[3]) : "r"(addr));
}

__device__ __forceinline__ void mma16816(float* c, const uint32_t* a, const uint32_t* b) {
    asm volatile(
        "mma.sync.aligned.m16n8k16.row.col.f32.bf16.bf16.f32 "
        "{%0,%1,%2,%3}, {%4,%5,%6,%7}, {%8,%9}, {%0,%1,%2,%3};"
        : "+f"(c[0]), "+f"(c[1]), "+f"(c[2]), "+f"(c[3])
        : "r"(a[0]), "r"(a[1]), "r"(a[2]), "r"(a[3]), "r"(b[0]), "r"(b[1]));
}

__device__ __forceinline__ void cpasync16(uint32_t s, const void* g) {
    asm volatile("cp.async.cg.shared.global [%0], [%1], 16;" :: "r"(s), "l"(g));
}
__device__ __forceinline__ void cpasync_wait() {
    asm volatile("cp.async.commit_group;");
    asm volatile("cp.async.wait_group 0;" ::: "memory");
}

__device__ __forceinline__ void split8(const float* v, uint4& h4, uint4& l4) {
    uint16_t* hp = (uint16_t*)&h4;
    uint16_t* lp = (uint16_t*)&l4;
#pragma unroll
    for (int i = 0; i < 8; i++) {
        __nv_bfloat16 hb = __float2bfloat16(v[i]);
        float r = v[i] - __bfloat162float(hb);
        __nv_bfloat16 lb = __float2bfloat16(r);
        hp[i] = *(uint16_t*)&hb;
        lp[i] = *(uint16_t*)&lb;
    }
}

// 16B-chunk XOR swizzle within 128B groups: conflict-free ldmatrix + STS.
__device__ __forceinline__ uint32_t swz(int row, int g, int ROWB) {
    int c = (g & ~7) | ((g ^ row) & 7);
    return (uint32_t)(row * ROWB + c * 16);
}

// ---------------------------------------------------------------------------
// Weight prep: build fused [W|rW]^T hi/lo planes.
// ---------------------------------------------------------------------------
struct Prep8 {
    const float* W[8];
    int K[8], N[8], off[8];
};

__global__ void prep_kernel(Prep8 p) {
    for (int m = 0; m < 8; m++) {
        const int K = p.K[m], N = p.N[m], tot = K * N, off = p.off[m];
        const float* W = p.W[m];
        for (int idx = blockIdx.x * blockDim.x + threadIdx.x; idx < tot;
             idx += gridDim.x * blockDim.x) {
            int n = idx / K, k = idx - n * K;
            float w = W[(size_t)k * N + n];
            __nv_bfloat16 h = __float2bfloat16(w);
            float r = w - __bfloat162float(h);
            __nv_bfloat16 l = __float2bfloat16(r);
            g_wthi[off + idx] = *(uint16_t*)&h;
            g_wtlo[off + idx] = *(uint16_t*)&l;
        }
    }
}

// ---------------------------------------------------------------------------
// Fused bf16x3 GEMM:  [C1 | C2][M,128+128] = [A1|A2][M,192] @ [W|rW]^T
// Also computes el/er from the C1 register fragments.
// ---------------------------------------------------------------------------
template <int K>
__global__ __launch_bounds__(256, 1) void tc_gemm_fused(
    const float* __restrict__ A1, int K1,
    const float* __restrict__ A2,
    const uint16_t* __restrict__ Bh, const uint16_t* __restrict__ Bl,
    const float* __restrict__ al, const float* __restrict__ ar,
    float* __restrict__ C1, float* __restrict__ C2, int M)
{
    constexpr int BN   = 256;
    constexpr int ROWB = K * 2;
    constexpr int NG   = K / 8;
    constexpr int WN   = 128;
    constexpr int NT   = WN / 8;          // 16
    constexpr int KS   = K / 16;          // 12
    constexpr int AOFF  = 0;
    constexpr int ALOFF = 128 * ROWB;
    constexpr int BOFF  = 2 * 128 * ROWB;

    extern __shared__ char smem[];
    const uint32_t sb  = smem_u32(smem);
    const uint32_t sAH = sb + AOFF;
    const uint32_t sAL = sb + ALOFF;
    const uint32_t sB  = sb + BOFF;

    const int t    = threadIdx.x;
    const int wid  = t >> 5;
    const int lane = t & 31;
    const int bm   = blockIdx.x * 128;

    for (int idx = t; idx < BN * NG; idx += 256) {
        int rn = idx / NG, g = idx - rn * NG;
        cpasync16(sB + swz(rn, g, ROWB), Bh + (size_t)rn * K + g * 8);
    }

    for (int idx = t; idx < 128 * NG; idx += 256) {
        int row = idx / NG, g = idx - row * NG, k0 = g * 8;
        int grow = bm + row;
        float v[8] = {0, 0, 0, 0, 0, 0, 0, 0};
        if (grow < M) {
            const float* p = (k0 < K1) ? (A1 + (size_t)grow * K1 + k0)
                                       : (A2 + (size_t)grow * (K - K1) + (k0 - K1));
            *(float4*)&v[0] = ((const float4*)p)[0];
            *(float4*)&v[4] = ((const float4*)p)[1];
        }
        uint4 h4, l4;
        split8(v, h4, l4);
        uint32_t o = swz(row, g, ROWB);
        *(uint4*)(smem + AOFF + o)  = h4;
        *(uint4*)(smem + ALOFF + o) = l4;
    }
    cpasync_wait();
    __syncthreads();

    const int wm   = wid & 3;
    const int wn   = wid >> 2;
    const int lr   = lane & 7;
    const int sel  = lane >> 3;
    const int selb1 = sel & 1;
    const int selb2 = sel >> 1;
    const int rowA_base = wm * 32 + lr + selb1 * 8;
    const int rowB_base = wn * WN + lr + selb2 * 8;

    float acc[2][NT][4];
#pragma unroll
    for (int mt = 0; mt < 2; mt++)
#pragma unroll
        for (int nt = 0; nt < NT; nt++)
#pragma unroll
            for (int q = 0; q < 4; q++) acc[mt][nt][q] = 0.f;

#pragma unroll
    for (int ks = 0; ks < KS; ks++) {
        uint32_t bfr[NT][2];
#pragma unroll
        for (int nt2 = 0; nt2 < NT / 2; nt2++) {
            uint32_t r[4];
            ldsm_x4(r, sB + swz(rowB_base + nt2 * 16, ks * 2 + selb1, ROWB));
            bfr[2 * nt2][0]     = r[0];
            bfr[2 * nt2][1]     = r[1];
            bfr[2 * nt2 + 1][0] = r[2];
            bfr[2 * nt2 + 1][1] = r[3];
        }
        uint32_t afr[2][4];
#pragma unroll
        for (int mt = 0; mt < 2; mt++)
            ldsm_x4(afr[mt], sAH + swz(rowA_base + mt * 16, ks * 2 + selb2, ROWB));
#pragma unroll
        for (int mt = 0; mt < 2; mt++)
#pragma unroll
            for (int nt = 0; nt < NT; nt++)
                mma16816(acc[mt][nt], afr[mt], bfr[nt]);
#pragma unroll
        for (int mt = 0; mt < 2; mt++)
            ldsm_x4(afr[mt], sAL + swz(rowA_base + mt * 16, ks * 2 + selb2, ROWB));
#pragma unroll
        for (int mt = 0; mt < 2; mt++)
#pragma unroll
            for (int nt = 0; nt < NT; nt++)
                mma16816(acc[mt][nt], afr[mt], bfr[nt]);
    }

    __syncthreads();
    for (int idx = t; idx < BN * NG; idx += 256) {
        int rn = idx / NG, g = idx - rn * NG;
        cpasync16(sB + swz(rn, g, ROWB), Bl + (size_t)rn * K + g * 8);
    }
    cpasync_wait();
    __syncthreads();

#pragma unroll
    for (int ks = 0; ks < KS; ks++) {
        uint32_t bfr[NT][2];
#pragma unroll
        for (int nt2 = 0; nt2 < NT / 2; nt2++) {
            uint32_t r[4];
            ldsm_x4(r, sB + swz(rowB_base + nt2 * 16, ks * 2 + selb1, ROWB));
            bfr[2 * nt2][0]     = r[0];
            bfr[2 * nt2][1]     = r[1];
            bfr[2 * nt2 + 1][0] = r[2];
            bfr[2 * nt2 + 1][1] = r[3];
        }
        uint32_t afr[2][4];
#pragma unroll
        for (int mt = 0; mt < 2; mt++)
            ldsm_x4(afr[mt], sAH + swz(rowA_base + mt * 16, ks * 2 + selb2, ROWB));
#pragma unroll
        for (int mt = 0; mt < 2; mt++)
#pragma unroll
            for (int nt = 0; nt < NT; nt++)
                mma16816(acc[mt][nt], afr[mt], bfr[nt]);
    }

    float* __restrict__ C = (wn == 0) ? C1 : C2;
    const int colb = (lane & 3) * 2;
#pragma unroll
    for (int mt = 0; mt < 2; mt++) {
        int r0 = bm + wm * 32 + mt * 16 + (lane >> 2);
        int r1 = r0 + 8;
#pragma unroll
        for (int nt = 0; nt < NT; nt++) {
            int col = colb + nt * 8;
            if (r0 < M) *(float2*)&C[(size_t)r0 * 128 + col] =
                make_float2(acc[mt][nt][0], acc[mt][nt][1]);
            if (r1 < M) *(float2*)&C[(size_t)r1 * 128 + col] =
                make_float2(acc[mt][nt][2], acc[mt][nt][3]);
        }
    }

    if (wn == 0) {
#pragma unroll
        for (int mt = 0; mt < 2; mt++) {
            float e[8];
#pragma unroll
            for (int q = 0; q < 8; q++) e[q] = 0.f;
#pragma unroll
            for (int nt = 0; nt < NT; nt++) {
                int c = colb + nt * 8;
                float a0 = al[c], a1 = al[c + 1];
                float b0 = ar[c], b1 = ar[c + 1];
                float sl0 = acc[mt][nt][0] * a0 + acc[mt][nt][1] * a1;
                float sl1 = acc[mt][nt][2] * a0 + acc[mt][nt][3] * a1;
                float sr0 = acc[mt][nt][0] * b0 + acc[mt][nt][1] * b1;
                float sr1 = acc[mt][nt][2] * b0 + acc[mt][nt][3] * b1;
                int hsel = (nt < 8) ? 0 : 1;
                e[hsel]     += sl0;
                e[2 + hsel] += sr0;
                e[4 + hsel] += sl1;
                e[6 + hsel] += sr1;
            }
#pragma unroll
            for (int o = 1; o <= 2; o <<= 1)
#pragma unroll
                for (int q = 0; q < 8; q++)
                    e[q] += __shfl_xor_sync(0xffffffffu, e[q], o);
            if ((lane & 3) == 0) {
                int r0 = bm + wm * 32 + mt * 16 + (lane >> 2);
                int r1 = r0 + 8;
                if (r0 < M) {
                    g_el[2 * r0] = e[0]; g_el[2 * r0 + 1] = e[1];
                    g_er[2 * r0] = e[2]; g_er[2 * r0 + 1] = e[3];
                }
                if (r1 < M) {
                    g_el[2 * r1] = e[4]; g_el[2 * r1 + 1] = e[5];
                    g_er[2 * r1] = e[6]; g_er[2 * r1 + 1] = e[7];
                }
            }
        }
    }
}

// ---------------------------------------------------------------------------
// Small bf16x3 GEMM (pg layers) with fused el/er epilogue.
// BN=64: warps 4(M) x 2(N); wn selects head (cols 0-31 = head0, 32-63 = head1).
// ---------------------------------------------------------------------------
template <int BN, int K>
__global__ __launch_bounds__(256, 1) void tc_gemm_small(
    const float* __restrict__ A1,
    const uint16_t* __restrict__ Bh, const uint16_t* __restrict__ Bl,
    const float* __restrict__ al, const float* __restrict__ ar,
    float* __restrict__ C, int M)
{
    constexpr int ROWB = K * 2;
    constexpr int NG   = K / 8;
    constexpr int WN   = BN / 2;          // 32
    constexpr int NT   = WN / 8;          // 4
    constexpr int KS   = K / 16;

    extern __shared__ char smem[];
    const uint32_t sAH = smem_u32(smem);
    const uint32_t sAL = sAH + 128 * ROWB;
    const uint32_t sBH = sAL + 128 * ROWB;
    const uint32_t sBL = sBH + BN * ROWB;

    const int t    = threadIdx.x;
    const int wid  = t >> 5;
    const int lane = t & 31;
    const int bm   = blockIdx.x * 128;

    for (int idx = t; idx < BN * NG; idx += 256) {
        int rn = idx / NG, g = idx - rn * NG, k0 = g * 8;
        cpasync16(sBH + swz(rn, g, ROWB), Bh + (size_t)rn * K + k0);
        cpasync16(sBL + swz(rn, g, ROWB), Bl + (size_t)rn * K + k0);
    }
    for (int idx = t; idx < 128 * NG; idx += 256) {
        int row = idx / NG, g = idx - row * NG, k0 = g * 8;
        int grow = bm + row;
        float v[8] = {0, 0, 0, 0, 0, 0, 0, 0};
        if (grow < M) {
            const float* p = A1 + (size_t)grow * K + k0;
            *(float4*)&v[0] = ((const float4*)p)[0];
            *(float4*)&v[4] = ((const float4*)p)[1];
        }
        uint4 h4, l4;
        split8(v, h4, l4);
        uint32_t o = swz(row, g, ROWB);
        *(uint4*)(smem + o) = h4;
        *(uint4*)(smem + 128 * ROWB + o) = l4;
    }
    cpasync_wait();
    __syncthreads();

    const int wm = wid & 3;
    const int wn = wid >> 2;
    const int lr   = lane & 7;
    const int sel  = lane >> 3;
    const int selb1 = sel & 1;
    const int selb2 = sel >> 1;
    const int rowA_base = wm * 32 + lr + selb1 * 8;
    const int rowB_base = wn * WN + lr + selb2 * 8;

    float acc[2][NT][4];
#pragma unroll
    for (int mt = 0; mt < 2; mt++)
#pragma unroll
        for (int nt = 0; nt < NT; nt++)
#pragma unroll
            for (int q = 0; q < 4; q++) acc[mt][nt][q] = 0.f;

#pragma unroll
    for (int pr = 0; pr < 3; pr++) {
        const uint32_t baseA = (pr == 2) ? sAL : sAH;
        const uint32_t baseB = (pr == 1) ? sBL : sBH;
#pragma unroll
        for (int ks = 0; ks < KS; ks++) {
            uint32_t afr[2][4];
#pragma unroll
            for (int mt = 0; mt < 2; mt++)
                ldsm_x4(afr[mt], baseA + swz(rowA_base + mt * 16, ks * 2 + selb2, ROWB));
            uint32_t bfr[NT][2];
#pragma unroll
            for (int nt2 = 0; nt2 < NT / 2; nt2++) {
                uint32_t r[4];
                ldsm_x4(r, baseB + swz(rowB_base + nt2 * 16, ks * 2 + selb1, ROWB));
                bfr[2 * nt2][0]     = r[0];
                bfr[2 * nt2][1]     = r[1];
                bfr[2 * nt2 + 1][0] = r[2];
                bfr[2 * nt2 + 1][1] = r[3];
            }
#pragma unroll
            for (int mt = 0; mt < 2; mt++)
#pragma unroll
                for (int nt = 0; nt < NT; nt++)
                    mma16816(acc[mt][nt], afr[mt], bfr[nt]);
        }
    }

    const int colb = wn * WN + (lane & 3) * 2;
#pragma unroll
    for (int mt = 0; mt < 2; mt++) {
        int r0 = bm + wm * 32 + mt * 16 + (lane >> 2);
        int r1 = r0 + 8;
#pragma unroll
        for (int nt = 0; nt < NT; nt++) {
            int col = colb + nt * 8;
            if (r0 < M) *(float2*)&C[(size_t)r0 * BN + col] =
                make_float2(acc[mt][nt][0], acc[mt][nt][1]);
            if (r1 < M) *(float2*)&C[(size_t)r1 * BN + col] =
                make_float2(acc[mt][nt][2], acc[mt][nt][3]);
        }
    }

    // ---- fused el/er: wn = head index ----
#pragma unroll
    for (int mt = 0; mt < 2; mt++) {
        float e[4];   // {el_r0, er_r0, el_r1, er_r1} for this head
#pragma unroll
        for (int q = 0; q < 4; q++) e[q] = 0.f;
#pragma unroll
        for (int nt = 0; nt < NT; nt++) {
            int c = colb + nt * 8;
            float a0 = al[c], a1 = al[c + 1];
            float b0 = ar[c], b1 = ar[c + 1];
            e[0] += acc[mt][nt][0] * a0 + acc[mt][nt][1] * a1;
            e[1] += acc[mt][nt][0] * b0 + acc[mt][nt][1] * b1;
            e[2] += acc[mt][nt][2] * a0 + acc[mt][nt][3] * a1;
            e[3] += acc[mt][nt][2] * b0 + acc[mt][nt][3] * b1;
        }
#pragma unroll
        for (int o = 1; o <= 2; o <<= 1)
#pragma unroll
            for (int q = 0; q < 4; q++)
                e[q] += __shfl_xor_sync(0xffffffffu, e[q], o);
        if ((lane & 3) == 0) {
            int r0 = bm + wm * 32 + mt * 16 + (lane >> 2);
            int r1 = r0 + 8;
            if (r0 < M) { g_el[2 * r0 + wn] = e[0]; g_er[2 * r0 + wn] = e[1]; }
            if (r1 < M) { g_el[2 * r1 + wn] = e[2]; g_er[2 * r1 + wn] = e[3]; }
        }
    }
}

// ---------------------------------------------------------------------------
// CSR build
// ---------------------------------------------------------------------------
__global__ void count_kernel(const int* __restrict__ dst, int e) {
    int i = blockIdx.x * blockDim.x + threadIdx.x;
    if (i < e) atomicAdd(&g_cnt[dst[i]], 1);
}

__global__ void scan_kernel(int n) {
    __shared__ int partial[1024];
    const int t = threadIdx.x;
    const int C = (n + 1023) / 1024;
    int s = 0;
    for (int j = 0; j < C; j++) {
        int idx = t * C + j;
        if (idx < n) s += g_cnt[idx];
    }
    partial[t] = s;
    __syncthreads();
    for (int ofs = 1; ofs < 1024; ofs <<= 1) {
        int v = (t >= ofs) ? partial[t - ofs] : 0;
        __syncthreads();
        partial[t] += v;
        __syncthreads();
    }
    int run = (t == 0) ? 0 : partial[t - 1];
    for (int j = 0; j < C; j++) {
        int idx = t * C + j;
        if (idx < n) {
            g_off[idx] = run;
            run += g_cnt[idx];
            g_cnt[idx] = 0;
        }
    }
    if (t == 1023) g_off[n] = run;
}

__global__ void fill_kernel(const int* __restrict__ src, const int* __restrict__ dst, int e) {
    int i = blockIdx.x * blockDim.x + threadIdx.x;
    if (i < e) {
        int d = dst[i];
        int p = atomicAdd(&g_cnt[d], 1);
        g_esrc[g_off[d] + p] = src[i];
    }
}

// ---------------------------------------------------------------------------
// Aggregation: warp per dst node; lane owns V contiguous cols; 4-edge unroll
// in both passes for MLP. ACT: 0 = elu, 1 = tanh.
// ---------------------------------------------------------------------------
__device__ __forceinline__ float leaky02(float x) { return x > 0.f ? x : 0.2f * x; }

template <int HD, int ACT, bool HEADMEAN>
__global__ void agg_kernel(const float* __restrict__ h,
                           const float* __restrict__ res,
                           float* __restrict__ out, int n)
{
    constexpr int V = HD / 32;           // 4 or 2
    int node = (blockIdx.x * blockDim.x + threadIdx.x) >> 5;
    int lane = threadIdx.x & 31;
    if (node >= n) return;

    const int beg = g_off[node];
    const int end = g_off[node + 1];
    const float2 erv = ((const float2*)g_er)[node];
    const float2* __restrict__ el2 = (const float2*)g_el;
    const int* __restrict__ esrc = g_esrc;

    // ---- pass 1: max (4-edge unroll) ----
    float m0 = -1e30f, m1 = -1e30f;
    int i = beg;
    for (; i + 4 <= end; i += 4) {
        int s[4];
#pragma unroll
        for (int j = 0; j < 4; j++) s[j] = esrc[i + j];
        float2 ev[4];
#pragma unroll
        for (int j = 0; j < 4; j++) ev[j] = el2[s[j]];
#pragma unroll
        for (int j = 0; j < 4; j++) {
            m0 = fmaxf(m0, leaky02(ev[j].x + erv.x));
            m1 = fmaxf(m1, leaky02(ev[j].y + erv.y));
        }
    }
    for (; i < end; i++) {
        float2 ev = el2[esrc[i]];
        m0 = fmaxf(m0, leaky02(ev.x + erv.x));
        m1 = fmaxf(m1, leaky02(ev.y + erv.y));
    }

    // ---- pass 2: weighted sum (4-edge unroll) ----
    const bool head0 = (lane * V) < (HD / 2);
    float acc[V];
#pragma unroll
    for (int q = 0; q < V; q++) acc[q] = 0.f;
    float d0 = 0.f, d1 = 0.f;

    i = beg;
    for (; i + 4 <= end; i += 4) {
        int s[4];
#pragma unroll
        for (int j = 0; j < 4; j++) s[j] = esrc[i + j];
        float2 ev[4];
#pragma unroll
        for (int j = 0; j < 4; j++) ev[j] = el2[s[j]];
        float hv[4][V];
#pragma unroll
        for (int j = 0; j < 4; j++) {
            if (V == 4) *(float4*)hv[j] = *(const float4*)(h + (size_t)s[j] * HD + lane * V);
            else        *(float2*)hv[j] = *(const float2*)(h + (size_t)s[j] * HD + lane * V);
        }
#pragma unroll
        for (int j = 0; j < 4; j++) {
            float w0 = __expf(leaky02(ev[j].x + erv.x) - m0);
            float w1 = __expf(leaky02(ev[j].y + erv.y) - m1);
            d0 += w0; d1 += w1;
            float wv = head0 ? w0 : w1;
#pragma unroll
            for (int q = 0; q < V; q++) acc[q] = fmaf(wv, hv[j][q], acc[q]);
        }
    }
    for (; i < end; i++) {
        int s = esrc[i];
        float2 ev = el2[s];
        float hv[V];
        if (V == 4) *(float4*)hv = *(const float4*)(h + (size_t)s * HD + lane * V);
        else        *(float2*)hv = *(const float2*)(h + (size_t)s * HD + lane * V);
        float w0 = __expf(leaky02(ev.x + erv.x) - m0);
        float w1 = __expf(leaky02(ev.y + erv.y) - m1);
        d0 += w0; d1 += w1;
        float wv = head0 ? w0 : w1;
#pragma unroll
        for (int q = 0; q < V; q++) acc[q] = fmaf(wv, hv[q], acc[q]);
    }

    const bool has = (end > beg);
    const float inv0 = has ? 1.f / d0 : 0.f;
    const float inv1 = has ? 1.f / d1 : 0.f;
    const float invv = head0 ? inv0 : inv1;

    float rr[V];
    if (V == 4) *(float4*)rr = *(const float4*)(res + (size_t)node * HD + lane * V);
    else        *(float2*)rr = *(const float2*)(res + (size_t)node * HD + lane * V);

    float v[V];
#pragma unroll
    for (int q = 0; q < V; q++) {
        v[q] = acc[q] * invv + rr[q];
        if (ACT == 0) v[q] = v[q] > 0.f ? v[q] : expm1f(v[q]);
        else          v[q] = tanhf(v[q]);
    }

    if (HEADMEAN) {
        float p[V];
#pragma unroll
        for (int q = 0; q < V; q++) p[q] = __shfl_xor_sync(0xffffffffu, v[q], 16);
        if (lane < 16) {
            float o[V];
#pragma unroll
            for (int q = 0; q < V; q++) o[q] = 0.5f * (v[q] + p[q]);
            if (V == 4) *(float4*)(out + (size_t)node * 64 + lane * V) = *(float4*)o;
            else        *(float2*)(out + (size_t)node * 64 + lane * V) = *(float2*)o;
        }
    } else {
        if (V == 4) *(float4*)(out + (size_t)node * HD + lane * V) = *(float4*)v;
        else        *(float2*)(out + (size_t)node * HD + lane * V) = *(float2*)v;
    }
}

// ---------------------------------------------------------------------------
// Launch
// ---------------------------------------------------------------------------
extern "C" void kernel_launch(void* const* d_in, const int* in_sizes, int n_in,
                              void* d_out, int out_size)
{
    const float* fvs = (const float*)d_in[0];
    const float* pos = (const float*)d_in[1];
    const int*   src = (const int*)d_in[2];
    const int*   dst = (const int*)d_in[3];
    const float* g0W  = (const float*)d_in[4];
    const float* g0al = (const float*)d_in[5];
    const float* g0ar = (const float*)d_in[6];
    const float* g0rW = (const float*)d_in[7];
    const float* g1W  = (const float*)d_in[8];
    const float* g1al = (const float*)d_in[9];
    const float* g1ar = (const float*)d_in[10];
    const float* g1rW = (const float*)d_in[11];
    const float* g2W  = (const float*)d_in[12];
    const float* g2al = (const float*)d_in[13];
    const float* g2ar = (const float*)d_in[14];
    const float* g2rW = (const float*)d_in[15];
    const float* p0W  = (const float*)d_in[16];
    const float* p0al = (const float*)d_in[17];
    const float* p0ar = (const float*)d_in[18];
    const float* p1W  = (const float*)d_in[19];
    const float* p1al = (const float*)d_in[20];
    const float* p1ar = (const float*)d_in[21];

    const int n = in_sizes[0] / 128;
    const int e = in_sizes[2];

    float *h, *rh, *hs, *hs2, *hp;
    int* cnt;
    uint16_t *wthi, *wtlo;
    cudaGetSymbolAddress((void**)&h,    g_h);
    cudaGetSymbolAddress((void**)&rh,   g_rh);
    cudaGetSymbolAddress((void**)&hs,   g_hs);
    cudaGetSymbolAddress((void**)&hs2,  g_hs2);
    cudaGetSymbolAddress((void**)&hp,   g_hp);
    cudaGetSymbolAddress((void**)&cnt,  g_cnt);
    cudaGetSymbolAddress((void**)&wthi, g_wthi);
    cudaGetSymbolAddress((void**)&wtlo, g_wtlo);

    float* out_hs = (float*)d_out;
    float* out_hp = (float*)d_out + (size_t)n * 64;

    const int EB = (e + 255) / 256;
    const int GB = (n + 127) / 128;
    const int WB = (n + 7) / 8;

    constexpr int SMEM_F     = 2 * 128 * 384 + 256 * 384;          // 196608
    constexpr int SMEM_SMALL = (128 + 128 + 64 + 64) * 64 * 2;     // 49152
    cudaFuncSetAttribute(tc_gemm_fused<192>,   cudaFuncAttributeMaxDynamicSharedMemorySize, SMEM_F);
    cudaFuncSetAttribute(tc_gemm_small<64, 64>, cudaFuncAttributeMaxDynamicSharedMemorySize, SMEM_SMALL);

    // ---- weight prep: fused [W|rW]^T layout ----
    Prep8 pa;
    const float* Ws[8] = {g0W, g0rW, g1W, g1rW, g2W, g2rW, p0W, p1W};
    for (int m = 0; m < 8; m++) {
        pa.W[m] = Ws[m];
        pa.K[m] = (m < 6) ? 192 : 64;
        pa.N[m] = (m < 6) ? 128 : 64;
        pa.off[m] = (m < 6) ? (m >> 1) * WT_FUSED + (m & 1) * (128 * 192)
                            : 3 * WT_FUSED + (m - 6) * WT_SMALL;
    }
    prep_kernel<<<64, 256>>>(pa);

    // ---- CSR build ----
    cudaMemsetAsync(cnt, 0, (size_t)n * sizeof(int));
    count_kernel<<<EB, 256>>>(dst, e);
    scan_kernel<<<1, 1024>>>(n);
    fill_kernel<<<EB, 256>>>(src, dst, e);

    const int F0 = 0 * WT_FUSED, F1 = 1 * WT_FUSED, F2 = 2 * WT_FUSED;
    const int P0 = 3 * WT_FUSED, P1 = 3 * WT_FUSED + WT_SMALL;

    // ---- layer 0 ----
    tc_gemm_fused<192><<<GB, 256, SMEM_F>>>(fvs, 128, pos, wthi + F0, wtlo + F0,
                                            g0al, g0ar, h, rh, n);
    agg_kernel<128, 0, false><<<WB, 256>>>(h, rh, hs, n);
    tc_gemm_small<64, 64><<<GB, 256, SMEM_SMALL>>>(pos, wthi + P0, wtlo + P0,
                                                   p0al, p0ar, h, n);
    agg_kernel<64, 1, false><<<WB, 256>>>(h, pos, hp, n);

    // ---- layer 1 ----
    tc_gemm_fused<192><<<GB, 256, SMEM_F>>>(hs, 128, hp, wthi + F1, wtlo + F1,
                                            g1al, g1ar, h, rh, n);
    agg_kernel<128, 0, false><<<WB, 256>>>(h, rh, hs2, n);
    tc_gemm_small<64, 64><<<GB, 256, SMEM_SMALL>>>(hp, wthi + P1, wtlo + P1,
                                                   p1al, p1ar, h, n);
    agg_kernel<64, 1, false><<<WB, 256>>>(h, hp, out_hp, n);

    // ---- layer 2 (output, head-mean) ----
    tc_gemm_fused<192><<<GB, 256, SMEM_F>>>(hs2, 128, out_hp, wthi + F2, wtlo + F2,
                                            g2al, g2ar, h, rh, n);
    agg_kernel<128, 0, true><<<WB, 256>>>(h, rh, out_hs, n);
}

// round 8
// speedup vs baseline: 1.8136x; 1.0064x over previous
#include <cuda_runtime.h>
#include <cuda_bf16.h>
#include <math.h>
#include <stdint.h>

// ---------------------------------------------------------------------------
// Problem constants
// ---------------------------------------------------------------------------
#define NMAX 50000
#define EMAX 800000

// ---------------------------------------------------------------------------
// Scratch (device globals)
// ---------------------------------------------------------------------------
__device__ float g_h  [(size_t)NMAX * 128];
__device__ float g_rh [(size_t)NMAX * 128];
__device__ float g_hs [(size_t)NMAX * 128];
__device__ float g_hs2[(size_t)NMAX * 128];
__device__ float g_hp [(size_t)NMAX * 64];
__device__ float g_el [(size_t)NMAX * 2];
__device__ float g_er [(size_t)NMAX * 2];
__device__ int   g_off[NMAX + 1];
__device__ int   g_cnt[NMAX];
__device__ int   g_esrc[EMAX];

// Fused transposed hi/lo bf16 weights:
// 3 fused big mats [256 x 192]  (rows 0-127 = W^T, rows 128-255 = rW^T)
// 2 small mats [64 x 64]
#define WT_FUSED (256 * 192)
#define WT_SMALL (64 * 64)
__device__ uint16_t g_wthi[3 * WT_FUSED + 2 * WT_SMALL];
__device__ uint16_t g_wtlo[3 * WT_FUSED + 2 * WT_SMALL];

// ---------------------------------------------------------------------------
// Helpers
// ---------------------------------------------------------------------------
__device__ __forceinline__ uint32_t smem_u32(const void* p) {
    uint32_t a;
    asm("{ .reg .u64 t; cvta.to.shared.u64 t, %1; cvt.u32.u64 %0, t; }"
        : "=r"(a) : "l"(p));
    return a;
}

__device__ __forceinline__ void ldsm_x4(uint32_t* r, uint32_t addr) {
    asm volatile("ldmatrix.sync.aligned.m8n8.x4.shared.b16 {%0,%1,%2,%3}, [%4];"
                 : "=r"(r[0]), "=r"(r[1]), "=r"(r[2]), "=r"(r[3]) : "r"(addr));
}

__device__ __forceinline__ void mma16816(float* c, const uint32_t* a, const uint32_t* b) {
    asm volatile(
        "mma.sync.aligned.m16n8k16.row.col.f32.bf16.bf16.f32 "
        "{%0,%1,%2,%3}, {%4,%5,%6,%7}, {%8,%9}, {%0,%1,%2,%3};"
        : "+f"(c[0]), "+f"(c[1]), "+f"(c[2]), "+f"(c[3])
        : "r"(a[0]), "r"(a[1]), "r"(a[2]), "r"(a[3]), "r"(b[0]), "r"(b[1]));
}

__device__ __forceinline__ void cpasync16(uint32_t s, const void* g) {
    asm volatile("cp.async.cg.shared.global [%0], [%1], 16;" :: "r"(s), "l"(g));
}
__device__ __forceinline__ void cpasync_wait() {
    asm volatile("cp.async.commit_group;");
    asm volatile("cp.async.wait_group 0;" ::: "memory");
}

__device__ __forceinline__ void split8(const float* v, uint4& h4, uint4& l4) {
    uint16_t* hp = (uint16_t*)&h4;
    uint16_t* lp = (uint16_t*)&l4;
#pragma unroll
    for (int i = 0; i < 8; i++) {
        __nv_bfloat16 hb = __float2bfloat16(v[i]);
        float r = v[i] - __bfloat162float(hb);
        __nv_bfloat16 lb = __float2bfloat16(r);
        hp[i] = *(uint16_t*)&hb;
        lp[i] = *(uint16_t*)&lb;
    }
}

// 16B-chunk XOR swizzle within 128B groups: conflict-free ldmatrix + STS.
__device__ __forceinline__ uint32_t swz(int row, int g, int ROWB) {
    int c = (g & ~7) | ((g ^ row) & 7);
    return (uint32_t)(row * ROWB + c * 16);
}

// ---------------------------------------------------------------------------
// Weight prep: build fused [W|rW]^T hi/lo planes.
// ---------------------------------------------------------------------------
struct Prep8 {
    const float* W[8];
    int K[8], N[8], off[8];
};

__global__ void prep_kernel(Prep8 p) {
    for (int m = 0; m < 8; m++) {
        const int K = p.K[m], N = p.N[m], tot = K * N, off = p.off[m];
        const float* W = p.W[m];
        for (int idx = blockIdx.x * blockDim.x + threadIdx.x; idx < tot;
             idx += gridDim.x * blockDim.x) {
            int n = idx / K, k = idx - n * K;
            float w = W[(size_t)k * N + n];
            __nv_bfloat16 h = __float2bfloat16(w);
            float r = w - __bfloat162float(h);
            __nv_bfloat16 l = __float2bfloat16(r);
            g_wthi[off + idx] = *(uint16_t*)&h;
            g_wtlo[off + idx] = *(uint16_t*)&l;
        }
    }
}

// ---------------------------------------------------------------------------
// Fused bf16x3 GEMM:  [C1 | C2][M,128+128] = [A1|A2][M,192] @ [W|rW]^T
// Also computes el/er from the C1 register fragments.
// ---------------------------------------------------------------------------
template <int K>
__global__ __launch_bounds__(256, 1) void tc_gemm_fused(
    const float* __restrict__ A1, int K1,
    const float* __restrict__ A2,
    const uint16_t* __restrict__ Bh, const uint16_t* __restrict__ Bl,
    const float* __restrict__ al, const float* __restrict__ ar,
    float* __restrict__ C1, float* __restrict__ C2, int M)
{
    constexpr int BN   = 256;
    constexpr int ROWB = K * 2;
    constexpr int NG   = K / 8;
    constexpr int WN   = 128;
    constexpr int NT   = WN / 8;          // 16
    constexpr int KS   = K / 16;          // 12
    constexpr int AOFF  = 0;
    constexpr int ALOFF = 128 * ROWB;
    constexpr int BOFF  = 2 * 128 * ROWB;

    extern __shared__ char smem[];
    const uint32_t sb  = smem_u32(smem);
    const uint32_t sAH = sb + AOFF;
    const uint32_t sAL = sb + ALOFF;
    const uint32_t sB  = sb + BOFF;

    const int t    = threadIdx.x;
    const int wid  = t >> 5;
    const int lane = t & 31;
    const int bm   = blockIdx.x * 128;

    for (int idx = t; idx < BN * NG; idx += 256) {
        int rn = idx / NG, g = idx - rn * NG;
        cpasync16(sB + swz(rn, g, ROWB), Bh + (size_t)rn * K + g * 8);
    }

    for (int idx = t; idx < 128 * NG; idx += 256) {
        int row = idx / NG, g = idx - row * NG, k0 = g * 8;
        int grow = bm + row;
        float v[8] = {0, 0, 0, 0, 0, 0, 0, 0};
        if (grow < M) {
            const float* p = (k0 < K1) ? (A1 + (size_t)grow * K1 + k0)
                                       : (A2 + (size_t)grow * (K - K1) + (k0 - K1));
            *(float4*)&v[0] = ((const float4*)p)[0];
            *(float4*)&v[4] = ((const float4*)p)[1];
        }
        uint4 h4, l4;
        split8(v, h4, l4);
        uint32_t o = swz(row, g, ROWB);
        *(uint4*)(smem + AOFF + o)  = h4;
        *(uint4*)(smem + ALOFF + o) = l4;
    }
    cpasync_wait();
    __syncthreads();

    const int wm   = wid & 3;
    const int wn   = wid >> 2;
    const int lr   = lane & 7;
    const int sel  = lane >> 3;
    const int selb1 = sel & 1;
    const int selb2 = sel >> 1;
    const int rowA_base = wm * 32 + lr + selb1 * 8;
    const int rowB_base = wn * WN + lr + selb2 * 8;

    float acc[2][NT][4];
#pragma unroll
    for (int mt = 0; mt < 2; mt++)
#pragma unroll
        for (int nt = 0; nt < NT; nt++)
#pragma unroll
            for (int q = 0; q < 4; q++) acc[mt][nt][q] = 0.f;

#pragma unroll
    for (int ks = 0; ks < KS; ks++) {
        uint32_t bfr[NT][2];
#pragma unroll
        for (int nt2 = 0; nt2 < NT / 2; nt2++) {
            uint32_t r[4];
            ldsm_x4(r, sB + swz(rowB_base + nt2 * 16, ks * 2 + selb1, ROWB));
            bfr[2 * nt2][0]     = r[0];
            bfr[2 * nt2][1]     = r[1];
            bfr[2 * nt2 + 1][0] = r[2];
            bfr[2 * nt2 + 1][1] = r[3];
        }
        uint32_t afr[2][4];
#pragma unroll
        for (int mt = 0; mt < 2; mt++)
            ldsm_x4(afr[mt], sAH + swz(rowA_base + mt * 16, ks * 2 + selb2, ROWB));
#pragma unroll
        for (int mt = 0; mt < 2; mt++)
#pragma unroll
            for (int nt = 0; nt < NT; nt++)
                mma16816(acc[mt][nt], afr[mt], bfr[nt]);
#pragma unroll
        for (int mt = 0; mt < 2; mt++)
            ldsm_x4(afr[mt], sAL + swz(rowA_base + mt * 16, ks * 2 + selb2, ROWB));
#pragma unroll
        for (int mt = 0; mt < 2; mt++)
#pragma unroll
            for (int nt = 0; nt < NT; nt++)
                mma16816(acc[mt][nt], afr[mt], bfr[nt]);
    }

    __syncthreads();
    for (int idx = t; idx < BN * NG; idx += 256) {
        int rn = idx / NG, g = idx - rn * NG;
        cpasync16(sB + swz(rn, g, ROWB), Bl + (size_t)rn * K + g * 8);
    }
    cpasync_wait();
    __syncthreads();

#pragma unroll
    for (int ks = 0; ks < KS; ks++) {
        uint32_t bfr[NT][2];
#pragma unroll
        for (int nt2 = 0; nt2 < NT / 2; nt2++) {
            uint32_t r[4];
            ldsm_x4(r, sB + swz(rowB_base + nt2 * 16, ks * 2 + selb1, ROWB));
            bfr[2 * nt2][0]     = r[0];
            bfr[2 * nt2][1]     = r[1];
            bfr[2 * nt2 + 1][0] = r[2];
            bfr[2 * nt2 + 1][1] = r[3];
        }
        uint32_t afr[2][4];
#pragma unroll
        for (int mt = 0; mt < 2; mt++)
            ldsm_x4(afr[mt], sAH + swz(rowA_base + mt * 16, ks * 2 + selb2, ROWB));
#pragma unroll
        for (int mt = 0; mt < 2; mt++)
#pragma unroll
            for (int nt = 0; nt < NT; nt++)
                mma16816(acc[mt][nt], afr[mt], bfr[nt]);
    }

    float* __restrict__ C = (wn == 0) ? C1 : C2;
    const int colb = (lane & 3) * 2;
#pragma unroll
    for (int mt = 0; mt < 2; mt++) {
        int r0 = bm + wm * 32 + mt * 16 + (lane >> 2);
        int r1 = r0 + 8;
#pragma unroll
        for (int nt = 0; nt < NT; nt++) {
            int col = colb + nt * 8;
            if (r0 < M) *(float2*)&C[(size_t)r0 * 128 + col] =
                make_float2(acc[mt][nt][0], acc[mt][nt][1]);
            if (r1 < M) *(float2*)&C[(size_t)r1 * 128 + col] =
                make_float2(acc[mt][nt][2], acc[mt][nt][3]);
        }
    }

    if (wn == 0) {
#pragma unroll
        for (int mt = 0; mt < 2; mt++) {
            float e[8];
#pragma unroll
            for (int q = 0; q < 8; q++) e[q] = 0.f;
#pragma unroll
            for (int nt = 0; nt < NT; nt++) {
                int c = colb + nt * 8;
                float a0 = al[c], a1 = al[c + 1];
                float b0 = ar[c], b1 = ar[c + 1];
                float sl0 = acc[mt][nt][0] * a0 + acc[mt][nt][1] * a1;
                float sl1 = acc[mt][nt][2] * a0 + acc[mt][nt][3] * a1;
                float sr0 = acc[mt][nt][0] * b0 + acc[mt][nt][1] * b1;
                float sr1 = acc[mt][nt][2] * b0 + acc[mt][nt][3] * b1;
                int hsel = (nt < 8) ? 0 : 1;
                e[hsel]     += sl0;
                e[2 + hsel] += sr0;
                e[4 + hsel] += sl1;
                e[6 + hsel] += sr1;
            }
#pragma unroll
            for (int o = 1; o <= 2; o <<= 1)
#pragma unroll
                for (int q = 0; q < 8; q++)
                    e[q] += __shfl_xor_sync(0xffffffffu, e[q], o);
            if ((lane & 3) == 0) {
                int r0 = bm + wm * 32 + mt * 16 + (lane >> 2);
                int r1 = r0 + 8;
                if (r0 < M) {
                    g_el[2 * r0] = e[0]; g_el[2 * r0 + 1] = e[1];
                    g_er[2 * r0] = e[2]; g_er[2 * r0 + 1] = e[3];
                }
                if (r1 < M) {
                    g_el[2 * r1] = e[4]; g_el[2 * r1 + 1] = e[5];
                    g_er[2 * r1] = e[6]; g_er[2 * r1 + 1] = e[7];
                }
            }
        }
    }
}

// ---------------------------------------------------------------------------
// Small bf16x3 GEMM (pg layers) with fused el/er epilogue.
// ---------------------------------------------------------------------------
template <int BN, int K>
__global__ __launch_bounds__(256, 1) void tc_gemm_small(
    const float* __restrict__ A1,
    const uint16_t* __restrict__ Bh, const uint16_t* __restrict__ Bl,
    const float* __restrict__ al, const float* __restrict__ ar,
    float* __restrict__ C, int M)
{
    constexpr int ROWB = K * 2;
    constexpr int NG   = K / 8;
    constexpr int WN   = BN / 2;          // 32
    constexpr int NT   = WN / 8;          // 4
    constexpr int KS   = K / 16;

    extern __shared__ char smem[];
    const uint32_t sAH = smem_u32(smem);
    const uint32_t sAL = sAH + 128 * ROWB;
    const uint32_t sBH = sAL + 128 * ROWB;
    const uint32_t sBL = sBH + BN * ROWB;

    const int t    = threadIdx.x;
    const int wid  = t >> 5;
    const int lane = t & 31;
    const int bm   = blockIdx.x * 128;

    for (int idx = t; idx < BN * NG; idx += 256) {
        int rn = idx / NG, g = idx - rn * NG, k0 = g * 8;
        cpasync16(sBH + swz(rn, g, ROWB), Bh + (size_t)rn * K + k0);
        cpasync16(sBL + swz(rn, g, ROWB), Bl + (size_t)rn * K + k0);
    }
    for (int idx = t; idx < 128 * NG; idx += 256) {
        int row = idx / NG, g = idx - row * NG, k0 = g * 8;
        int grow = bm + row;
        float v[8] = {0, 0, 0, 0, 0, 0, 0, 0};
        if (grow < M) {
            const float* p = A1 + (size_t)grow * K + k0;
            *(float4*)&v[0] = ((const float4*)p)[0];
            *(float4*)&v[4] = ((const float4*)p)[1];
        }
        uint4 h4, l4;
        split8(v, h4, l4);
        uint32_t o = swz(row, g, ROWB);
        *(uint4*)(smem + o) = h4;
        *(uint4*)(smem + 128 * ROWB + o) = l4;
    }
    cpasync_wait();
    __syncthreads();

    const int wm = wid & 3;
    const int wn = wid >> 2;
    const int lr   = lane & 7;
    const int sel  = lane >> 3;
    const int selb1 = sel & 1;
    const int selb2 = sel >> 1;
    const int rowA_base = wm * 32 + lr + selb1 * 8;
    const int rowB_base = wn * WN + lr + selb2 * 8;

    float acc[2][NT][4];
#pragma unroll
    for (int mt = 0; mt < 2; mt++)
#pragma unroll
        for (int nt = 0; nt < NT; nt++)
#pragma unroll
            for (int q = 0; q < 4; q++) acc[mt][nt][q] = 0.f;

#pragma unroll
    for (int pr = 0; pr < 3; pr++) {
        const uint32_t baseA = (pr == 2) ? sAL : sAH;
        const uint32_t baseB = (pr == 1) ? sBL : sBH;
#pragma unroll
        for (int ks = 0; ks < KS; ks++) {
            uint32_t afr[2][4];
#pragma unroll
            for (int mt = 0; mt < 2; mt++)
                ldsm_x4(afr[mt], baseA + swz(rowA_base + mt * 16, ks * 2 + selb2, ROWB));
            uint32_t bfr[NT][2];
#pragma unroll
            for (int nt2 = 0; nt2 < NT / 2; nt2++) {
                uint32_t r[4];
                ldsm_x4(r, baseB + swz(rowB_base + nt2 * 16, ks * 2 + selb1, ROWB));
                bfr[2 * nt2][0]     = r[0];
                bfr[2 * nt2][1]     = r[1];
                bfr[2 * nt2 + 1][0] = r[2];
                bfr[2 * nt2 + 1][1] = r[3];
            }
#pragma unroll
            for (int mt = 0; mt < 2; mt++)
#pragma unroll
                for (int nt = 0; nt < NT; nt++)
                    mma16816(acc[mt][nt], afr[mt], bfr[nt]);
        }
    }

    const int colb = wn * WN + (lane & 3) * 2;
#pragma unroll
    for (int mt = 0; mt < 2; mt++) {
        int r0 = bm + wm * 32 + mt * 16 + (lane >> 2);
        int r1 = r0 + 8;
#pragma unroll
        for (int nt = 0; nt < NT; nt++) {
            int col = colb + nt * 8;
            if (r0 < M) *(float2*)&C[(size_t)r0 * BN + col] =
                make_float2(acc[mt][nt][0], acc[mt][nt][1]);
            if (r1 < M) *(float2*)&C[(size_t)r1 * BN + col] =
                make_float2(acc[mt][nt][2], acc[mt][nt][3]);
        }
    }

#pragma unroll
    for (int mt = 0; mt < 2; mt++) {
        float e[4];
#pragma unroll
        for (int q = 0; q < 4; q++) e[q] = 0.f;
#pragma unroll
        for (int nt = 0; nt < NT; nt++) {
            int c = colb + nt * 8;
            float a0 = al[c], a1 = al[c + 1];
            float b0 = ar[c], b1 = ar[c + 1];
            e[0] += acc[mt][nt][0] * a0 + acc[mt][nt][1] * a1;
            e[1] += acc[mt][nt][0] * b0 + acc[mt][nt][1] * b1;
            e[2] += acc[mt][nt][2] * a0 + acc[mt][nt][3] * a1;
            e[3] += acc[mt][nt][2] * b0 + acc[mt][nt][3] * b1;
        }
#pragma unroll
        for (int o = 1; o <= 2; o <<= 1)
#pragma unroll
            for (int q = 0; q < 4; q++)
                e[q] += __shfl_xor_sync(0xffffffffu, e[q], o);
        if ((lane & 3) == 0) {
            int r0 = bm + wm * 32 + mt * 16 + (lane >> 2);
            int r1 = r0 + 8;
            if (r0 < M) { g_el[2 * r0 + wn] = e[0]; g_er[2 * r0 + wn] = e[1]; }
            if (r1 < M) { g_el[2 * r1 + wn] = e[2]; g_er[2 * r1 + wn] = e[3]; }
        }
    }
}

// ---------------------------------------------------------------------------
// CSR build (4 edges per thread for MLP)
// ---------------------------------------------------------------------------
__global__ void count_kernel(const int* __restrict__ dst, int e) {
    int i = (blockIdx.x * blockDim.x + threadIdx.x) * 4;
    if (i + 4 <= e) {
        int4 d = *(const int4*)(dst + i);
        atomicAdd(&g_cnt[d.x], 1);
        atomicAdd(&g_cnt[d.y], 1);
        atomicAdd(&g_cnt[d.z], 1);
        atomicAdd(&g_cnt[d.w], 1);
    } else {
        for (int j = i; j < e; j++) atomicAdd(&g_cnt[dst[j]], 1);
    }
}

__global__ void scan_kernel(int n) {
    __shared__ int partial[1024];
    const int t = threadIdx.x;
    const int C = (n + 1023) / 1024;
    int s = 0;
    for (int j = 0; j < C; j++) {
        int idx = t * C + j;
        if (idx < n) s += g_cnt[idx];
    }
    partial[t] = s;
    __syncthreads();
    for (int ofs = 1; ofs < 1024; ofs <<= 1) {
        int v = (t >= ofs) ? partial[t - ofs] : 0;
        __syncthreads();
        partial[t] += v;
        __syncthreads();
    }
    int run = (t == 0) ? 0 : partial[t - 1];
    for (int j = 0; j < C; j++) {
        int idx = t * C + j;
        if (idx < n) {
            g_off[idx] = run;
            run += g_cnt[idx];
            g_cnt[idx] = 0;
        }
    }
    if (t == 1023) g_off[n] = run;
}

__global__ void fill_kernel(const int* __restrict__ src, const int* __restrict__ dst, int e) {
    int i = (blockIdx.x * blockDim.x + threadIdx.x) * 4;
    if (i + 4 <= e) {
        int4 d = *(const int4*)(dst + i);
        int4 s = *(const int4*)(src + i);
        int o0 = g_off[d.x], o1 = g_off[d.y], o2 = g_off[d.z], o3 = g_off[d.w];
        int p0 = atomicAdd(&g_cnt[d.x], 1);
        int p1 = atomicAdd(&g_cnt[d.y], 1);
        int p2 = atomicAdd(&g_cnt[d.z], 1);
        int p3 = atomicAdd(&g_cnt[d.w], 1);
        g_esrc[o0 + p0] = s.x;
        g_esrc[o1 + p1] = s.y;
        g_esrc[o2 + p2] = s.z;
        g_esrc[o3 + p3] = s.w;
    } else {
        for (int j = i; j < e; j++) {
            int d = dst[j];
            int p = atomicAdd(&g_cnt[d], 1);
            g_esrc[g_off[d] + p] = src[j];
        }
    }
}

// ---------------------------------------------------------------------------
// Aggregation: warp per dst node, SINGLE PASS online softmax.
// Lane owns V=HD/32 contiguous cols; 4-edge load batching.
// ACT: 0 = elu, 1 = tanh.
// ---------------------------------------------------------------------------
__device__ __forceinline__ float leaky02(float x) { return x > 0.f ? x : 0.2f * x; }

template <int HD, int ACT, bool HEADMEAN>
__global__ void agg_kernel(const float* __restrict__ h,
                           const float* __restrict__ res,
                           float* __restrict__ out, int n)
{
    constexpr int V = HD / 32;           // 4 or 2
    int node = (blockIdx.x * blockDim.x + threadIdx.x) >> 5;
    int lane = threadIdx.x & 31;
    if (node >= n) return;

    const int beg = g_off[node];
    const int end = g_off[node + 1];
    const float2 erv = ((const float2*)g_er)[node];
    const float2* __restrict__ el2 = (const float2*)g_el;
    const int* __restrict__ esrc = g_esrc;

    const bool head0 = (lane * V) < (HD / 2);
    float m0 = -1e30f, m1 = -1e30f;
    float d0 = 0.f, d1 = 0.f;
    float acc[V];
#pragma unroll
    for (int q = 0; q < V; q++) acc[q] = 0.f;

    int i = beg;
    for (; i + 4 <= end; i += 4) {
        int s[4];
#pragma unroll
        for (int j = 0; j < 4; j++) s[j] = esrc[i + j];
        float2 ev[4];
#pragma unroll
        for (int j = 0; j < 4; j++) ev[j] = el2[s[j]];
        float hv[4][V];
#pragma unroll
        for (int j = 0; j < 4; j++) {
            if (V == 4) *(float4*)hv[j] = *(const float4*)(h + (size_t)s[j] * HD + lane * V);
            else        *(float2*)hv[j] = *(const float2*)(h + (size_t)s[j] * HD + lane * V);
        }
#pragma unroll
        for (int j = 0; j < 4; j++) {
            float e0 = leaky02(ev[j].x + erv.x);
            float e1 = leaky02(ev[j].y + erv.y);
            float nm0 = fmaxf(m0, e0), nm1 = fmaxf(m1, e1);
            float sc0 = __expf(m0 - nm0), w0 = __expf(e0 - nm0);
            float sc1 = __expf(m1 - nm1), w1 = __expf(e1 - nm1);
            d0 = d0 * sc0 + w0;
            d1 = d1 * sc1 + w1;
            m0 = nm0; m1 = nm1;
            float scv = head0 ? sc0 : sc1;
            float wv  = head0 ? w0  : w1;
#pragma unroll
            for (int q = 0; q < V; q++) acc[q] = fmaf(acc[q], scv, wv * hv[j][q]);
        }
    }
    for (; i < end; i++) {
        int s = esrc[i];
        float2 ev = el2[s];
        float hv[V];
        if (V == 4) *(float4*)hv = *(const float4*)(h + (size_t)s * HD + lane * V);
        else        *(float2*)hv = *(const float2*)(h + (size_t)s * HD + lane * V);
        float e0 = leaky02(ev.x + erv.x);
        float e1 = leaky02(ev.y + erv.y);
        float nm0 = fmaxf(m0, e0), nm1 = fmaxf(m1, e1);
        float sc0 = __expf(m0 - nm0), w0 = __expf(e0 - nm0);
        float sc1 = __expf(m1 - nm1), w1 = __expf(e1 - nm1);
        d0 = d0 * sc0 + w0;
        d1 = d1 * sc1 + w1;
        m0 = nm0; m1 = nm1;
        float scv = head0 ? sc0 : sc1;
        float wv  = head0 ? w0  : w1;
#pragma unroll
        for (int q = 0; q < V; q++) acc[q] = fmaf(acc[q], scv, wv * hv[q]);
    }

    const bool has = (end > beg);
    const float inv0 = has ? 1.f / d0 : 0.f;
    const float inv1 = has ? 1.f / d1 : 0.f;
    const float invv = head0 ? inv0 : inv1;

    float rr[V];
    if (V == 4) *(float4*)rr = *(const float4*)(res + (size_t)node * HD + lane * V);
    else        *(float2*)rr = *(const float2*)(res + (size_t)node * HD + lane * V);

    float v[V];
#pragma unroll
    for (int q = 0; q < V; q++) {
        v[q] = acc[q] * invv + rr[q];
        if (ACT == 0) v[q] = v[q] > 0.f ? v[q] : expm1f(v[q]);
        else          v[q] = tanhf(v[q]);
    }

    if (HEADMEAN) {
        float p[V];
#pragma unroll
        for (int q = 0; q < V; q++) p[q] = __shfl_xor_sync(0xffffffffu, v[q], 16);
        if (lane < 16) {
            float o[V];
#pragma unroll
            for (int q = 0; q < V; q++) o[q] = 0.5f * (v[q] + p[q]);
            if (V == 4) *(float4*)(out + (size_t)node * 64 + lane * V) = *(float4*)o;
            else        *(float2*)(out + (size_t)node * 64 + lane * V) = *(float2*)o;
        }
    } else {
        if (V == 4) *(float4*)(out + (size_t)node * HD + lane * V) = *(float4*)v;
        else        *(float2*)(out + (size_t)node * HD + lane * V) = *(float2*)v;
    }
}

// ---------------------------------------------------------------------------
// Launch
// ---------------------------------------------------------------------------
extern "C" void kernel_launch(void* const* d_in, const int* in_sizes, int n_in,
                              void* d_out, int out_size)
{
    const float* fvs = (const float*)d_in[0];
    const float* pos = (const float*)d_in[1];
    const int*   src = (const int*)d_in[2];
    const int*   dst = (const int*)d_in[3];
    const float* g0W  = (const float*)d_in[4];
    const float* g0al = (const float*)d_in[5];
    const float* g0ar = (const float*)d_in[6];
    const float* g0rW = (const float*)d_in[7];
    const float* g1W  = (const float*)d_in[8];
    const float* g1al = (const float*)d_in[9];
    const float* g1ar = (const float*)d_in[10];
    const float* g1rW = (const float*)d_in[11];
    const float* g2W  = (const float*)d_in[12];
    const float* g2al = (const float*)d_in[13];
    const float* g2ar = (const float*)d_in[14];
    const float* g2rW = (const float*)d_in[15];
    const float* p0W  = (const float*)d_in[16];
    const float* p0al = (const float*)d_in[17];
    const float* p0ar = (const float*)d_in[18];
    const float* p1W  = (const float*)d_in[19];
    const float* p1al = (const float*)d_in[20];
    const float* p1ar = (const float*)d_in[21];

    const int n = in_sizes[0] / 128;
    const int e = in_sizes[2];

    float *h, *rh, *hs, *hs2, *hp;
    int* cnt;
    uint16_t *wthi, *wtlo;
    cudaGetSymbolAddress((void**)&h,    g_h);
    cudaGetSymbolAddress((void**)&rh,   g_rh);
    cudaGetSymbolAddress((void**)&hs,   g_hs);
    cudaGetSymbolAddress((void**)&hs2,  g_hs2);
    cudaGetSymbolAddress((void**)&hp,   g_hp);
    cudaGetSymbolAddress((void**)&cnt,  g_cnt);
    cudaGetSymbolAddress((void**)&wthi, g_wthi);
    cudaGetSymbolAddress((void**)&wtlo, g_wtlo);

    float* out_hs = (float*)d_out;
    float* out_hp = (float*)d_out + (size_t)n * 64;

    const int EB4 = (e / 4 + 255) / 256;
    const int GB  = (n + 127) / 128;
    const int WB  = (n + 7) / 8;

    constexpr int SMEM_F     = 2 * 128 * 384 + 256 * 384;          // 196608
    constexpr int SMEM_SMALL = (128 + 128 + 64 + 64) * 64 * 2;     // 49152
    cudaFuncSetAttribute(tc_gemm_fused<192>,    cudaFuncAttributeMaxDynamicSharedMemorySize, SMEM_F);
    cudaFuncSetAttribute(tc_gemm_small<64, 64>, cudaFuncAttributeMaxDynamicSharedMemorySize, SMEM_SMALL);

    // ---- weight prep: fused [W|rW]^T layout ----
    Prep8 pa;
    const float* Ws[8] = {g0W, g0rW, g1W, g1rW, g2W, g2rW, p0W, p1W};
    for (int m = 0; m < 8; m++) {
        pa.W[m] = Ws[m];
        pa.K[m] = (m < 6) ? 192 : 64;
        pa.N[m] = (m < 6) ? 128 : 64;
        pa.off[m] = (m < 6) ? (m >> 1) * WT_FUSED + (m & 1) * (128 * 192)
                            : 3 * WT_FUSED + (m - 6) * WT_SMALL;
    }
    prep_kernel<<<64, 256>>>(pa);

    // ---- CSR build ----
    cudaMemsetAsync(cnt, 0, (size_t)n * sizeof(int));
    count_kernel<<<EB4, 256>>>(dst, e);
    scan_kernel<<<1, 1024>>>(n);
    fill_kernel<<<EB4, 256>>>(src, dst, e);

    const int F0 = 0 * WT_FUSED, F1 = 1 * WT_FUSED, F2 = 2 * WT_FUSED;
    const int P0 = 3 * WT_FUSED, P1 = 3 * WT_FUSED + WT_SMALL;

    // ---- layer 0 ----
    tc_gemm_fused<192><<<GB, 256, SMEM_F>>>(fvs, 128, pos, wthi + F0, wtlo + F0,
                                            g0al, g0ar, h, rh, n);
    agg_kernel<128, 0, false><<<WB, 256>>>(h, rh, hs, n);
    tc_gemm_small<64, 64><<<GB, 256, SMEM_SMALL>>>(pos, wthi + P0, wtlo + P0,
                                                   p0al, p0ar, h, n);
    agg_kernel<64, 1, false><<<WB, 256>>>(h, pos, hp, n);

    // ---- layer 1 ----
    tc_gemm_fused<192><<<GB, 256, SMEM_F>>>(hs, 128, hp, wthi + F1, wtlo + F1,
                                            g1al, g1ar, h, rh, n);
    agg_kernel<128, 0, false><<<WB, 256>>>(h, rh, hs2, n);
    tc_gemm_small<64, 64><<<GB, 256, SMEM_SMALL>>>(hp, wthi + P1, wtlo + P1,
                                                   p1al, p1ar, h, n);
    agg_kernel<64, 1, false><<<WB, 256>>>(h, hp, out_hp, n);

    // ---- layer 2 (output, head-mean) ----
    tc_gemm_fused<192><<<GB, 256, SMEM_F>>>(hs2, 128, out_hp, wthi + F2, wtlo + F2,
                                            g2al, g2ar, h, rh, n);
    agg_kernel<128, 0, true><<<WB, 256>>>(h, rh, out_hs, n);
}

// round 9
// speedup vs baseline: 1.9944x; 1.0997x over previous
#include <cuda_runtime.h>
#include <cuda_bf16.h>
#include <math.h>
#include <stdint.h>

// ---------------------------------------------------------------------------
// Problem constants
// ---------------------------------------------------------------------------
#define NMAX 50000
#define EMAX 800000

// ---------------------------------------------------------------------------
// Scratch (device globals)
// ---------------------------------------------------------------------------
__device__ float g_h  [(size_t)NMAX * 128];   // gat chain Wh
__device__ float g_rh [(size_t)NMAX * 128];   // gat chain rWh
__device__ float g_hs [(size_t)NMAX * 128];
__device__ float g_hs2[(size_t)NMAX * 128];
__device__ float g_hp [(size_t)NMAX * 64];
__device__ float g_hq [(size_t)NMAX * 64];    // pg chain Wh (private scratch)
__device__ float g_el [(size_t)NMAX * 2];     // gat chain el/er
__device__ float g_er [(size_t)NMAX * 2];
__device__ float g_el2[(size_t)NMAX * 2];     // pg chain el/er (private)
__device__ float g_er2[(size_t)NMAX * 2];
__device__ int   g_off[NMAX + 1];
__device__ int   g_cnt[NMAX];
__device__ int   g_esrc[EMAX];

// Fused transposed hi/lo bf16 weights:
// 3 fused big mats [256 x 192]  (rows 0-127 = W^T, rows 128-255 = rW^T)
// 2 small mats [64 x 64]
#define WT_FUSED (256 * 192)
#define WT_SMALL (64 * 64)
__device__ uint16_t g_wthi[3 * WT_FUSED + 2 * WT_SMALL];
__device__ uint16_t g_wtlo[3 * WT_FUSED + 2 * WT_SMALL];

// ---------------------------------------------------------------------------
// Helpers
// ---------------------------------------------------------------------------
__device__ __forceinline__ uint32_t smem_u32(const void* p) {
    uint32_t a;
    asm("{ .reg .u64 t; cvta.to.shared.u64 t, %1; cvt.u32.u64 %0, t; }"
        : "=r"(a) : "l"(p));
    return a;
}

__device__ __forceinline__ void ldsm_x4(uint32_t* r, uint32_t addr) {
    asm volatile("ldmatrix.sync.aligned.m8n8.x4.shared.b16 {%0,%1,%2,%3}, [%4];"
                 : "=r"(r[0]), "=r"(r[1]), "=r"(r[2]), "=r"(r[3]) : "r"(addr));
}

__device__ __forceinline__ void mma16816(float* c, const uint32_t* a, const uint32_t* b) {
    asm volatile(
        "mma.sync.aligned.m16n8k16.row.col.f32.bf16.bf16.f32 "
        "{%0,%1,%2,%3}, {%4,%5,%6,%7}, {%8,%9}, {%0,%1,%2,%3};"
        : "+f"(c[0]), "+f"(c[1]), "+f"(c[2]), "+f"(c[3])
        : "r"(a[0]), "r"(a[1]), "r"(a[2]), "r"(a[3]), "r"(b[0]), "r"(b[1]));
}

__device__ __forceinline__ void cpasync16(uint32_t s, const void* g) {
    asm volatile("cp.async.cg.shared.global [%0], [%1], 16;" :: "r"(s), "l"(g));
}
__device__ __forceinline__ void cpasync_wait() {
    asm volatile("cp.async.commit_group;");
    asm volatile("cp.async.wait_group 0;" ::: "memory");
}

__device__ __forceinline__ void split8(const float* v, uint4& h4, uint4& l4) {
    uint16_t* hp = (uint16_t*)&h4;
    uint16_t* lp = (uint16_t*)&l4;
#pragma unroll
    for (int i = 0; i < 8; i++) {
        __nv_bfloat16 hb = __float2bfloat16(v[i]);
        float r = v[i] - __bfloat162float(hb);
        __nv_bfloat16 lb = __float2bfloat16(r);
        hp[i] = *(uint16_t*)&hb;
        lp[i] = *(uint16_t*)&lb;
    }
}

__device__ __forceinline__ uint32_t swz(int row, int g, int ROWB) {
    int c = (g & ~7) | ((g ^ row) & 7);
    return (uint32_t)(row * ROWB + c * 16);
}

// ---------------------------------------------------------------------------
// Weight prep
// ---------------------------------------------------------------------------
struct Prep8 {
    const float* W[8];
    int K[8], N[8], off[8];
};

__global__ void prep_kernel(Prep8 p) {
    for (int m = 0; m < 8; m++) {
        const int K = p.K[m], N = p.N[m], tot = K * N, off = p.off[m];
        const float* W = p.W[m];
        for (int idx = blockIdx.x * blockDim.x + threadIdx.x; idx < tot;
             idx += gridDim.x * blockDim.x) {
            int n = idx / K, k = idx - n * K;
            float w = W[(size_t)k * N + n];
            __nv_bfloat16 h = __float2bfloat16(w);
            float r = w - __bfloat162float(h);
            __nv_bfloat16 l = __float2bfloat16(r);
            g_wthi[off + idx] = *(uint16_t*)&h;
            g_wtlo[off + idx] = *(uint16_t*)&l;
        }
    }
}

// ---------------------------------------------------------------------------
// Fused bf16x3 GEMM + el/er epilogue (gat chain)
// ---------------------------------------------------------------------------
template <int K>
__global__ __launch_bounds__(256, 1) void tc_gemm_fused(
    const float* __restrict__ A1, int K1,
    const float* __restrict__ A2,
    const uint16_t* __restrict__ Bh, const uint16_t* __restrict__ Bl,
    const float* __restrict__ al, const float* __restrict__ ar,
    float* __restrict__ el, float* __restrict__ er,
    float* __restrict__ C1, float* __restrict__ C2, int M)
{
    constexpr int BN   = 256;
    constexpr int ROWB = K * 2;
    constexpr int NG   = K / 8;
    constexpr int WN   = 128;
    constexpr int NT   = WN / 8;
    constexpr int KS   = K / 16;
    constexpr int AOFF  = 0;
    constexpr int ALOFF = 128 * ROWB;
    constexpr int BOFF  = 2 * 128 * ROWB;

    extern __shared__ char smem[];
    const uint32_t sb  = smem_u32(smem);
    const uint32_t sAH = sb + AOFF;
    const uint32_t sAL = sb + ALOFF;
    const uint32_t sB  = sb + BOFF;

    const int t    = threadIdx.x;
    const int wid  = t >> 5;
    const int lane = t & 31;
    const int bm   = blockIdx.x * 128;

    for (int idx = t; idx < BN * NG; idx += 256) {
        int rn = idx / NG, g = idx - rn * NG;
        cpasync16(sB + swz(rn, g, ROWB), Bh + (size_t)rn * K + g * 8);
    }

    for (int idx = t; idx < 128 * NG; idx += 256) {
        int row = idx / NG, g = idx - row * NG, k0 = g * 8;
        int grow = bm + row;
        float v[8] = {0, 0, 0, 0, 0, 0, 0, 0};
        if (grow < M) {
            const float* p = (k0 < K1) ? (A1 + (size_t)grow * K1 + k0)
                                       : (A2 + (size_t)grow * (K - K1) + (k0 - K1));
            *(float4*)&v[0] = ((const float4*)p)[0];
            *(float4*)&v[4] = ((const float4*)p)[1];
        }
        uint4 h4, l4;
        split8(v, h4, l4);
        uint32_t o = swz(row, g, ROWB);
        *(uint4*)(smem + AOFF + o)  = h4;
        *(uint4*)(smem + ALOFF + o) = l4;
    }
    cpasync_wait();
    __syncthreads();

    const int wm   = wid & 3;
    const int wn   = wid >> 2;
    const int lr   = lane & 7;
    const int sel  = lane >> 3;
    const int selb1 = sel & 1;
    const int selb2 = sel >> 1;
    const int rowA_base = wm * 32 + lr + selb1 * 8;
    const int rowB_base = wn * WN + lr + selb2 * 8;

    float acc[2][NT][4];
#pragma unroll
    for (int mt = 0; mt < 2; mt++)
#pragma unroll
        for (int nt = 0; nt < NT; nt++)
#pragma unroll
            for (int q = 0; q < 4; q++) acc[mt][nt][q] = 0.f;

#pragma unroll
    for (int ks = 0; ks < KS; ks++) {
        uint32_t bfr[NT][2];
#pragma unroll
        for (int nt2 = 0; nt2 < NT / 2; nt2++) {
            uint32_t r[4];
            ldsm_x4(r, sB + swz(rowB_base + nt2 * 16, ks * 2 + selb1, ROWB));
            bfr[2 * nt2][0]     = r[0];
            bfr[2 * nt2][1]     = r[1];
            bfr[2 * nt2 + 1][0] = r[2];
            bfr[2 * nt2 + 1][1] = r[3];
        }
        uint32_t afr[2][4];
#pragma unroll
        for (int mt = 0; mt < 2; mt++)
            ldsm_x4(afr[mt], sAH + swz(rowA_base + mt * 16, ks * 2 + selb2, ROWB));
#pragma unroll
        for (int mt = 0; mt < 2; mt++)
#pragma unroll
            for (int nt = 0; nt < NT; nt++)
                mma16816(acc[mt][nt], afr[mt], bfr[nt]);
#pragma unroll
        for (int mt = 0; mt < 2; mt++)
            ldsm_x4(afr[mt], sAL + swz(rowA_base + mt * 16, ks * 2 + selb2, ROWB));
#pragma unroll
        for (int mt = 0; mt < 2; mt++)
#pragma unroll
            for (int nt = 0; nt < NT; nt++)
                mma16816(acc[mt][nt], afr[mt], bfr[nt]);
    }

    __syncthreads();
    for (int idx = t; idx < BN * NG; idx += 256) {
        int rn = idx / NG, g = idx - rn * NG;
        cpasync16(sB + swz(rn, g, ROWB), Bl + (size_t)rn * K + g * 8);
    }
    cpasync_wait();
    __syncthreads();

#pragma unroll
    for (int ks = 0; ks < KS; ks++) {
        uint32_t bfr[NT][2];
#pragma unroll
        for (int nt2 = 0; nt2 < NT / 2; nt2++) {
            uint32_t r[4];
            ldsm_x4(r, sB + swz(rowB_base + nt2 * 16, ks * 2 + selb1, ROWB));
            bfr[2 * nt2][0]     = r[0];
            bfr[2 * nt2][1]     = r[1];
            bfr[2 * nt2 + 1][0] = r[2];
            bfr[2 * nt2 + 1][1] = r[3];
        }
        uint32_t afr[2][4];
#pragma unroll
        for (int mt = 0; mt < 2; mt++)
            ldsm_x4(afr[mt], sAH + swz(rowA_base + mt * 16, ks * 2 + selb2, ROWB));
#pragma unroll
        for (int mt = 0; mt < 2; mt++)
#pragma unroll
            for (int nt = 0; nt < NT; nt++)
                mma16816(acc[mt][nt], afr[mt], bfr[nt]);
    }

    float* __restrict__ C = (wn == 0) ? C1 : C2;
    const int colb = (lane & 3) * 2;
#pragma unroll
    for (int mt = 0; mt < 2; mt++) {
        int r0 = bm + wm * 32 + mt * 16 + (lane >> 2);
        int r1 = r0 + 8;
#pragma unroll
        for (int nt = 0; nt < NT; nt++) {
            int col = colb + nt * 8;
            if (r0 < M) *(float2*)&C[(size_t)r0 * 128 + col] =
                make_float2(acc[mt][nt][0], acc[mt][nt][1]);
            if (r1 < M) *(float2*)&C[(size_t)r1 * 128 + col] =
                make_float2(acc[mt][nt][2], acc[mt][nt][3]);
        }
    }

    if (wn == 0) {
#pragma unroll
        for (int mt = 0; mt < 2; mt++) {
            float e[8];
#pragma unroll
            for (int q = 0; q < 8; q++) e[q] = 0.f;
#pragma unroll
            for (int nt = 0; nt < NT; nt++) {
                int c = colb + nt * 8;
                float a0 = al[c], a1 = al[c + 1];
                float b0 = ar[c], b1 = ar[c + 1];
                float sl0 = acc[mt][nt][0] * a0 + acc[mt][nt][1] * a1;
                float sl1 = acc[mt][nt][2] * a0 + acc[mt][nt][3] * a1;
                float sr0 = acc[mt][nt][0] * b0 + acc[mt][nt][1] * b1;
                float sr1 = acc[mt][nt][2] * b0 + acc[mt][nt][3] * b1;
                int hsel = (nt < 8) ? 0 : 1;
                e[hsel]     += sl0;
                e[2 + hsel] += sr0;
                e[4 + hsel] += sl1;
                e[6 + hsel] += sr1;
            }
#pragma unroll
            for (int o = 1; o <= 2; o <<= 1)
#pragma unroll
                for (int q = 0; q < 8; q++)
                    e[q] += __shfl_xor_sync(0xffffffffu, e[q], o);
            if ((lane & 3) == 0) {
                int r0 = bm + wm * 32 + mt * 16 + (lane >> 2);
                int r1 = r0 + 8;
                if (r0 < M) {
                    el[2 * r0] = e[0]; el[2 * r0 + 1] = e[1];
                    er[2 * r0] = e[2]; er[2 * r0 + 1] = e[3];
                }
                if (r1 < M) {
                    el[2 * r1] = e[4]; el[2 * r1 + 1] = e[5];
                    er[2 * r1] = e[6]; er[2 * r1 + 1] = e[7];
                }
            }
        }
    }
}

// ---------------------------------------------------------------------------
// Small bf16x3 GEMM (pg layers) with fused el/er epilogue
// ---------------------------------------------------------------------------
template <int BN, int K>
__global__ __launch_bounds__(256, 1) void tc_gemm_small(
    const float* __restrict__ A1,
    const uint16_t* __restrict__ Bh, const uint16_t* __restrict__ Bl,
    const float* __restrict__ al, const float* __restrict__ ar,
    float* __restrict__ el, float* __restrict__ er,
    float* __restrict__ C, int M)
{
    constexpr int ROWB = K * 2;
    constexpr int NG   = K / 8;
    constexpr int WN   = BN / 2;
    constexpr int NT   = WN / 8;
    constexpr int KS   = K / 16;

    extern __shared__ char smem[];
    const uint32_t sAH = smem_u32(smem);
    const uint32_t sAL = sAH + 128 * ROWB;
    const uint32_t sBH = sAL + 128 * ROWB;
    const uint32_t sBL = sBH + BN * ROWB;

    const int t    = threadIdx.x;
    const int wid  = t >> 5;
    const int lane = t & 31;
    const int bm   = blockIdx.x * 128;

    for (int idx = t; idx < BN * NG; idx += 256) {
        int rn = idx / NG, g = idx - rn * NG, k0 = g * 8;
        cpasync16(sBH + swz(rn, g, ROWB), Bh + (size_t)rn * K + k0);
        cpasync16(sBL + swz(rn, g, ROWB), Bl + (size_t)rn * K + k0);
    }
    for (int idx = t; idx < 128 * NG; idx += 256) {
        int row = idx / NG, g = idx - row * NG, k0 = g * 8;
        int grow = bm + row;
        float v[8] = {0, 0, 0, 0, 0, 0, 0, 0};
        if (grow < M) {
            const float* p = A1 + (size_t)grow * K + k0;
            *(float4*)&v[0] = ((const float4*)p)[0];
            *(float4*)&v[4] = ((const float4*)p)[1];
        }
        uint4 h4, l4;
        split8(v, h4, l4);
        uint32_t o = swz(row, g, ROWB);
        *(uint4*)(smem + o) = h4;
        *(uint4*)(smem + 128 * ROWB + o) = l4;
    }
    cpasync_wait();
    __syncthreads();

    const int wm = wid & 3;
    const int wn = wid >> 2;
    const int lr   = lane & 7;
    const int sel  = lane >> 3;
    const int selb1 = sel & 1;
    const int selb2 = sel >> 1;
    const int rowA_base = wm * 32 + lr + selb1 * 8;
    const int rowB_base = wn * WN + lr + selb2 * 8;

    float acc[2][NT][4];
#pragma unroll
    for (int mt = 0; mt < 2; mt++)
#pragma unroll
        for (int nt = 0; nt < NT; nt++)
#pragma unroll
            for (int q = 0; q < 4; q++) acc[mt][nt][q] = 0.f;

#pragma unroll
    for (int pr = 0; pr < 3; pr++) {
        const uint32_t baseA = (pr == 2) ? sAL : sAH;
        const uint32_t baseB = (pr == 1) ? sBL : sBH;
#pragma unroll
        for (int ks = 0; ks < KS; ks++) {
            uint32_t afr[2][4];
#pragma unroll
            for (int mt = 0; mt < 2; mt++)
                ldsm_x4(afr[mt], baseA + swz(rowA_base + mt * 16, ks * 2 + selb2, ROWB));
            uint32_t bfr[NT][2];
#pragma unroll
            for (int nt2 = 0; nt2 < NT / 2; nt2++) {
                uint32_t r[4];
                ldsm_x4(r, baseB + swz(rowB_base + nt2 * 16, ks * 2 + selb1, ROWB));
                bfr[2 * nt2][0]     = r[0];
                bfr[2 * nt2][1]     = r[1];
                bfr[2 * nt2 + 1][0] = r[2];
                bfr[2 * nt2 + 1][1] = r[3];
            }
#pragma unroll
            for (int mt = 0; mt < 2; mt++)
#pragma unroll
                for (int nt = 0; nt < NT; nt++)
                    mma16816(acc[mt][nt], afr[mt], bfr[nt]);
        }
    }

    const int colb = wn * WN + (lane & 3) * 2;
#pragma unroll
    for (int mt = 0; mt < 2; mt++) {
        int r0 = bm + wm * 32 + mt * 16 + (lane >> 2);
        int r1 = r0 + 8;
#pragma unroll
        for (int nt = 0; nt < NT; nt++) {
            int col = colb + nt * 8;
            if (r0 < M) *(float2*)&C[(size_t)r0 * BN + col] =
                make_float2(acc[mt][nt][0], acc[mt][nt][1]);
            if (r1 < M) *(float2*)&C[(size_t)r1 * BN + col] =
                make_float2(acc[mt][nt][2], acc[mt][nt][3]);
        }
    }

#pragma unroll
    for (int mt = 0; mt < 2; mt++) {
        float e[4];
#pragma unroll
        for (int q = 0; q < 4; q++) e[q] = 0.f;
#pragma unroll
        for (int nt = 0; nt < NT; nt++) {
            int c = colb + nt * 8;
            float a0 = al[c], a1 = al[c + 1];
            float b0 = ar[c], b1 = ar[c + 1];
            e[0] += acc[mt][nt][0] * a0 + acc[mt][nt][1] * a1;
            e[1] += acc[mt][nt][0] * b0 + acc[mt][nt][1] * b1;
            e[2] += acc[mt][nt][2] * a0 + acc[mt][nt][3] * a1;
            e[3] += acc[mt][nt][2] * b0 + acc[mt][nt][3] * b1;
        }
#pragma unroll
        for (int o = 1; o <= 2; o <<= 1)
#pragma unroll
            for (int q = 0; q < 4; q++)
                e[q] += __shfl_xor_sync(0xffffffffu, e[q], o);
        if ((lane & 3) == 0) {
            int r0 = bm + wm * 32 + mt * 16 + (lane >> 2);
            int r1 = r0 + 8;
            if (r0 < M) { el[2 * r0 + wn] = e[0]; er[2 * r0 + wn] = e[1]; }
            if (r1 < M) { el[2 * r1 + wn] = e[2]; er[2 * r1 + wn] = e[3]; }
        }
    }
}

// ---------------------------------------------------------------------------
// CSR build
// ---------------------------------------------------------------------------
__global__ void count_kernel(const int* __restrict__ dst, int e) {
    int i = blockIdx.x * blockDim.x + threadIdx.x;
    if (i < e) atomicAdd(&g_cnt[dst[i]], 1);
}

__global__ void scan_kernel(int n) {
    __shared__ int partial[1024];
    const int t = threadIdx.x;
    const int C = (n + 1023) / 1024;
    int s = 0;
    for (int j = 0; j < C; j++) {
        int idx = t * C + j;
        if (idx < n) s += g_cnt[idx];
    }
    partial[t] = s;
    __syncthreads();
    for (int ofs = 1; ofs < 1024; ofs <<= 1) {
        int v = (t >= ofs) ? partial[t - ofs] : 0;
        __syncthreads();
        partial[t] += v;
        __syncthreads();
    }
    int run = (t == 0) ? 0 : partial[t - 1];
    for (int j = 0; j < C; j++) {
        int idx = t * C + j;
        if (idx < n) {
            g_off[idx] = run;
            run += g_cnt[idx];
            g_cnt[idx] = 0;
        }
    }
    if (t == 1023) g_off[n] = run;
}

__global__ void fill_kernel(const int* __restrict__ src, const int* __restrict__ dst, int e) {
    int i = blockIdx.x * blockDim.x + threadIdx.x;
    if (i < e) {
        int d = dst[i];
        int p = atomicAdd(&g_cnt[d], 1);
        g_esrc[g_off[d] + p] = src[i];
    }
}

// ---------------------------------------------------------------------------
// Aggregation: warp per dst node, single-pass online softmax (R8 proven).
// ---------------------------------------------------------------------------
__device__ __forceinline__ float leaky02(float x) { return x > 0.f ? x : 0.2f * x; }

template <int HD, int ACT, bool HEADMEAN>
__global__ void agg_kernel(const float* __restrict__ h,
                           const float* __restrict__ res,
                           const float* __restrict__ elp,
                           const float* __restrict__ erp,
                           float* __restrict__ out, int n)
{
    constexpr int V = HD / 32;
    int node = (blockIdx.x * blockDim.x + threadIdx.x) >> 5;
    int lane = threadIdx.x & 31;
    if (node >= n) return;

    const int beg = g_off[node];
    const int end = g_off[node + 1];
    const float2 erv = ((const float2*)erp)[node];
    const float2* __restrict__ el2 = (const float2*)elp;
    const int* __restrict__ esrc = g_esrc;

    const bool head0 = (lane * V) < (HD / 2);
    float m0 = -1e30f, m1 = -1e30f;
    float d0 = 0.f, d1 = 0.f;
    float acc[V];
#pragma unroll
    for (int q = 0; q < V; q++) acc[q] = 0.f;

    int i = beg;
    for (; i + 4 <= end; i += 4) {
        int s[4];
#pragma unroll
        for (int j = 0; j < 4; j++) s[j] = esrc[i + j];
        float2 ev[4];
#pragma unroll
        for (int j = 0; j < 4; j++) ev[j] = el2[s[j]];
        float hv[4][V];
#pragma unroll
        for (int j = 0; j < 4; j++) {
            if (V == 4) *(float4*)hv[j] = *(const float4*)(h + (size_t)s[j] * HD + lane * V);
            else        *(float2*)hv[j] = *(const float2*)(h + (size_t)s[j] * HD + lane * V);
        }
#pragma unroll
        for (int j = 0; j < 4; j++) {
            float e0 = leaky02(ev[j].x + erv.x);
            float e1 = leaky02(ev[j].y + erv.y);
            float nm0 = fmaxf(m0, e0), nm1 = fmaxf(m1, e1);
            float sc0 = __expf(m0 - nm0), w0 = __expf(e0 - nm0);
            float sc1 = __expf(m1 - nm1), w1 = __expf(e1 - nm1);
            d0 = d0 * sc0 + w0;
            d1 = d1 * sc1 + w1;
            m0 = nm0; m1 = nm1;
            float scv = head0 ? sc0 : sc1;
            float wv  = head0 ? w0  : w1;
#pragma unroll
            for (int q = 0; q < V; q++) acc[q] = fmaf(acc[q], scv, wv * hv[j][q]);
        }
    }
    for (; i < end; i++) {
        int s = esrc[i];
        float2 ev = el2[s];
        float hv[V];
        if (V == 4) *(float4*)hv = *(const float4*)(h + (size_t)s * HD + lane * V);
        else        *(float2*)hv = *(const float2*)(h + (size_t)s * HD + lane * V);
        float e0 = leaky02(ev.x + erv.x);
        float e1 = leaky02(ev.y + erv.y);
        float nm0 = fmaxf(m0, e0), nm1 = fmaxf(m1, e1);
        float sc0 = __expf(m0 - nm0), w0 = __expf(e0 - nm0);
        float sc1 = __expf(m1 - nm1), w1 = __expf(e1 - nm1);
        d0 = d0 * sc0 + w0;
        d1 = d1 * sc1 + w1;
        m0 = nm0; m1 = nm1;
        float scv = head0 ? sc0 : sc1;
        float wv  = head0 ? w0  : w1;
#pragma unroll
        for (int q = 0; q < V; q++) acc[q] = fmaf(acc[q], scv, wv * hv[q]);
    }

    const bool has = (end > beg);
    const float inv0 = has ? 1.f / d0 : 0.f;
    const float inv1 = has ? 1.f / d1 : 0.f;
    const float invv = head0 ? inv0 : inv1;

    float rr[V];
    if (V == 4) *(float4*)rr = *(const float4*)(res + (size_t)node * HD + lane * V);
    else        *(float2*)rr = *(const float2*)(res + (size_t)node * HD + lane * V);

    float v[V];
#pragma unroll
    for (int q = 0; q < V; q++) {
        v[q] = acc[q] * invv + rr[q];
        if (ACT == 0) v[q] = v[q] > 0.f ? v[q] : expm1f(v[q]);
        else          v[q] = tanhf(v[q]);
    }

    if (HEADMEAN) {
        float p[V];
#pragma unroll
        for (int q = 0; q < V; q++) p[q] = __shfl_xor_sync(0xffffffffu, v[q], 16);
        if (lane < 16) {
            float o[V];
#pragma unroll
            for (int q = 0; q < V; q++) o[q] = 0.5f * (v[q] + p[q]);
            if (V == 4) *(float4*)(out + (size_t)node * 64 + lane * V) = *(float4*)o;
            else        *(float2*)(out + (size_t)node * 64 + lane * V) = *(float2*)o;
        }
    } else {
        if (V == 4) *(float4*)(out + (size_t)node * HD + lane * V) = *(float4*)v;
        else        *(float2*)(out + (size_t)node * HD + lane * V) = *(float2*)v;
    }
}

// ---------------------------------------------------------------------------
// Launch — multi-stream graph (s1 = gat chain, s2 = pg chain, s0 = CSR)
// ---------------------------------------------------------------------------
extern "C" void kernel_launch(void* const* d_in, const int* in_sizes, int n_in,
                              void* d_out, int out_size)
{
    const float* fvs = (const float*)d_in[0];
    const float* pos = (const float*)d_in[1];
    const int*   src = (const int*)d_in[2];
    const int*   dst = (const int*)d_in[3];
    const float* g0W  = (const float*)d_in[4];
    const float* g0al = (const float*)d_in[5];
    const float* g0ar = (const float*)d_in[6];
    const float* g0rW = (const float*)d_in[7];
    const float* g1W  = (const float*)d_in[8];
    const float* g1al = (const float*)d_in[9];
    const float* g1ar = (const float*)d_in[10];
    const float* g1rW = (const float*)d_in[11];
    const float* g2W  = (const float*)d_in[12];
    const float* g2al = (const float*)d_in[13];
    const float* g2ar = (const float*)d_in[14];
    const float* g2rW = (const float*)d_in[15];
    const float* p0W  = (const float*)d_in[16];
    const float* p0al = (const float*)d_in[17];
    const float* p0ar = (const float*)d_in[18];
    const float* p1W  = (const float*)d_in[19];
    const float* p1al = (const float*)d_in[20];
    const float* p1ar = (const float*)d_in[21];

    const int n = in_sizes[0] / 128;
    const int e = in_sizes[2];

    float *h, *rh, *hs, *hs2, *hp, *hq, *el, *er, *el2, *er2;
    int* cnt;
    uint16_t *wthi, *wtlo;
    cudaGetSymbolAddress((void**)&h,    g_h);
    cudaGetSymbolAddress((void**)&rh,   g_rh);
    cudaGetSymbolAddress((void**)&hs,   g_hs);
    cudaGetSymbolAddress((void**)&hs2,  g_hs2);
    cudaGetSymbolAddress((void**)&hp,   g_hp);
    cudaGetSymbolAddress((void**)&hq,   g_hq);
    cudaGetSymbolAddress((void**)&el,   g_el);
    cudaGetSymbolAddress((void**)&er,   g_er);
    cudaGetSymbolAddress((void**)&el2,  g_el2);
    cudaGetSymbolAddress((void**)&er2,  g_er2);
    cudaGetSymbolAddress((void**)&cnt,  g_cnt);
    cudaGetSymbolAddress((void**)&wthi, g_wthi);
    cudaGetSymbolAddress((void**)&wtlo, g_wtlo);

    float* out_hs = (float*)d_out;
    float* out_hp = (float*)d_out + (size_t)n * 64;

    const int EB = (e + 255) / 256;
    const int GB = (n + 127) / 128;
    const int WB = (n + 7) / 8;

    constexpr int SMEM_F     = 2 * 128 * 384 + 256 * 384;          // 196608
    constexpr int SMEM_SMALL = (128 + 128 + 64 + 64) * 64 * 2;     // 49152
    cudaFuncSetAttribute(tc_gemm_fused<192>,    cudaFuncAttributeMaxDynamicSharedMemorySize, SMEM_F);
    cudaFuncSetAttribute(tc_gemm_small<64, 64>, cudaFuncAttributeMaxDynamicSharedMemorySize, SMEM_SMALL);

    // Persistent streams/events (host-side resources only; created once;
    // the launched work is identical on every call).
    static cudaStream_t s1 = nullptr, s2 = nullptr;
    static cudaEvent_t evFork, evPrep, evCSR, evP0, evP1, evEnd1, evEnd2;
    if (s1 == nullptr) {
        cudaStreamCreateWithFlags(&s1, cudaStreamNonBlocking);
        cudaStreamCreateWithFlags(&s2, cudaStreamNonBlocking);
        cudaEventCreateWithFlags(&evFork, cudaEventDisableTiming);
        cudaEventCreateWithFlags(&evPrep, cudaEventDisableTiming);
        cudaEventCreateWithFlags(&evCSR,  cudaEventDisableTiming);
        cudaEventCreateWithFlags(&evP0,   cudaEventDisableTiming);
        cudaEventCreateWithFlags(&evP1,   cudaEventDisableTiming);
        cudaEventCreateWithFlags(&evEnd1, cudaEventDisableTiming);
        cudaEventCreateWithFlags(&evEnd2, cudaEventDisableTiming);
    }

    Prep8 pa;
    const float* Ws[8] = {g0W, g0rW, g1W, g1rW, g2W, g2rW, p0W, p1W};
    for (int m = 0; m < 8; m++) {
        pa.W[m] = Ws[m];
        pa.K[m] = (m < 6) ? 192 : 64;
        pa.N[m] = (m < 6) ? 128 : 64;
        pa.off[m] = (m < 6) ? (m >> 1) * WT_FUSED + (m & 1) * (128 * 192)
                            : 3 * WT_FUSED + (m - 6) * WT_SMALL;
    }

    const int F0 = 0 * WT_FUSED, F1 = 1 * WT_FUSED, F2 = 2 * WT_FUSED;
    const int P0 = 3 * WT_FUSED, P1 = 3 * WT_FUSED + WT_SMALL;

    // ---- fork ----
    cudaEventRecord(evFork, 0);
    cudaStreamWaitEvent(s1, evFork, 0);
    cudaStreamWaitEvent(s2, evFork, 0);

    // s1: weight prep (both chains need it)
    prep_kernel<<<64, 256, 0, s1>>>(pa);
    cudaEventRecord(evPrep, s1);
    cudaStreamWaitEvent(s2, evPrep, 0);

    // s0: CSR build (concurrent with prep + first GEMMs)
    cudaMemsetAsync(cnt, 0, (size_t)n * sizeof(int), 0);
    count_kernel<<<EB, 256, 0, 0>>>(dst, e);
    scan_kernel<<<1, 1024, 0, 0>>>(n);
    fill_kernel<<<EB, 256, 0, 0>>>(src, dst, e);
    cudaEventRecord(evCSR, 0);
    cudaStreamWaitEvent(s1, evCSR, 0);
    cudaStreamWaitEvent(s2, evCSR, 0);

    // ---- layer 0 ----
    tc_gemm_fused<192><<<GB, 256, SMEM_F, s1>>>(fvs, 128, pos, wthi + F0, wtlo + F0,
                                                g0al, g0ar, el, er, h, rh, n);
    agg_kernel<128, 0, false><<<WB, 256, 0, s1>>>(h, rh, el, er, hs, n);

    tc_gemm_small<64, 64><<<GB, 256, SMEM_SMALL, s2>>>(pos, wthi + P0, wtlo + P0,
                                                       p0al, p0ar, el2, er2, hq, n);
    agg_kernel<64, 1, false><<<WB, 256, 0, s2>>>(hq, pos, el2, er2, hp, n);
    cudaEventRecord(evP0, s2);

    // ---- layer 1 ----
    cudaStreamWaitEvent(s1, evP0, 0);   // gemmF1 needs hp
    tc_gemm_fused<192><<<GB, 256, SMEM_F, s1>>>(hs, 128, hp, wthi + F1, wtlo + F1,
                                                g1al, g1ar, el, er, h, rh, n);
    agg_kernel<128, 0, false><<<WB, 256, 0, s1>>>(h, rh, el, er, hs2, n);

    tc_gemm_small<64, 64><<<GB, 256, SMEM_SMALL, s2>>>(hp, wthi + P1, wtlo + P1,
                                                       p1al, p1ar, el2, er2, hq, n);
    agg_kernel<64, 1, false><<<WB, 256, 0, s2>>>(hq, hp, el2, er2, out_hp, n);
    cudaEventRecord(evP1, s2);

    // ---- layer 2 (output, head-mean) ----
    cudaStreamWaitEvent(s1, evP1, 0);   // gemmF2 needs out_hp
    tc_gemm_fused<192><<<GB, 256, SMEM_F, s1>>>(hs2, 128, out_hp, wthi + F2, wtlo + F2,
                                                g2al, g2ar, el, er, h, rh, n);
    agg_kernel<128, 0, true><<<WB, 256, 0, s1>>>(h, rh, el, er, out_hs, n);
    cudaEventRecord(evEnd1, s1);
    cudaEventRecord(evEnd2, s2);

    // ---- join ----
    cudaStreamWaitEvent(0, evEnd1, 0);
    cudaStreamWaitEvent(0, evEnd2, 0);
}

// round 10
// speedup vs baseline: 2.0017x; 1.0037x over previous
#include <cuda_runtime.h>
#include <cuda_bf16.h>
#include <math.h>
#include <stdint.h>

// ---------------------------------------------------------------------------
// Problem constants
// ---------------------------------------------------------------------------
#define NMAX 50000
#define EMAX 800000

// ---------------------------------------------------------------------------
// Scratch (device globals)
// ---------------------------------------------------------------------------
__device__ float g_h  [(size_t)NMAX * 128];   // gat chain Wh
__device__ float g_rh [(size_t)NMAX * 128];   // gat chain rWh
__device__ float g_hs [(size_t)NMAX * 128];
__device__ float g_hs2[(size_t)NMAX * 128];
__device__ float g_hp [(size_t)NMAX * 64];
__device__ float g_hq [(size_t)NMAX * 64];    // pg chain Wh (private scratch)
__device__ float g_el [(size_t)NMAX * 2];     // gat chain el/er
__device__ float g_er [(size_t)NMAX * 2];
__device__ float g_el2[(size_t)NMAX * 2];     // pg chain el/er (private)
__device__ float g_er2[(size_t)NMAX * 2];
__device__ int   g_off[NMAX + 1];
__device__ int   g_cnt[NMAX];
__device__ int   g_esrc[EMAX];

// Fused transposed hi/lo bf16 weights:
// 3 fused big mats [256 x 192]  (rows 0-127 = W^T, rows 128-255 = rW^T)
// 2 small mats [64 x 64]
#define WT_FUSED (256 * 192)
#define WT_SMALL (64 * 64)
__device__ uint16_t g_wthi[3 * WT_FUSED + 2 * WT_SMALL];
__device__ uint16_t g_wtlo[3 * WT_FUSED + 2 * WT_SMALL];

// ---------------------------------------------------------------------------
// Helpers
// ---------------------------------------------------------------------------
__device__ __forceinline__ uint32_t smem_u32(const void* p) {
    uint32_t a;
    asm("{ .reg .u64 t; cvta.to.shared.u64 t, %1; cvt.u32.u64 %0, t; }"
        : "=r"(a) : "l"(p));
    return a;
}

__device__ __forceinline__ void ldsm_x4(uint32_t* r, uint32_t addr) {
    asm volatile("ldmatrix.sync.aligned.m8n8.x4.shared.b16 {%0,%1,%2,%3}, [%4];"
                 : "=r"(r[0]), "=r"(r[1]), "=r"(r[2]), "=r"(r[3]) : "r"(addr));
}

__device__ __forceinline__ void mma16816(float* c, const uint32_t* a, const uint32_t* b) {
    asm volatile(
        "mma.sync.aligned.m16n8k16.row.col.f32.bf16.bf16.f32 "
        "{%0,%1,%2,%3}, {%4,%5,%6,%7}, {%8,%9}, {%0,%1,%2,%3};"
        : "+f"(c[0]), "+f"(c[1]), "+f"(c[2]), "+f"(c[3])
        : "r"(a[0]), "r"(a[1]), "r"(a[2]), "r"(a[3]), "r"(b[0]), "r"(b[1]));
}

__device__ __forceinline__ void cpasync16(uint32_t s, const void* g) {
    asm volatile("cp.async.cg.shared.global [%0], [%1], 16;" :: "r"(s), "l"(g));
}
__device__ __forceinline__ void cpasync_wait() {
    asm volatile("cp.async.commit_group;");
    asm volatile("cp.async.wait_group 0;" ::: "memory");
}

__device__ __forceinline__ void split8(const float* v, uint4& h4, uint4& l4) {
    uint16_t* hp = (uint16_t*)&h4;
    uint16_t* lp = (uint16_t*)&l4;
#pragma unroll
    for (int i = 0; i < 8; i++) {
        __nv_bfloat16 hb = __float2bfloat16(v[i]);
        float r = v[i] - __bfloat162float(hb);
        __nv_bfloat16 lb = __float2bfloat16(r);
        hp[i] = *(uint16_t*)&hb;
        lp[i] = *(uint16_t*)&lb;
    }
}

__device__ __forceinline__ uint32_t swz(int row, int g, int ROWB) {
    int c = (g & ~7) | ((g ^ row) & 7);
    return (uint32_t)(row * ROWB + c * 16);
}

// ---------------------------------------------------------------------------
// Weight prep
// ---------------------------------------------------------------------------
struct Prep8 {
    const float* W[8];
    int K[8], N[8], off[8];
};

__global__ void prep_kernel(Prep8 p) {
    for (int m = 0; m < 8; m++) {
        const int K = p.K[m], N = p.N[m], tot = K * N, off = p.off[m];
        const float* W = p.W[m];
        for (int idx = blockIdx.x * blockDim.x + threadIdx.x; idx < tot;
             idx += gridDim.x * blockDim.x) {
            int n = idx / K, k = idx - n * K;
            float w = W[(size_t)k * N + n];
            __nv_bfloat16 h = __float2bfloat16(w);
            float r = w - __bfloat162float(h);
            __nv_bfloat16 l = __float2bfloat16(r);
            g_wthi[off + idx] = *(uint16_t*)&h;
            g_wtlo[off + idx] = *(uint16_t*)&l;
        }
    }
}

// ---------------------------------------------------------------------------
// Fused bf16x3 GEMM + el/er epilogue (gat chain)
// ---------------------------------------------------------------------------
template <int K>
__global__ __launch_bounds__(256, 1) void tc_gemm_fused(
    const float* __restrict__ A1, int K1,
    const float* __restrict__ A2,
    const uint16_t* __restrict__ Bh, const uint16_t* __restrict__ Bl,
    const float* __restrict__ al, const float* __restrict__ ar,
    float* __restrict__ el, float* __restrict__ er,
    float* __restrict__ C1, float* __restrict__ C2, int M)
{
    constexpr int BN   = 256;
    constexpr int ROWB = K * 2;
    constexpr int NG   = K / 8;
    constexpr int WN   = 128;
    constexpr int NT   = WN / 8;
    constexpr int KS   = K / 16;
    constexpr int AOFF  = 0;
    constexpr int ALOFF = 128 * ROWB;
    constexpr int BOFF  = 2 * 128 * ROWB;

    extern __shared__ char smem[];
    const uint32_t sb  = smem_u32(smem);
    const uint32_t sAH = sb + AOFF;
    const uint32_t sAL = sb + ALOFF;
    const uint32_t sB  = sb + BOFF;

    const int t    = threadIdx.x;
    const int wid  = t >> 5;
    const int lane = t & 31;
    const int bm   = blockIdx.x * 128;

    for (int idx = t; idx < BN * NG; idx += 256) {
        int rn = idx / NG, g = idx - rn * NG;
        cpasync16(sB + swz(rn, g, ROWB), Bh + (size_t)rn * K + g * 8);
    }

    for (int idx = t; idx < 128 * NG; idx += 256) {
        int row = idx / NG, g = idx - row * NG, k0 = g * 8;
        int grow = bm + row;
        float v[8] = {0, 0, 0, 0, 0, 0, 0, 0};
        if (grow < M) {
            const float* p = (k0 < K1) ? (A1 + (size_t)grow * K1 + k0)
                                       : (A2 + (size_t)grow * (K - K1) + (k0 - K1));
            *(float4*)&v[0] = ((const float4*)p)[0];
            *(float4*)&v[4] = ((const float4*)p)[1];
        }
        uint4 h4, l4;
        split8(v, h4, l4);
        uint32_t o = swz(row, g, ROWB);
        *(uint4*)(smem + AOFF + o)  = h4;
        *(uint4*)(smem + ALOFF + o) = l4;
    }
    cpasync_wait();
    __syncthreads();

    const int wm   = wid & 3;
    const int wn   = wid >> 2;
    const int lr   = lane & 7;
    const int sel  = lane >> 3;
    const int selb1 = sel & 1;
    const int selb2 = sel >> 1;
    const int rowA_base = wm * 32 + lr + selb1 * 8;
    const int rowB_base = wn * WN + lr + selb2 * 8;

    float acc[2][NT][4];
#pragma unroll
    for (int mt = 0; mt < 2; mt++)
#pragma unroll
        for (int nt = 0; nt < NT; nt++)
#pragma unroll
            for (int q = 0; q < 4; q++) acc[mt][nt][q] = 0.f;

#pragma unroll
    for (int ks = 0; ks < KS; ks++) {
        uint32_t bfr[NT][2];
#pragma unroll
        for (int nt2 = 0; nt2 < NT / 2; nt2++) {
            uint32_t r[4];
            ldsm_x4(r, sB + swz(rowB_base + nt2 * 16, ks * 2 + selb1, ROWB));
            bfr[2 * nt2][0]     = r[0];
            bfr[2 * nt2][1]     = r[1];
            bfr[2 * nt2 + 1][0] = r[2];
            bfr[2 * nt2 + 1][1] = r[3];
        }
        uint32_t afr[2][4];
#pragma unroll
        for (int mt = 0; mt < 2; mt++)
            ldsm_x4(afr[mt], sAH + swz(rowA_base + mt * 16, ks * 2 + selb2, ROWB));
#pragma unroll
        for (int mt = 0; mt < 2; mt++)
#pragma unroll
            for (int nt = 0; nt < NT; nt++)
                mma16816(acc[mt][nt], afr[mt], bfr[nt]);
#pragma unroll
        for (int mt = 0; mt < 2; mt++)
            ldsm_x4(afr[mt], sAL + swz(rowA_base + mt * 16, ks * 2 + selb2, ROWB));
#pragma unroll
        for (int mt = 0; mt < 2; mt++)
#pragma unroll
            for (int nt = 0; nt < NT; nt++)
                mma16816(acc[mt][nt], afr[mt], bfr[nt]);
    }

    __syncthreads();
    for (int idx = t; idx < BN * NG; idx += 256) {
        int rn = idx / NG, g = idx - rn * NG;
        cpasync16(sB + swz(rn, g, ROWB), Bl + (size_t)rn * K + g * 8);
    }
    cpasync_wait();
    __syncthreads();

#pragma unroll
    for (int ks = 0; ks < KS; ks++) {
        uint32_t bfr[NT][2];
#pragma unroll
        for (int nt2 = 0; nt2 < NT / 2; nt2++) {
            uint32_t r[4];
            ldsm_x4(r, sB + swz(rowB_base + nt2 * 16, ks * 2 + selb1, ROWB));
            bfr[2 * nt2][0]     = r[0];
            bfr[2 * nt2][1]     = r[1];
            bfr[2 * nt2 + 1][0] = r[2];
            bfr[2 * nt2 + 1][1] = r[3];
        }
        uint32_t afr[2][4];
#pragma unroll
        for (int mt = 0; mt < 2; mt++)
            ldsm_x4(afr[mt], sAH + swz(rowA_base + mt * 16, ks * 2 + selb2, ROWB));
#pragma unroll
        for (int mt = 0; mt < 2; mt++)
#pragma unroll
            for (int nt = 0; nt < NT; nt++)
                mma16816(acc[mt][nt], afr[mt], bfr[nt]);
    }

    float* __restrict__ C = (wn == 0) ? C1 : C2;
    const int colb = (lane & 3) * 2;
#pragma unroll
    for (int mt = 0; mt < 2; mt++) {
        int r0 = bm + wm * 32 + mt * 16 + (lane >> 2);
        int r1 = r0 + 8;
#pragma unroll
        for (int nt = 0; nt < NT; nt++) {
            int col = colb + nt * 8;
            if (r0 < M) *(float2*)&C[(size_t)r0 * 128 + col] =
                make_float2(acc[mt][nt][0], acc[mt][nt][1]);
            if (r1 < M) *(float2*)&C[(size_t)r1 * 128 + col] =
                make_float2(acc[mt][nt][2], acc[mt][nt][3]);
        }
    }

    if (wn == 0) {
#pragma unroll
        for (int mt = 0; mt < 2; mt++) {
            float e[8];
#pragma unroll
            for (int q = 0; q < 8; q++) e[q] = 0.f;
#pragma unroll
            for (int nt = 0; nt < NT; nt++) {
                int c = colb + nt * 8;
                float a0 = al[c], a1 = al[c + 1];
                float b0 = ar[c], b1 = ar[c + 1];
                float sl0 = acc[mt][nt][0] * a0 + acc[mt][nt][1] * a1;
                float sl1 = acc[mt][nt][2] * a0 + acc[mt][nt][3] * a1;
                float sr0 = acc[mt][nt][0] * b0 + acc[mt][nt][1] * b1;
                float sr1 = acc[mt][nt][2] * b0 + acc[mt][nt][3] * b1;
                int hsel = (nt < 8) ? 0 : 1;
                e[hsel]     += sl0;
                e[2 + hsel] += sr0;
                e[4 + hsel] += sl1;
                e[6 + hsel] += sr1;
            }
#pragma unroll
            for (int o = 1; o <= 2; o <<= 1)
#pragma unroll
                for (int q = 0; q < 8; q++)
                    e[q] += __shfl_xor_sync(0xffffffffu, e[q], o);
            if ((lane & 3) == 0) {
                int r0 = bm + wm * 32 + mt * 16 + (lane >> 2);
                int r1 = r0 + 8;
                if (r0 < M) {
                    el[2 * r0] = e[0]; el[2 * r0 + 1] = e[1];
                    er[2 * r0] = e[2]; er[2 * r0 + 1] = e[3];
                }
                if (r1 < M) {
                    el[2 * r1] = e[4]; el[2 * r1 + 1] = e[5];
                    er[2 * r1] = e[6]; er[2 * r1 + 1] = e[7];
                }
            }
        }
    }
}

// ---------------------------------------------------------------------------
// Small bf16x3 GEMM (pg layers) with fused el/er epilogue
// ---------------------------------------------------------------------------
template <int BN, int K>
__global__ __launch_bounds__(256, 1) void tc_gemm_small(
    const float* __restrict__ A1,
    const uint16_t* __restrict__ Bh, const uint16_t* __restrict__ Bl,
    const float* __restrict__ al, const float* __restrict__ ar,
    float* __restrict__ el, float* __restrict__ er,
    float* __restrict__ C, int M)
{
    constexpr int ROWB = K * 2;
    constexpr int NG   = K / 8;
    constexpr int WN   = BN / 2;
    constexpr int NT   = WN / 8;
    constexpr int KS   = K / 16;

    extern __shared__ char smem[];
    const uint32_t sAH = smem_u32(smem);
    const uint32_t sAL = sAH + 128 * ROWB;
    const uint32_t sBH = sAL + 128 * ROWB;
    const uint32_t sBL = sBH + BN * ROWB;

    const int t    = threadIdx.x;
    const int wid  = t >> 5;
    const int lane = t & 31;
    const int bm   = blockIdx.x * 128;

    for (int idx = t; idx < BN * NG; idx += 256) {
        int rn = idx / NG, g = idx - rn * NG, k0 = g * 8;
        cpasync16(sBH + swz(rn, g, ROWB), Bh + (size_t)rn * K + k0);
        cpasync16(sBL + swz(rn, g, ROWB), Bl + (size_t)rn * K + k0);
    }
    for (int idx = t; idx < 128 * NG; idx += 256) {
        int row = idx / NG, g = idx - row * NG, k0 = g * 8;
        int grow = bm + row;
        float v[8] = {0, 0, 0, 0, 0, 0, 0, 0};
        if (grow < M) {
            const float* p = A1 + (size_t)grow * K + k0;
            *(float4*)&v[0] = ((const float4*)p)[0];
            *(float4*)&v[4] = ((const float4*)p)[1];
        }
        uint4 h4, l4;
        split8(v, h4, l4);
        uint32_t o = swz(row, g, ROWB);
        *(uint4*)(smem + o) = h4;
        *(uint4*)(smem + 128 * ROWB + o) = l4;
    }
    cpasync_wait();
    __syncthreads();

    const int wm = wid & 3;
    const int wn = wid >> 2;
    const int lr   = lane & 7;
    const int sel  = lane >> 3;
    const int selb1 = sel & 1;
    const int selb2 = sel >> 1;
    const int rowA_base = wm * 32 + lr + selb1 * 8;
    const int rowB_base = wn * WN + lr + selb2 * 8;

    float acc[2][NT][4];
#pragma unroll
    for (int mt = 0; mt < 2; mt++)
#pragma unroll
        for (int nt = 0; nt < NT; nt++)
#pragma unroll
            for (int q = 0; q < 4; q++) acc[mt][nt][q] = 0.f;

#pragma unroll
    for (int pr = 0; pr < 3; pr++) {
        const uint32_t baseA = (pr == 2) ? sAL : sAH;
        const uint32_t baseB = (pr == 1) ? sBL : sBH;
#pragma unroll
        for (int ks = 0; ks < KS; ks++) {
            uint32_t afr[2][4];
#pragma unroll
            for (int mt = 0; mt < 2; mt++)
                ldsm_x4(afr[mt], baseA + swz(rowA_base + mt * 16, ks * 2 + selb2, ROWB));
            uint32_t bfr[NT][2];
#pragma unroll
            for (int nt2 = 0; nt2 < NT / 2; nt2++) {
                uint32_t r[4];
                ldsm_x4(r, baseB + swz(rowB_base + nt2 * 16, ks * 2 + selb1, ROWB));
                bfr[2 * nt2][0]     = r[0];
                bfr[2 * nt2][1]     = r[1];
                bfr[2 * nt2 + 1][0] = r[2];
                bfr[2 * nt2 + 1][1] = r[3];
            }
#pragma unroll
            for (int mt = 0; mt < 2; mt++)
#pragma unroll
                for (int nt = 0; nt < NT; nt++)
                    mma16816(acc[mt][nt], afr[mt], bfr[nt]);
        }
    }

    const int colb = wn * WN + (lane & 3) * 2;
#pragma unroll
    for (int mt = 0; mt < 2; mt++) {
        int r0 = bm + wm * 32 + mt * 16 + (lane >> 2);
        int r1 = r0 + 8;
#pragma unroll
        for (int nt = 0; nt < NT; nt++) {
            int col = colb + nt * 8;
            if (r0 < M) *(float2*)&C[(size_t)r0 * BN + col] =
                make_float2(acc[mt][nt][0], acc[mt][nt][1]);
            if (r1 < M) *(float2*)&C[(size_t)r1 * BN + col] =
                make_float2(acc[mt][nt][2], acc[mt][nt][3]);
        }
    }

#pragma unroll
    for (int mt = 0; mt < 2; mt++) {
        float e[4];
#pragma unroll
        for (int q = 0; q < 4; q++) e[q] = 0.f;
#pragma unroll
        for (int nt = 0; nt < NT; nt++) {
            int c = colb + nt * 8;
            float a0 = al[c], a1 = al[c + 1];
            float b0 = ar[c], b1 = ar[c + 1];
            e[0] += acc[mt][nt][0] * a0 + acc[mt][nt][1] * a1;
            e[1] += acc[mt][nt][0] * b0 + acc[mt][nt][1] * b1;
            e[2] += acc[mt][nt][2] * a0 + acc[mt][nt][3] * a1;
            e[3] += acc[mt][nt][2] * b0 + acc[mt][nt][3] * b1;
        }
#pragma unroll
        for (int o = 1; o <= 2; o <<= 1)
#pragma unroll
            for (int q = 0; q < 4; q++)
                e[q] += __shfl_xor_sync(0xffffffffu, e[q], o);
        if ((lane & 3) == 0) {
            int r0 = bm + wm * 32 + mt * 16 + (lane >> 2);
            int r1 = r0 + 8;
            if (r0 < M) { el[2 * r0 + wn] = e[0]; er[2 * r0 + wn] = e[1]; }
            if (r1 < M) { el[2 * r1 + wn] = e[2]; er[2 * r1 + wn] = e[3]; }
        }
    }
}

// ---------------------------------------------------------------------------
// CSR build
// ---------------------------------------------------------------------------
__global__ void count_kernel(const int* __restrict__ dst, int e) {
    int i = blockIdx.x * blockDim.x + threadIdx.x;
    if (i < e) atomicAdd(&g_cnt[dst[i]], 1);
}

__global__ void scan_kernel(int n) {
    __shared__ int partial[1024];
    const int t = threadIdx.x;
    const int C = (n + 1023) / 1024;
    int s = 0;
    for (int j = 0; j < C; j++) {
        int idx = t * C + j;
        if (idx < n) s += g_cnt[idx];
    }
    partial[t] = s;
    __syncthreads();
    for (int ofs = 1; ofs < 1024; ofs <<= 1) {
        int v = (t >= ofs) ? partial[t - ofs] : 0;
        __syncthreads();
        partial[t] += v;
        __syncthreads();
    }
    int run = (t == 0) ? 0 : partial[t - 1];
    for (int j = 0; j < C; j++) {
        int idx = t * C + j;
        if (idx < n) {
            g_off[idx] = run;
            run += g_cnt[idx];
            g_cnt[idx] = 0;
        }
    }
    if (t == 1023) g_off[n] = run;
}

__global__ void fill_kernel(const int* __restrict__ src, const int* __restrict__ dst, int e) {
    int i = blockIdx.x * blockDim.x + threadIdx.x;
    if (i < e) {
        int d = dst[i];
        int p = atomicAdd(&g_cnt[d], 1);
        g_esrc[g_off[d] + p] = src[i];
    }
}

// ---------------------------------------------------------------------------
// Aggregation: warp per dst node, single-pass online softmax.
// ---------------------------------------------------------------------------
__device__ __forceinline__ float leaky02(float x) { return x > 0.f ? x : 0.2f * x; }

template <int HD, int ACT, bool HEADMEAN>
__global__ void agg_kernel(const float* __restrict__ h,
                           const float* __restrict__ res,
                           const float* __restrict__ elp,
                           const float* __restrict__ erp,
                           float* __restrict__ out, int n)
{
    constexpr int V = HD / 32;
    int node = (blockIdx.x * blockDim.x + threadIdx.x) >> 5;
    int lane = threadIdx.x & 31;
    if (node >= n) return;

    const int beg = g_off[node];
    const int end = g_off[node + 1];
    const float2 erv = ((const float2*)erp)[node];
    const float2* __restrict__ el2 = (const float2*)elp;
    const int* __restrict__ esrc = g_esrc;

    const bool head0 = (lane * V) < (HD / 2);
    float m0 = -1e30f, m1 = -1e30f;
    float d0 = 0.f, d1 = 0.f;
    float acc[V];
#pragma unroll
    for (int q = 0; q < V; q++) acc[q] = 0.f;

    int i = beg;
    for (; i + 4 <= end; i += 4) {
        int s[4];
#pragma unroll
        for (int j = 0; j < 4; j++) s[j] = esrc[i + j];
        float2 ev[4];
#pragma unroll
        for (int j = 0; j < 4; j++) ev[j] = el2[s[j]];
        float hv[4][V];
#pragma unroll
        for (int j = 0; j < 4; j++) {
            if (V == 4) *(float4*)hv[j] = *(const float4*)(h + (size_t)s[j] * HD + lane * V);
            else        *(float2*)hv[j] = *(const float2*)(h + (size_t)s[j] * HD + lane * V);
        }
#pragma unroll
        for (int j = 0; j < 4; j++) {
            float e0 = leaky02(ev[j].x + erv.x);
            float e1 = leaky02(ev[j].y + erv.y);
            float nm0 = fmaxf(m0, e0), nm1 = fmaxf(m1, e1);
            float sc0 = __expf(m0 - nm0), w0 = __expf(e0 - nm0);
            float sc1 = __expf(m1 - nm1), w1 = __expf(e1 - nm1);
            d0 = d0 * sc0 + w0;
            d1 = d1 * sc1 + w1;
            m0 = nm0; m1 = nm1;
            float scv = head0 ? sc0 : sc1;
            float wv  = head0 ? w0  : w1;
#pragma unroll
            for (int q = 0; q < V; q++) acc[q] = fmaf(acc[q], scv, wv * hv[j][q]);
        }
    }
    for (; i < end; i++) {
        int s = esrc[i];
        float2 ev = el2[s];
        float hv[V];
        if (V == 4) *(float4*)hv = *(const float4*)(h + (size_t)s * HD + lane * V);
        else        *(float2*)hv = *(const float2*)(h + (size_t)s * HD + lane * V);
        float e0 = leaky02(ev.x + erv.x);
        float e1 = leaky02(ev.y + erv.y);
        float nm0 = fmaxf(m0, e0), nm1 = fmaxf(m1, e1);
        float sc0 = __expf(m0 - nm0), w0 = __expf(e0 - nm0);
        float sc1 = __expf(m1 - nm1), w1 = __expf(e1 - nm1);
        d0 = d0 * sc0 + w0;
        d1 = d1 * sc1 + w1;
        m0 = nm0; m1 = nm1;
        float scv = head0 ? sc0 : sc1;
        float wv  = head0 ? w0  : w1;
#pragma unroll
        for (int q = 0; q < V; q++) acc[q] = fmaf(acc[q], scv, wv * hv[q]);
    }

    const bool has = (end > beg);
    const float inv0 = has ? 1.f / d0 : 0.f;
    const float inv1 = has ? 1.f / d1 : 0.f;
    const float invv = head0 ? inv0 : inv1;

    float rr[V];
    if (V == 4) *(float4*)rr = *(const float4*)(res + (size_t)node * HD + lane * V);
    else        *(float2*)rr = *(const float2*)(res + (size_t)node * HD + lane * V);

    float v[V];
#pragma unroll
    for (int q = 0; q < V; q++) {
        v[q] = acc[q] * invv + rr[q];
        if (ACT == 0) v[q] = v[q] > 0.f ? v[q] : expm1f(v[q]);
        else          v[q] = tanhf(v[q]);
    }

    if (HEADMEAN) {
        float p[V];
#pragma unroll
        for (int q = 0; q < V; q++) p[q] = __shfl_xor_sync(0xffffffffu, v[q], 16);
        if (lane < 16) {
            float o[V];
#pragma unroll
            for (int q = 0; q < V; q++) o[q] = 0.5f * (v[q] + p[q]);
            if (V == 4) *(float4*)(out + (size_t)node * 64 + lane * V) = *(float4*)o;
            else        *(float2*)(out + (size_t)node * 64 + lane * V) = *(float2*)o;
        }
    } else {
        if (V == 4) *(float4*)(out + (size_t)node * HD + lane * V) = *(float4*)v;
        else        *(float2*)(out + (size_t)node * HD + lane * V) = *(float2*)v;
    }
}

// ---------------------------------------------------------------------------
// Launch — multi-stream graph. CSR dependency attaches ONLY to agg kernels.
// ---------------------------------------------------------------------------
extern "C" void kernel_launch(void* const* d_in, const int* in_sizes, int n_in,
                              void* d_out, int out_size)
{
    const float* fvs = (const float*)d_in[0];
    const float* pos = (const float*)d_in[1];
    const int*   src = (const int*)d_in[2];
    const int*   dst = (const int*)d_in[3];
    const float* g0W  = (const float*)d_in[4];
    const float* g0al = (const float*)d_in[5];
    const float* g0ar = (const float*)d_in[6];
    const float* g0rW = (const float*)d_in[7];
    const float* g1W  = (const float*)d_in[8];
    const float* g1al = (const float*)d_in[9];
    const float* g1ar = (const float*)d_in[10];
    const float* g1rW = (const float*)d_in[11];
    const float* g2W  = (const float*)d_in[12];
    const float* g2al = (const float*)d_in[13];
    const float* g2ar = (const float*)d_in[14];
    const float* g2rW = (const float*)d_in[15];
    const float* p0W  = (const float*)d_in[16];
    const float* p0al = (const float*)d_in[17];
    const float* p0ar = (const float*)d_in[18];
    const float* p1W  = (const float*)d_in[19];
    const float* p1al = (const float*)d_in[20];
    const float* p1ar = (const float*)d_in[21];

    const int n = in_sizes[0] / 128;
    const int e = in_sizes[2];

    float *h, *rh, *hs, *hs2, *hp, *hq, *el, *er, *el2, *er2;
    int* cnt;
    uint16_t *wthi, *wtlo;
    cudaGetSymbolAddress((void**)&h,    g_h);
    cudaGetSymbolAddress((void**)&rh,   g_rh);
    cudaGetSymbolAddress((void**)&hs,   g_hs);
    cudaGetSymbolAddress((void**)&hs2,  g_hs2);
    cudaGetSymbolAddress((void**)&hp,   g_hp);
    cudaGetSymbolAddress((void**)&hq,   g_hq);
    cudaGetSymbolAddress((void**)&el,   g_el);
    cudaGetSymbolAddress((void**)&er,   g_er);
    cudaGetSymbolAddress((void**)&el2,  g_el2);
    cudaGetSymbolAddress((void**)&er2,  g_er2);
    cudaGetSymbolAddress((void**)&cnt,  g_cnt);
    cudaGetSymbolAddress((void**)&wthi, g_wthi);
    cudaGetSymbolAddress((void**)&wtlo, g_wtlo);

    float* out_hs = (float*)d_out;
    float* out_hp = (float*)d_out + (size_t)n * 64;

    const int EB = (e + 255) / 256;
    const int GB = (n + 127) / 128;
    const int WB = (n + 7) / 8;

    constexpr int SMEM_F     = 2 * 128 * 384 + 256 * 384;          // 196608
    constexpr int SMEM_SMALL = (128 + 128 + 64 + 64) * 64 * 2;     // 49152
    cudaFuncSetAttribute(tc_gemm_fused<192>,    cudaFuncAttributeMaxDynamicSharedMemorySize, SMEM_F);
    cudaFuncSetAttribute(tc_gemm_small<64, 64>, cudaFuncAttributeMaxDynamicSharedMemorySize, SMEM_SMALL);

    static cudaStream_t s1 = nullptr, s2 = nullptr;
    static cudaEvent_t evFork, evPrep, evCSR, evP0, evP1, evEnd1, evEnd2;
    if (s1 == nullptr) {
        cudaStreamCreateWithFlags(&s1, cudaStreamNonBlocking);
        cudaStreamCreateWithFlags(&s2, cudaStreamNonBlocking);
        cudaEventCreateWithFlags(&evFork, cudaEventDisableTiming);
        cudaEventCreateWithFlags(&evPrep, cudaEventDisableTiming);
        cudaEventCreateWithFlags(&evCSR,  cudaEventDisableTiming);
        cudaEventCreateWithFlags(&evP0,   cudaEventDisableTiming);
        cudaEventCreateWithFlags(&evP1,   cudaEventDisableTiming);
        cudaEventCreateWithFlags(&evEnd1, cudaEventDisableTiming);
        cudaEventCreateWithFlags(&evEnd2, cudaEventDisableTiming);
    }

    Prep8 pa;
    const float* Ws[8] = {g0W, g0rW, g1W, g1rW, g2W, g2rW, p0W, p1W};
    for (int m = 0; m < 8; m++) {
        pa.W[m] = Ws[m];
        pa.K[m] = (m < 6) ? 192 : 64;
        pa.N[m] = (m < 6) ? 128 : 64;
        pa.off[m] = (m < 6) ? (m >> 1) * WT_FUSED + (m & 1) * (128 * 192)
                            : 3 * WT_FUSED + (m - 6) * WT_SMALL;
    }

    const int F0 = 0 * WT_FUSED, F1 = 1 * WT_FUSED, F2 = 2 * WT_FUSED;
    const int P0 = 3 * WT_FUSED, P1 = 3 * WT_FUSED + WT_SMALL;

    // ---- fork ----
    cudaEventRecord(evFork, 0);
    cudaStreamWaitEvent(s1, evFork, 0);
    cudaStreamWaitEvent(s2, evFork, 0);

    // s1: weight prep (both chains depend on it)
    prep_kernel<<<64, 256, 0, s1>>>(pa);
    cudaEventRecord(evPrep, s1);
    cudaStreamWaitEvent(s2, evPrep, 0);

    // s0: CSR build — runs concurrent with prep AND the first GEMMs.
    cudaMemsetAsync(cnt, 0, (size_t)n * sizeof(int), 0);
    count_kernel<<<EB, 256, 0, 0>>>(dst, e);
    scan_kernel<<<1, 1024, 0, 0>>>(n);
    fill_kernel<<<EB, 256, 0, 0>>>(src, dst, e);
    cudaEventRecord(evCSR, 0);

    // ---- layer 0 ----
    // GEMMs need only prepped weights — launch immediately.
    tc_gemm_fused<192><<<GB, 256, SMEM_F, s1>>>(fvs, 128, pos, wthi + F0, wtlo + F0,
                                                g0al, g0ar, el, er, h, rh, n);
    tc_gemm_small<64, 64><<<GB, 256, SMEM_SMALL, s2>>>(pos, wthi + P0, wtlo + P0,
                                                       p0al, p0ar, el2, er2, hq, n);
    // agg kernels read g_off/g_esrc — CSR dependency attaches here.
    cudaStreamWaitEvent(s1, evCSR, 0);
    cudaStreamWaitEvent(s2, evCSR, 0);
    agg_kernel<128, 0, false><<<WB, 256, 0, s1>>>(h, rh, el, er, hs, n);
    agg_kernel<64, 1, false><<<WB, 256, 0, s2>>>(hq, pos, el2, er2, hp, n);
    cudaEventRecord(evP0, s2);

    // ---- layer 1 ----
    cudaStreamWaitEvent(s1, evP0, 0);   // gemmF1 needs hp
    tc_gemm_fused<192><<<GB, 256, SMEM_F, s1>>>(hs, 128, hp, wthi + F1, wtlo + F1,
                                                g1al, g1ar, el, er, h, rh, n);
    agg_kernel<128, 0, false><<<WB, 256, 0, s1>>>(h, rh, el, er, hs2, n);

    tc_gemm_small<64, 64><<<GB, 256, SMEM_SMALL, s2>>>(hp, wthi + P1, wtlo + P1,
                                                       p1al, p1ar, el2, er2, hq, n);
    agg_kernel<64, 1, false><<<WB, 256, 0, s2>>>(hq, hp, el2, er2, out_hp, n);
    cudaEventRecord(evP1, s2);

    // ---- layer 2 (output, head-mean) ----
    cudaStreamWaitEvent(s1, evP1, 0);   // gemmF2 needs out_hp
    tc_gemm_fused<192><<<GB, 256, SMEM_F, s1>>>(hs2, 128, out_hp, wthi + F2, wtlo + F2,
                                                g2al, g2ar, el, er, h, rh, n);
    agg_kernel<128, 0, true><<<WB, 256, 0, s1>>>(h, rh, el, er, out_hs, n);
    cudaEventRecord(evEnd1, s1);
    cudaEventRecord(evEnd2, s2);

    // ---- join ----
    cudaStreamWaitEvent(0, evEnd1, 0);
    cudaStreamWaitEvent(0, evEnd2, 0);
}